// round 9
// baseline (speedup 1.0000x reference)
#include <cuda_runtime.h>
#include <cuda_bf16.h>
#include <math.h>
#include <stdint.h>

#define BB 2
#define LL 48
#define NN 3000
#define DD 128
#define L_OUT 24
#define BNN (BB*NN)          // 6000
#define BLL (BB*LL)          // 96
#define ROWS (BNN*LL)        // 288000 token rows
#define ENC_N (ROWS*DD)      // 36,864,000

typedef __nv_bfloat16 bf16;

// ---------------- scratch (device globals; no runtime allocation) ----------------
__device__ float d_mean[BNN];
__device__ float d_enc[ENC_N];           // enc[seq][l][c]
__device__ float d_qb[ENC_N];            // q fp32 (raw)
__device__ float d_kb[ENC_N];
__device__ float d_vb[ENC_N];
__device__ float d_gout[NN*BLL*DD];      // gout[n][bl][o]
__device__ float d_gmu[BLL*4];
__device__ float d_grs[BLL*4];
__device__ float d_gsum[BLL*4];
__device__ float d_gsq[BLL*4];

// bf16 split pairs
__device__ bf16 d_hh[ENC_N],  d_hl[ENC_N];     // LN output
__device__ bf16 d_qh[ENC_N],  d_ql[ENC_N];     // att_pre
__device__ bf16 d_ffh[ROWS*512], d_ffl[ROWS*512];
__device__ bf16 d_adjh[NN*NN], d_adjl[NN*NN];
__device__ bf16 d_Xh[BLL*DD*NN], d_Xl[BLL*DD*NN];
__device__ bf16 d_peTh[DD*NN], d_peTl[DD*NN];
__device__ bf16 d_WT2h[DD*DD*DD], d_WT2l[DD*DD*DD];  // [(o*128+i)][d]
__device__ bf16 d_pe2h[NN*DD], d_pe2l[NN*DD];
__device__ bf16 d_aggh[NN*BLL*DD], d_aggl[NN*BLL*DD]; // [n][bl*128+i]
__device__ bf16 d_pwh[NN*DD*DD], d_pwl[NN*DD*DD];     // [n][o*128+i]
// weight pool: [wq|wk|wv|wo|ffw1|ffw2]
#define WPO_Q 0
#define WPO_K 16384
#define WPO_V 32768
#define WPO_O 49152
#define WPO_F1 65536
#define WPO_F2 131072
__device__ bf16 d_wph[196608], d_wpl[196608];

__device__ __forceinline__ float gelu_exact(float x) {
    return 0.5f * x * (1.0f + erff(x * 0.70710678118654752f));
}
__device__ __forceinline__ void pack_split(float x0, float x1, uint32_t& hi, uint32_t& lo) {
    uint32_t h;
    asm("cvt.rn.bf16x2.f32 %0, %1, %2;" : "=r"(h) : "f"(x1), "f"(x0));
    float h0 = __uint_as_float(h << 16);
    float h1 = __uint_as_float(h & 0xFFFF0000u);
    float r0 = x0 - h0, r1 = x1 - h1;
    uint32_t l;
    asm("cvt.rn.bf16x2.f32 %0, %1, %2;" : "=r"(l) : "f"(r1), "f"(r0));
    hi = h; lo = l;
}
__device__ __forceinline__ void scalar_split(float v, bf16& h, bf16& l) {
    h = __float2bfloat16_rn(v);
    l = __float2bfloat16_rn(v - __bfloat162float(h));
}

// ---------------- small prep kernels ----------------
__global__ void k_mean(const float* __restrict__ x) {
    int i = blockIdx.x * blockDim.x + threadIdx.x;
    if (i >= BNN) return;
    int b = i / NN, n = i % NN;
    float s = 0.f;
    #pragma unroll
    for (int l = 0; l < LL; ++l) s += x[(b*LL + l)*NN + n];
    d_mean[i] = s * (1.0f / LL);
}

__global__ void k_split(const float* __restrict__ in, bf16* __restrict__ h,
                        bf16* __restrict__ l, int n) {
    int i = blockIdx.x * blockDim.x + threadIdx.x;
    if (i >= n) return;
    scalar_split(in[i], h[i], l[i]);
}

// merged split of all dense weights into the pool
__global__ void k_splitW(const float* __restrict__ wq, const float* __restrict__ wk,
                         const float* __restrict__ wv, const float* __restrict__ wo,
                         const float* __restrict__ f1, const float* __restrict__ f2) {
    int i = blockIdx.x * blockDim.x + threadIdx.x;
    if (i >= 196608) return;
    float v;
    if (i < 65536) {
        int j = i & 16383;
        v = (i < 16384) ? wq[j] : (i < 32768) ? wk[j] : (i < 49152) ? wv[j] : wo[j];
    } else if (i < 131072) {
        v = f1[i - 65536];
    } else {
        v = f2[i - 131072];
    }
    scalar_split(v, d_wph[i], d_wpl[i]);
}

__global__ void k_peT(const float* __restrict__ pr, const float* __restrict__ pw,
                      const float* __restrict__ pb) {
    int i = blockIdx.x * blockDim.x + threadIdx.x;
    if (i >= DD*NN) return;
    int d = i / NN, n = i % NN;
    float v = pr[n]*pw[d*3] + pr[NN+n]*pw[d*3+1] + pr[2*NN+n]*pw[d*3+2] + pb[d];
    scalar_split(v, d_peTh[i], d_peTl[i]);
}

// WT2[(o*128+i)][d] = wp[(d*128+i)][o]
__global__ void k_WT2(const float* __restrict__ wp) {
    int idx = blockIdx.x * blockDim.x + threadIdx.x;
    if (idx >= DD*DD*DD) return;
    int d = idx & 127;
    int nrow = idx >> 7;          // o*128+i
    int i = nrow & 127, o = nrow >> 7;
    scalar_split(wp[(d*128 + i)*128 + o], d_WT2h[idx], d_WT2l[idx]);
}

// circular conv1d k=3: enc[seq][l][c]
__global__ void k_conv(const float* __restrict__ x, const float* __restrict__ cw) {
    __shared__ float xs[LL + 2];
    int seq = blockIdx.x;
    int b = seq / NN, n = seq % NN;
    float m = d_mean[seq];
    int t = threadIdx.x;   // 128
    if (t < LL) xs[t + 1] = x[(b*LL + t)*NN + n] - m;
    __syncthreads();
    if (t == 0) { xs[0] = xs[LL]; xs[LL+1] = xs[1]; }
    __syncthreads();
    float w0 = cw[t*3], w1 = cw[t*3+1], w2 = cw[t*3+2];
    float* out = d_enc + (size_t)seq * (LL*DD);
    #pragma unroll
    for (int l = 0; l < LL; ++l)
        out[l*DD + t] = w0*xs[l] + w1*xs[l+1] + w2*xs[l+2];
}

// LayerNorm over rows of 128 (one warp per row), writes split bf16 pair
__global__ void k_ln(const float* __restrict__ X,
                     const float* __restrict__ g, const float* __restrict__ bta) {
    int warp = (blockIdx.x * blockDim.x + threadIdx.x) >> 5;
    int lane = threadIdx.x & 31;
    const float* xr = X + (size_t)warp * DD;
    float4 v = *(const float4*)(xr + lane*4);
    float s = v.x + v.y + v.z + v.w;
    float sq = v.x*v.x + v.y*v.y + v.z*v.z + v.w*v.w;
    #pragma unroll
    for (int o = 16; o; o >>= 1) {
        s  += __shfl_xor_sync(~0u, s, o);
        sq += __shfl_xor_sync(~0u, sq, o);
    }
    float mu = s * (1.0f/DD);
    float var = sq * (1.0f/DD) - mu*mu;
    float rs = rsqrtf(var + 1e-5f);
    float4 gg = *(const float4*)(g + lane*4);
    float4 bb = *(const float4*)(bta + lane*4);
    float o0 = (v.x - mu)*rs*gg.x + bb.x;
    float o1 = (v.y - mu)*rs*gg.y + bb.y;
    float o2 = (v.z - mu)*rs*gg.z + bb.z;
    float o3 = (v.w - mu)*rs*gg.w + bb.w;
    uint32_t h01, l01, h23, l23;
    pack_split(o0, o1, h01, l01);
    pack_split(o2, o3, h23, l23);
    ((uint2*)d_hh)[(size_t)warp*32 + lane] = make_uint2(h01, h23);
    ((uint2*)d_hl)[(size_t)warp*32 + lane] = make_uint2(l01, l23);
}

// ---------------- per-sequence linear attention: (softmax_q @ softmax_k^T) @ v ----------------
#define SPAD 52
#define ATTN_SMEM ((6144*3 + LL*SPAD) * 4)    // 83712 B -> 2 CTAs/SM
__global__ void __launch_bounds__(256) k_attn() {
    extern __shared__ float sm[];
    float* Q  = sm;               // 48x128
    float* KK = sm + 6144;        // 48x128
    float* V  = sm + 12288;       // 48x128
    float* S  = sm + 18432;       // 48xSPAD
    int seq = blockIdx.x, tid = threadIdx.x;
    size_t base = (size_t)seq * 6144;
    for (int i = tid; i < 6144; i += 256) {
        Q[i] = d_qb[base+i]; KK[i] = d_kb[base+i]; V[i] = d_vb[base+i];
    }
    __syncthreads();
    int te = tid & 31, tg = tid >> 5;
    // Q row softmax * d^-0.5
    for (int l = tg*6; l < tg*6+6; ++l) {
        float4 v = *(float4*)&Q[l*128 + te*4];
        float mx = fmaxf(fmaxf(v.x, v.y), fmaxf(v.z, v.w));
        #pragma unroll
        for (int o = 16; o; o >>= 1) mx = fmaxf(mx, __shfl_xor_sync(~0u, mx, o));
        v.x = expf(v.x - mx); v.y = expf(v.y - mx);
        v.z = expf(v.z - mx); v.w = expf(v.w - mx);
        float s = v.x + v.y + v.z + v.w;
        #pragma unroll
        for (int o = 16; o; o >>= 1) s += __shfl_xor_sync(~0u, s, o);
        float f = 0.08838834764831845f / s;
        v.x *= f; v.y *= f; v.z *= f; v.w *= f;
        *(float4*)&Q[l*128 + te*4] = v;
    }
    // K col softmax over L
    if (tid < 128) {
        int c = tid;
        float mx = -1e30f;
        #pragma unroll
        for (int l = 0; l < LL; ++l) mx = fmaxf(mx, KK[l*128 + c]);
        float s = 0.f;
        float ev[LL];
        #pragma unroll
        for (int l = 0; l < LL; ++l) { ev[l] = expf(KK[l*128 + c] - mx); s += ev[l]; }
        float inv = 1.0f / s;
        #pragma unroll
        for (int l = 0; l < LL; ++l) KK[l*128 + c] = ev[l] * inv;
    }
    __syncthreads();
    // S[i][j] = sum_d Q[i][d]*KK[j][d]   (48x48, k=128)
    {
        int ty = tid >> 4, tx = tid & 15;
        int i0 = ty*3, j0 = tx*3;
        float a[3][3] = {};
        #pragma unroll
        for (int d4 = 0; d4 < 128; d4 += 4) {
            float4 q0 = *(float4*)&Q [(i0+0)*128 + d4];
            float4 q1 = *(float4*)&Q [(i0+1)*128 + d4];
            float4 q2 = *(float4*)&Q [(i0+2)*128 + d4];
            float4 k0 = *(float4*)&KK[(j0+0)*128 + d4];
            float4 k1 = *(float4*)&KK[(j0+1)*128 + d4];
            float4 k2 = *(float4*)&KK[(j0+2)*128 + d4];
            a[0][0] += q0.x*k0.x + q0.y*k0.y + q0.z*k0.z + q0.w*k0.w;
            a[0][1] += q0.x*k1.x + q0.y*k1.y + q0.z*k1.z + q0.w*k1.w;
            a[0][2] += q0.x*k2.x + q0.y*k2.y + q0.z*k2.z + q0.w*k2.w;
            a[1][0] += q1.x*k0.x + q1.y*k0.y + q1.z*k0.z + q1.w*k0.w;
            a[1][1] += q1.x*k1.x + q1.y*k1.y + q1.z*k1.z + q1.w*k1.w;
            a[1][2] += q1.x*k2.x + q1.y*k2.y + q1.z*k2.z + q1.w*k2.w;
            a[2][0] += q2.x*k0.x + q2.y*k0.y + q2.z*k0.z + q2.w*k0.w;
            a[2][1] += q2.x*k1.x + q2.y*k1.y + q2.z*k1.z + q2.w*k1.w;
            a[2][2] += q2.x*k2.x + q2.y*k2.y + q2.z*k2.z + q2.w*k2.w;
        }
        #pragma unroll
        for (int r = 0; r < 3; ++r)
            #pragma unroll
            for (int c = 0; c < 3; ++c)
                S[(i0+r)*SPAD + j0 + c] = a[r][c];
    }
    __syncthreads();
    // att[l][e] = sum_j S[l][j]*V[j][e]  -> split store to d_qh/d_ql
    {
        int ty = tid >> 4, tx = tid & 15;
        int l0 = ty*3, e0 = tx*8;
        float a[3][8] = {};
        #pragma unroll
        for (int j = 0; j < LL; ++j) {
            float s0 = S[(l0+0)*SPAD + j];
            float s1 = S[(l0+1)*SPAD + j];
            float s2 = S[(l0+2)*SPAD + j];
            float4 v0 = *(float4*)&V[j*128 + e0];
            float4 v1 = *(float4*)&V[j*128 + e0 + 4];
            a[0][0]+=s0*v0.x; a[0][1]+=s0*v0.y; a[0][2]+=s0*v0.z; a[0][3]+=s0*v0.w;
            a[0][4]+=s0*v1.x; a[0][5]+=s0*v1.y; a[0][6]+=s0*v1.z; a[0][7]+=s0*v1.w;
            a[1][0]+=s1*v0.x; a[1][1]+=s1*v0.y; a[1][2]+=s1*v0.z; a[1][3]+=s1*v0.w;
            a[1][4]+=s1*v1.x; a[1][5]+=s1*v1.y; a[1][6]+=s1*v1.z; a[1][7]+=s1*v1.w;
            a[2][0]+=s2*v0.x; a[2][1]+=s2*v0.y; a[2][2]+=s2*v0.z; a[2][3]+=s2*v0.w;
            a[2][4]+=s2*v1.x; a[2][5]+=s2*v1.y; a[2][6]+=s2*v1.z; a[2][7]+=s2*v1.w;
        }
        #pragma unroll
        for (int r = 0; r < 3; ++r) {
            #pragma unroll
            for (int c = 0; c < 8; c += 2) {
                uint32_t hp, lp;
                pack_split(a[r][c], a[r][c+1], hp, lp);
                size_t w2 = (base + (size_t)(l0+r)*128 + e0 + c) >> 1;
                ((uint32_t*)d_qh)[w2] = hp;
                ((uint32_t*)d_ql)[w2] = lp;
            }
        }
    }
}

// ---------------- 3x-bf16 split GEMM with pre-split inputs (Round-6 mainloop) ----------------
// epi: 0 store fp32 C; 2 gelu(+bias)->Oh/Ol; 3 C+= ; 5 ->Oh/Ol; 6 QKV route C/C2/C3
#define TGW 12
#define TG_SMEM (2*4*128*TGW*4)   // 49152 bytes
__global__ void __launch_bounds__(256) tgemm(
    const bf16* __restrict__ Ah, const bf16* __restrict__ Al,
    const bf16* __restrict__ Bh, const bf16* __restrict__ Bl,
    float* __restrict__ C, float* __restrict__ C2, float* __restrict__ C3,
    bf16* __restrict__ Oh, bf16* __restrict__ Ol,
    int M, int N, int K, const float* __restrict__ bias, int epi, int gswap)
{
    extern __shared__ uint32_t SMu[];
    const int tid = threadIdx.x;
    const int m0 = (gswap ? blockIdx.x : blockIdx.y) * 128;
    const int n0 = (gswap ? blockIdx.y : blockIdx.x) * 128;
    const int lrow = tid >> 1, comp = tid & 1;
    const int warp = tid >> 5, lane = tid & 31;
    const int wm = (warp >> 2) * 64, wn = (warp & 3) * 32;
    const int g = lane >> 2, tig = lane & 3;

    const bf16* Arow = (comp ? Al : Ah) + (size_t)(m0 + lrow) * K;
    const bf16* Brow = (comp ? Bl : Bh) + (size_t)(n0 + lrow) * K;
    const bool mok = (m0 + lrow) < M;

    float acc[4][4][4];
    #pragma unroll
    for (int a = 0; a < 4; ++a)
        #pragma unroll
        for (int b = 0; b < 4; ++b)
            #pragma unroll
            for (int c = 0; c < 4; ++c) acc[a][b][c] = 0.f;

    const int nk = (K + 15) / 16;
    uint4 pa0, pa1, pb0, pb1;
    const uint4 zz = make_uint4(0,0,0,0);

    #define FETCH(kt) do { \
        int k_ = (kt)*16; \
        pa0 = (mok && k_+8  <= K) ? *(const uint4*)(Arow + k_    ) : zz; \
        pa1 = (mok && k_+16 <= K) ? *(const uint4*)(Arow + k_ + 8) : zz; \
        pb0 = (k_+8  <= K) ? *(const uint4*)(Brow + k_    ) : zz; \
        pb1 = (k_+16 <= K) ? *(const uint4*)(Brow + k_ + 8) : zz; \
    } while (0)
    #define STORE(buf) do { \
        uint32_t* pA = SMu + (((buf)*4 + comp)*128 + lrow)*TGW; \
        pA[0]=pa0.x; pA[1]=pa0.y; pA[2]=pa0.z; pA[3]=pa0.w; \
        pA[4]=pa1.x; pA[5]=pa1.y; pA[6]=pa1.z; pA[7]=pa1.w; \
        uint32_t* pB = SMu + (((buf)*4 + 2 + comp)*128 + lrow)*TGW; \
        pB[0]=pb0.x; pB[1]=pb0.y; pB[2]=pb0.z; pB[3]=pb0.w; \
        pB[4]=pb1.x; pB[5]=pb1.y; pB[6]=pb1.z; pB[7]=pb1.w; \
    } while (0)

    FETCH(0); STORE(0);
    __syncthreads();

    int s = 0;
    for (int kt = 0; kt < nk; ++kt) {
        bool nxt = (kt + 1) < nk;
        if (nxt) FETCH(kt + 1);

        uint32_t ah[4][4], al[4][4], bh[4][2], bl[4][2];
        const uint32_t* Ah_s = SMu + ((s*4 + 0)*128)*TGW;
        const uint32_t* Al_s = SMu + ((s*4 + 1)*128)*TGW;
        const uint32_t* Bh_s = SMu + ((s*4 + 2)*128)*TGW;
        const uint32_t* Bl_s = SMu + ((s*4 + 3)*128)*TGW;
        #pragma unroll
        for (int mi = 0; mi < 4; ++mi) {
            int r = wm + mi*16 + g;
            ah[mi][0] = Ah_s[ r     *TGW + tig    ];
            ah[mi][1] = Ah_s[(r + 8)*TGW + tig    ];
            ah[mi][2] = Ah_s[ r     *TGW + tig + 4];
            ah[mi][3] = Ah_s[(r + 8)*TGW + tig + 4];
            al[mi][0] = Al_s[ r     *TGW + tig    ];
            al[mi][1] = Al_s[(r + 8)*TGW + tig    ];
            al[mi][2] = Al_s[ r     *TGW + tig + 4];
            al[mi][3] = Al_s[(r + 8)*TGW + tig + 4];
        }
        #pragma unroll
        for (int ni = 0; ni < 4; ++ni) {
            int r = wn + ni*8 + g;
            bh[ni][0] = Bh_s[r*TGW + tig    ];
            bh[ni][1] = Bh_s[r*TGW + tig + 4];
            bl[ni][0] = Bl_s[r*TGW + tig    ];
            bl[ni][1] = Bl_s[r*TGW + tig + 4];
        }
        #pragma unroll
        for (int mi = 0; mi < 4; ++mi)
            #pragma unroll
            for (int ni = 0; ni < 4; ++ni) {
                asm volatile(
                    "mma.sync.aligned.m16n8k16.row.col.f32.bf16.bf16.f32 "
                    "{%0,%1,%2,%3}, {%4,%5,%6,%7}, {%8,%9}, {%0,%1,%2,%3};"
                    : "+f"(acc[mi][ni][0]), "+f"(acc[mi][ni][1]),
                      "+f"(acc[mi][ni][2]), "+f"(acc[mi][ni][3])
                    : "r"(ah[mi][0]), "r"(ah[mi][1]), "r"(ah[mi][2]), "r"(ah[mi][3]),
                      "r"(bl[ni][0]), "r"(bl[ni][1]));
                asm volatile(
                    "mma.sync.aligned.m16n8k16.row.col.f32.bf16.bf16.f32 "
                    "{%0,%1,%2,%3}, {%4,%5,%6,%7}, {%8,%9}, {%0,%1,%2,%3};"
                    : "+f"(acc[mi][ni][0]), "+f"(acc[mi][ni][1]),
                      "+f"(acc[mi][ni][2]), "+f"(acc[mi][ni][3])
                    : "r"(al[mi][0]), "r"(al[mi][1]), "r"(al[mi][2]), "r"(al[mi][3]),
                      "r"(bh[ni][0]), "r"(bh[ni][1]));
                asm volatile(
                    "mma.sync.aligned.m16n8k16.row.col.f32.bf16.bf16.f32 "
                    "{%0,%1,%2,%3}, {%4,%5,%6,%7}, {%8,%9}, {%0,%1,%2,%3};"
                    : "+f"(acc[mi][ni][0]), "+f"(acc[mi][ni][1]),
                      "+f"(acc[mi][ni][2]), "+f"(acc[mi][ni][3])
                    : "r"(ah[mi][0]), "r"(ah[mi][1]), "r"(ah[mi][2]), "r"(ah[mi][3]),
                      "r"(bh[ni][0]), "r"(bh[ni][1]));
            }
        if (nxt) STORE(s ^ 1);
        __syncthreads();
        s ^= 1;
    }
    #undef FETCH
    #undef STORE

    // epilogue
    #pragma unroll
    for (int mi = 0; mi < 4; ++mi) {
        #pragma unroll
        for (int ni = 0; ni < 4; ++ni) {
            int n = n0 + wn + ni*8 + tig*2;
            float bv0 = 0.f, bv1 = 0.f;
            if (bias) { bv0 = bias[n]; bv1 = bias[n+1]; }
            #pragma unroll
            for (int half = 0; half < 2; ++half) {
                int m = m0 + wm + mi*16 + g + half*8;
                if (m >= M) continue;
                float r0 = acc[mi][ni][half*2+0] + bv0;
                float r1 = acc[mi][ni][half*2+1] + bv1;
                size_t off = (size_t)m * N + n;
                if (epi == 0) {
                    *(float2*)(C + off) = make_float2(r0, r1);
                } else if (epi == 2) {
                    r0 = gelu_exact(r0); r1 = gelu_exact(r1);
                    uint32_t hp, lp;
                    pack_split(r0, r1, hp, lp);
                    ((uint32_t*)Oh)[off >> 1] = hp;
                    ((uint32_t*)Ol)[off >> 1] = lp;
                } else if (epi == 3) {
                    float2 cur = *(float2*)(C + off);
                    *(float2*)(C + off) = make_float2(r0 + cur.x, r1 + cur.y);
                } else if (epi == 5) {
                    uint32_t hp, lp;
                    pack_split(r0, r1, hp, lp);
                    ((uint32_t*)Oh)[off >> 1] = hp;
                    ((uint32_t*)Ol)[off >> 1] = lp;
                } else { // 6: QKV routing
                    int buf = n >> 7, col = n & 127;
                    float* Cd = (buf == 0) ? C : (buf == 1 ? C2 : C3);
                    *(float2*)(Cd + ((size_t)m << 7) + col) = make_float2(r0, r1);
                }
            }
        }
    }
}

// ---------------- transpose enc -> X[(bl*128+d)][n], split bf16 out ----------------
__global__ void k_transpose() {   // grid (94, 96), 256 threads
    __shared__ float T[32*129];
    int n0 = blockIdx.x * 32;
    int bl = blockIdx.y;
    int b = bl / LL, l = bl % LL;
    int tid = threadIdx.x;
    int nrem = NN - n0; if (nrem > 32) nrem = 32;
    for (int i = tid; i < 32*128; i += 256) {
        int r = i >> 7, c = i & 127;
        if (r < nrem)
            T[r*129 + c] = d_enc[((size_t)(b*NN + n0 + r))*6144 + l*128 + c];
    }
    __syncthreads();
    for (int i = tid; i < 128*32; i += 256) {
        int dd = i >> 5, j = i & 31;
        if (j < nrem) {
            float v = T[j*129 + dd];
            size_t o = ((size_t)(bl*128 + dd))*NN + n0 + j;
            scalar_split(v, d_Xh[o], d_Xl[o]);
        }
    }
}

// ---------------- GroupNorm stat zero / finalize ----------------
__global__ void k_gzero() {
    int i = threadIdx.x;   // 384
    d_gsum[i] = 0.f; d_gsq[i] = 0.f;
}
__global__ void k_gnfin() {
    int i = threadIdx.x;   // 384
    const float inv = 1.0f / (float)(NN*32);
    float mu = d_gsum[i] * inv;
    float var = d_gsq[i] * inv - mu*mu;
    d_gmu[i] = mu;
    d_grs[i] = rsqrtf(var + 1e-5f);
}

// ---------------- tensorized per-node grouped GEMM + fused GN partial stats ----------------
#define SA 68
#define GRP2_STATS (2*96*SA + 2*128*SA)            // u32 offset of stats region
#define GRP2_SMEM ((GRP2_STATS + 768) * 4)         // +3KB for stats
__global__ void __launch_bounds__(256) k_grouped2() {
    extern __shared__ uint32_t SMu[];
    uint32_t* Ah_s = SMu;
    uint32_t* Al_s = SMu + 96*SA;
    uint32_t* Bh_s = SMu + 2*96*SA;
    uint32_t* Bl_s = SMu + 2*96*SA + 128*SA;
    float* s_sum = (float*)(SMu + GRP2_STATS);       // 384
    float* s_sq  = (float*)(SMu + GRP2_STATS + 384); // 384
    int node = blockIdx.x, tid = threadIdx.x;
    for (int i = tid; i < 384; i += 256) { s_sum[i] = 0.f; s_sq[i] = 0.f; }
    const uint4* agh = (const uint4*)(d_aggh + (size_t)node * 12288);
    const uint4* agl = (const uint4*)(d_aggl + (size_t)node * 12288);
    const uint4* pwh = (const uint4*)(d_pwh + (size_t)node * 16384);
    const uint4* pwl = (const uint4*)(d_pwl + (size_t)node * 16384);
    for (int i = tid; i < 1536; i += 256) {
        int r = i >> 4, c = (i & 15) * 4;
        *(uint4*)(Ah_s + r*SA + c) = agh[i];
        *(uint4*)(Al_s + r*SA + c) = agl[i];
    }
    for (int i = tid; i < 2048; i += 256) {
        int r = i >> 4, c = (i & 15) * 4;
        *(uint4*)(Bh_s + r*SA + c) = pwh[i];
        *(uint4*)(Bl_s + r*SA + c) = pwl[i];
    }
    __syncthreads();

    int warp = tid >> 5, lane = tid & 31;
    int wm = (warp >> 2) * 48, wn = (warp & 3) * 32;
    int g = lane >> 2, tig = lane & 3;
    float acc[3][4][4];
    #pragma unroll
    for (int a = 0; a < 3; ++a)
        #pragma unroll
        for (int b = 0; b < 4; ++b)
            #pragma unroll
            for (int c = 0; c < 4; ++c) acc[a][b][c] = 0.f;

    #pragma unroll
    for (int kt = 0; kt < 8; ++kt) {
        uint32_t ah[3][4], al[3][4], bh[4][2], bl[4][2];
        int kb = kt*8 + tig;
        #pragma unroll
        for (int mi = 0; mi < 3; ++mi) {
            int r = wm + mi*16 + g;
            ah[mi][0] = Ah_s[ r     *SA + kb    ];
            ah[mi][1] = Ah_s[(r + 8)*SA + kb    ];
            ah[mi][2] = Ah_s[ r     *SA + kb + 4];
            ah[mi][3] = Ah_s[(r + 8)*SA + kb + 4];
            al[mi][0] = Al_s[ r     *SA + kb    ];
            al[mi][1] = Al_s[(r + 8)*SA + kb    ];
            al[mi][2] = Al_s[ r     *SA + kb + 4];
            al[mi][3] = Al_s[(r + 8)*SA + kb + 4];
        }
        #pragma unroll
        for (int ni = 0; ni < 4; ++ni) {
            int r = wn + ni*8 + g;
            bh[ni][0] = Bh_s[r*SA + kb    ];
            bh[ni][1] = Bh_s[r*SA + kb + 4];
            bl[ni][0] = Bl_s[r*SA + kb    ];
            bl[ni][1] = Bl_s[r*SA + kb + 4];
        }
        #pragma unroll
        for (int mi = 0; mi < 3; ++mi)
            #pragma unroll
            for (int ni = 0; ni < 4; ++ni) {
                asm volatile(
                    "mma.sync.aligned.m16n8k16.row.col.f32.bf16.bf16.f32 "
                    "{%0,%1,%2,%3}, {%4,%5,%6,%7}, {%8,%9}, {%0,%1,%2,%3};"
                    : "+f"(acc[mi][ni][0]), "+f"(acc[mi][ni][1]),
                      "+f"(acc[mi][ni][2]), "+f"(acc[mi][ni][3])
                    : "r"(ah[mi][0]), "r"(ah[mi][1]), "r"(ah[mi][2]), "r"(ah[mi][3]),
                      "r"(bl[ni][0]), "r"(bl[ni][1]));
                asm volatile(
                    "mma.sync.aligned.m16n8k16.row.col.f32.bf16.bf16.f32 "
                    "{%0,%1,%2,%3}, {%4,%5,%6,%7}, {%8,%9}, {%0,%1,%2,%3};"
                    : "+f"(acc[mi][ni][0]), "+f"(acc[mi][ni][1]),
                      "+f"(acc[mi][ni][2]), "+f"(acc[mi][ni][3])
                    : "r"(al[mi][0]), "r"(al[mi][1]), "r"(al[mi][2]), "r"(al[mi][3]),
                      "r"(bh[ni][0]), "r"(bh[ni][1]));
                asm volatile(
                    "mma.sync.aligned.m16n8k16.row.col.f32.bf16.bf16.f32 "
                    "{%0,%1,%2,%3}, {%4,%5,%6,%7}, {%8,%9}, {%0,%1,%2,%3};"
                    : "+f"(acc[mi][ni][0]), "+f"(acc[mi][ni][1]),
                      "+f"(acc[mi][ni][2]), "+f"(acc[mi][ni][3])
                    : "r"(ah[mi][0]), "r"(ah[mi][1]), "r"(ah[mi][2]), "r"(ah[mi][3]),
                      "r"(bh[ni][0]), "r"(bh[ni][1]));
            }
    }

    float* outp = d_gout + (size_t)node * 12288;
    #pragma unroll
    for (int mi = 0; mi < 3; ++mi)
        #pragma unroll
        for (int ni = 0; ni < 4; ++ni) {
            int n = wn + ni*8 + tig*2;
            int sidx = (n >> 5);    // group of col n (n, n+1 same group)
            #pragma unroll
            for (int half = 0; half < 2; ++half) {
                int m = wm + mi*16 + g + half*8;
                float v0 = acc[mi][ni][half*2+0];
                float v1 = acc[mi][ni][half*2+1];
                *(float2*)(outp + m*128 + n) = make_float2(v0, v1);
                atomicAdd(&s_sum[m*4 + sidx], v0 + v1);
                atomicAdd(&s_sq [m*4 + sidx], v0*v0 + v1*v1);
            }
        }
    __syncthreads();
    for (int i = tid; i < 384; i += 256) {
        atomicAdd(&d_gsum[i], s_sum[i]);
        atomicAdd(&d_gsq [i], s_sq [i]);
    }
}

// ---------------- fused GN-apply + SiLU proj + time proj + mean add ----------------
__global__ void k_final(const float* __restrict__ gg, const float* __restrict__ gb,
                        const float* __restrict__ p2w, const float* __restrict__ p2b,
                        const float* __restrict__ p1w, const float* __restrict__ p1b,
                        float* __restrict__ out) {
    __shared__ float Xs[6144];
    __shared__ float Ss[LL];
    int bn = blockIdx.x;
    int b = bn / NN, n = bn % NN;
    int tid = threadIdx.x;   // 256
    for (int i = tid; i < 6144; i += 256) {
        int l = i >> 7, c = i & 127;
        int bl = b*LL + l, g = c >> 5;
        float v = d_gout[(size_t)n*12288 + bl*128 + c];
        Xs[i] = (v - d_gmu[bl*4+g]) * d_grs[bl*4+g] * gg[c] + gb[c];
    }
    __syncthreads();
    int lane = tid & 31, w = tid >> 5;
    for (int l = w*6; l < w*6+6; ++l) {
        float s = Xs[l*128+lane]*p2w[lane] + Xs[l*128+lane+32]*p2w[lane+32]
                + Xs[l*128+lane+64]*p2w[lane+64] + Xs[l*128+lane+96]*p2w[lane+96];
        #pragma unroll
        for (int o = 16; o; o >>= 1) s += __shfl_xor_sync(~0u, s, o);
        if (lane == 0) {
            float z = s + p2b[0];
            Ss[l] = z / (1.0f + expf(-z));
        }
    }
    __syncthreads();
    if (tid < L_OUT) {
        float acc = p1b[tid];
        #pragma unroll
        for (int l = 0; l < LL; ++l) acc += Ss[l] * p1w[tid*LL + l];
        out[((size_t)(b*L_OUT + tid))*NN + n] = acc + d_mean[bn];
    }
}

// ---------------- launcher ----------------
extern "C" void kernel_launch(void* const* d_in, const int* in_sizes, int n_in,
                              void* d_out, int out_size) {
    const float* x_enc   = (const float*)d_in[0];
    const float* adj     = (const float*)d_in[1];
    const float* pe_raw  = (const float*)d_in[2];
    const float* conv_w  = (const float*)d_in[3];
    const float* pos_w   = (const float*)d_in[4];
    const float* pos_b   = (const float*)d_in[5];
    const float* wq      = (const float*)d_in[6];
    const float* wk      = (const float*)d_in[7];
    const float* wv      = (const float*)d_in[8];
    const float* wo      = (const float*)d_in[9];
    const float* ln1_g   = (const float*)d_in[10];
    const float* ln1_b   = (const float*)d_in[11];
    const float* ff_w1   = (const float*)d_in[12];
    const float* ff_b1   = (const float*)d_in[13];
    const float* ff_w2   = (const float*)d_in[14];
    const float* ff_b2   = (const float*)d_in[15];
    const float* ln2_g   = (const float*)d_in[16];
    const float* ln2_b   = (const float*)d_in[17];
    const float* wpool   = (const float*)d_in[18];
    const float* gn_g    = (const float*)d_in[19];
    const float* gn_b    = (const float*)d_in[20];
    const float* p2_w    = (const float*)d_in[21];
    const float* p2_b    = (const float*)d_in[22];
    const float* p1_w    = (const float*)d_in[23];
    const float* p1_b    = (const float*)d_in[24];
    float* out = (float*)d_out;

    float *p_enc, *p_q, *p_k, *p_v;
    bf16 *p_hh, *p_hl, *p_qh, *p_ql, *p_ffh, *p_ffl, *p_adjh, *p_adjl;
    bf16 *p_Xh, *p_Xl, *p_peTh, *p_peTl, *p_WT2h, *p_WT2l, *p_pe2h, *p_pe2l;
    bf16 *p_aggh, *p_aggl, *p_pwh, *p_pwl, *p_wph, *p_wpl;
    cudaGetSymbolAddress((void**)&p_enc, d_enc);
    cudaGetSymbolAddress((void**)&p_q,   d_qb);
    cudaGetSymbolAddress((void**)&p_k,   d_kb);
    cudaGetSymbolAddress((void**)&p_v,   d_vb);
    cudaGetSymbolAddress((void**)&p_hh,  d_hh);
    cudaGetSymbolAddress((void**)&p_hl,  d_hl);
    cudaGetSymbolAddress((void**)&p_qh,  d_qh);
    cudaGetSymbolAddress((void**)&p_ql,  d_ql);
    cudaGetSymbolAddress((void**)&p_ffh, d_ffh);
    cudaGetSymbolAddress((void**)&p_ffl, d_ffl);
    cudaGetSymbolAddress((void**)&p_adjh, d_adjh);
    cudaGetSymbolAddress((void**)&p_adjl, d_adjl);
    cudaGetSymbolAddress((void**)&p_Xh,  d_Xh);
    cudaGetSymbolAddress((void**)&p_Xl,  d_Xl);
    cudaGetSymbolAddress((void**)&p_peTh, d_peTh);
    cudaGetSymbolAddress((void**)&p_peTl, d_peTl);
    cudaGetSymbolAddress((void**)&p_WT2h, d_WT2h);
    cudaGetSymbolAddress((void**)&p_WT2l, d_WT2l);
    cudaGetSymbolAddress((void**)&p_pe2h, d_pe2h);
    cudaGetSymbolAddress((void**)&p_pe2l, d_pe2l);
    cudaGetSymbolAddress((void**)&p_aggh, d_aggh);
    cudaGetSymbolAddress((void**)&p_aggl, d_aggl);
    cudaGetSymbolAddress((void**)&p_pwh, d_pwh);
    cudaGetSymbolAddress((void**)&p_pwl, d_pwl);
    cudaGetSymbolAddress((void**)&p_wph, d_wph);
    cudaGetSymbolAddress((void**)&p_wpl, d_wpl);

    cudaFuncSetAttribute(k_attn,     cudaFuncAttributeMaxDynamicSharedMemorySize, ATTN_SMEM);
    cudaFuncSetAttribute(tgemm,      cudaFuncAttributeMaxDynamicSharedMemorySize, TG_SMEM);
    cudaFuncSetAttribute(k_grouped2, cudaFuncAttributeMaxDynamicSharedMemorySize, GRP2_SMEM);

    // prep + splits
    k_mean<<<(BNN+255)/256, 256>>>(x_enc);
    k_peT<<<(DD*NN+255)/256, 256>>>(pe_raw, pos_w, pos_b);
    k_WT2<<<(DD*DD*DD+255)/256, 256>>>(wpool);
    k_conv<<<BNN, 128>>>(x_enc, conv_w);
    k_split<<<(NN*NN+255)/256, 256>>>(adj, p_adjh, p_adjl, NN*NN);
    k_splitW<<<768, 256>>>(wq, wk, wv, wo, ff_w1, ff_w2);
    k_gzero<<<1, 384>>>();

    // temporal transformer
    k_ln<<<ROWS/8, 256>>>(p_enc, ln1_g, ln1_b);
    tgemm<<<dim3(3, ROWS/128), 256, TG_SMEM>>>(p_hh, p_hl, p_wph+WPO_Q, p_wpl+WPO_Q,
        p_q, p_k, p_v, nullptr, nullptr, ROWS, 384, 128, nullptr, 6, 0);
    k_attn<<<BNN, 256, ATTN_SMEM>>>();
    tgemm<<<dim3(1, ROWS/128), 256, TG_SMEM>>>(p_qh, p_ql, p_wph+WPO_O, p_wpl+WPO_O,
        p_enc, nullptr, nullptr, nullptr, nullptr, ROWS, 128, 128, nullptr, 3, 0);
    k_ln<<<ROWS/8, 256>>>(p_enc, ln2_g, ln2_b);
    tgemm<<<dim3(4, ROWS/128), 256, TG_SMEM>>>(p_hh, p_hl, p_wph+WPO_F1, p_wpl+WPO_F1,
        nullptr, nullptr, nullptr, p_ffh, p_ffl, ROWS, 512, 128, ff_b1, 2, 0);
    tgemm<<<dim3(1, ROWS/128), 256, TG_SMEM>>>(p_ffh, p_ffl, p_wph+WPO_F2, p_wpl+WPO_F2,
        p_enc, nullptr, nullptr, nullptr, nullptr, ROWS, 128, 512, ff_b2, 3, 0);

    // spatial GCN
    k_transpose<<<dim3(94, BLL), 256>>>();
    tgemm<<<dim3(1, 24), 256, TG_SMEM>>>(p_adjh, p_adjl, p_peTh, p_peTl,
        nullptr, nullptr, nullptr, p_pe2h, p_pe2l, NN, 128, NN, nullptr, 5, 0);
    tgemm<<<dim3(128, 24), 256, TG_SMEM>>>(p_pe2h, p_pe2l, p_WT2h, p_WT2l,
        nullptr, nullptr, nullptr, p_pwh, p_pwl, NN, 16384, 128, nullptr, 5, 0);
    tgemm<<<dim3(24, 96), 256, TG_SMEM>>>(p_adjh, p_adjl, p_Xh, p_Xl,
        nullptr, nullptr, nullptr, p_aggh, p_aggl, NN, 12288, NN, nullptr, 5, 1);
    k_grouped2<<<NN, 256, GRP2_SMEM>>>();

    // groupnorm + head
    k_gnfin<<<1, 384>>>();
    k_final<<<BNN, 256>>>(gn_g, gn_b, p2_w, p2_b, p1_w, p1_b, out);
}

// round 11
// speedup vs baseline: 1.7537x; 1.7537x over previous
#include <cuda_runtime.h>
#include <cuda_bf16.h>
#include <math.h>
#include <stdint.h>

#define BB 2
#define LL 48
#define NN 3000
#define DD 128
#define L_OUT 24
#define BNN (BB*NN)          // 6000
#define BLL (BB*LL)          // 96
#define ROWS (BNN*LL)        // 288000 token rows
#define ENC_N (ROWS*DD)      // 36,864,000

typedef __nv_bfloat16 bf16;

// ---------------- scratch (device globals; no runtime allocation) ----------------
__device__ float d_mean[BNN];
__device__ float d_enc[ENC_N];           // enc[seq][l][c]
__device__ float d_qb[ENC_N];            // q fp32 (raw)
__device__ float d_kb[ENC_N];
__device__ float d_vb[ENC_N];
__device__ float d_gout[NN*BLL*DD];      // gout[n][bl][o]
__device__ float d_gmu[BLL*4];
__device__ float d_grs[BLL*4];
__device__ float d_gsum[BLL*4];
__device__ float d_gsq[BLL*4];

// bf16 split pairs
__device__ bf16 d_hh[ENC_N],  d_hl[ENC_N];     // LN output
__device__ bf16 d_qh[ENC_N],  d_ql[ENC_N];     // att_pre
__device__ bf16 d_ffh[ROWS*512], d_ffl[ROWS*512];
__device__ bf16 d_adjh[NN*NN], d_adjl[NN*NN];
__device__ bf16 d_Xh[BLL*DD*NN], d_Xl[BLL*DD*NN];
__device__ bf16 d_peTh[DD*NN], d_peTl[DD*NN];
__device__ bf16 d_WT2h[DD*DD*DD], d_WT2l[DD*DD*DD];  // [(o*128+i)][d]
__device__ bf16 d_pe2h[NN*DD], d_pe2l[NN*DD];
__device__ bf16 d_aggh[NN*BLL*DD], d_aggl[NN*BLL*DD]; // [n][bl*128+i]
__device__ bf16 d_pwh[NN*DD*DD], d_pwl[NN*DD*DD];     // [n][o*128+i]
// weight pool: [wq|wk|wv|wo|ffw1|ffw2]
#define WPO_Q 0
#define WPO_K 16384
#define WPO_V 32768
#define WPO_O 49152
#define WPO_F1 65536
#define WPO_F2 131072
__device__ bf16 d_wph[196608], d_wpl[196608];

__device__ __forceinline__ float gelu_exact(float x) {
    return 0.5f * x * (1.0f + erff(x * 0.70710678118654752f));
}
__device__ __forceinline__ void pack_split(float x0, float x1, uint32_t& hi, uint32_t& lo) {
    uint32_t h;
    asm("cvt.rn.bf16x2.f32 %0, %1, %2;" : "=r"(h) : "f"(x1), "f"(x0));
    float h0 = __uint_as_float(h << 16);
    float h1 = __uint_as_float(h & 0xFFFF0000u);
    float r0 = x0 - h0, r1 = x1 - h1;
    uint32_t l;
    asm("cvt.rn.bf16x2.f32 %0, %1, %2;" : "=r"(l) : "f"(r1), "f"(r0));
    hi = h; lo = l;
}
__device__ __forceinline__ void scalar_split(float v, bf16& h, bf16& l) {
    h = __float2bfloat16_rn(v);
    l = __float2bfloat16_rn(v - __bfloat162float(h));
}
__device__ __forceinline__ void ldsm_x4(uint32_t& r0, uint32_t& r1, uint32_t& r2, uint32_t& r3,
                                        uint32_t addr) {
    asm volatile("ldmatrix.sync.aligned.m8n8.x4.shared.b16 {%0,%1,%2,%3}, [%4];"
                 : "=r"(r0), "=r"(r1), "=r"(r2), "=r"(r3) : "r"(addr));
}
__device__ __forceinline__ void cp16(uint32_t dst, const void* src, bool pred) {
    int sz = pred ? 16 : 0;
    asm volatile("cp.async.cg.shared.global [%0], [%1], 16, %2;\n"
                 :: "r"(dst), "l"(src), "r"(sz) : "memory");
}
#define CP_COMMIT() asm volatile("cp.async.commit_group;\n" ::: "memory")
#define CP_WAIT0()  asm volatile("cp.async.wait_group 0;\n" ::: "memory")

// ---------------- small prep kernels ----------------
__global__ void k_mean(const float* __restrict__ x) {
    int i = blockIdx.x * blockDim.x + threadIdx.x;
    if (i >= BNN) return;
    int b = i / NN, n = i % NN;
    float s = 0.f;
    #pragma unroll
    for (int l = 0; l < LL; ++l) s += x[(b*LL + l)*NN + n];
    d_mean[i] = s * (1.0f / LL);
}

__global__ void k_split(const float* __restrict__ in, bf16* __restrict__ h,
                        bf16* __restrict__ l, int n) {
    int i = blockIdx.x * blockDim.x + threadIdx.x;
    if (i >= n) return;
    scalar_split(in[i], h[i], l[i]);
}

// merged split of all dense weights into the pool
__global__ void k_splitW(const float* __restrict__ wq, const float* __restrict__ wk,
                         const float* __restrict__ wv, const float* __restrict__ wo,
                         const float* __restrict__ f1, const float* __restrict__ f2) {
    int i = blockIdx.x * blockDim.x + threadIdx.x;
    if (i >= 196608) return;
    float v;
    if (i < 65536) {
        int j = i & 16383;
        v = (i < 16384) ? wq[j] : (i < 32768) ? wk[j] : (i < 49152) ? wv[j] : wo[j];
    } else if (i < 131072) {
        v = f1[i - 65536];
    } else {
        v = f2[i - 131072];
    }
    scalar_split(v, d_wph[i], d_wpl[i]);
}

__global__ void k_peT(const float* __restrict__ pr, const float* __restrict__ pw,
                      const float* __restrict__ pb) {
    int i = blockIdx.x * blockDim.x + threadIdx.x;
    if (i >= DD*NN) return;
    int d = i / NN, n = i % NN;
    float v = pr[n]*pw[d*3] + pr[NN+n]*pw[d*3+1] + pr[2*NN+n]*pw[d*3+2] + pb[d];
    scalar_split(v, d_peTh[i], d_peTl[i]);
}

// WT2[(o*128+i)][d] = wp[(d*128+i)][o]
__global__ void k_WT2(const float* __restrict__ wp) {
    int idx = blockIdx.x * blockDim.x + threadIdx.x;
    if (idx >= DD*DD*DD) return;
    int d = idx & 127;
    int nrow = idx >> 7;          // o*128+i
    int i = nrow & 127, o = nrow >> 7;
    scalar_split(wp[(d*128 + i)*128 + o], d_WT2h[idx], d_WT2l[idx]);
}

// circular conv1d k=3: enc[seq][l][c]
__global__ void k_conv(const float* __restrict__ x, const float* __restrict__ cw) {
    __shared__ float xs[LL + 2];
    int seq = blockIdx.x;
    int b = seq / NN, n = seq % NN;
    float m = d_mean[seq];
    int t = threadIdx.x;   // 128
    if (t < LL) xs[t + 1] = x[(b*LL + t)*NN + n] - m;
    __syncthreads();
    if (t == 0) { xs[0] = xs[LL]; xs[LL+1] = xs[1]; }
    __syncthreads();
    float w0 = cw[t*3], w1 = cw[t*3+1], w2 = cw[t*3+2];
    float* out = d_enc + (size_t)seq * (LL*DD);
    #pragma unroll
    for (int l = 0; l < LL; ++l)
        out[l*DD + t] = w0*xs[l] + w1*xs[l+1] + w2*xs[l+2];
}

// LayerNorm over rows of 128 (one warp per row), writes split bf16 pair
__global__ void k_ln(const float* __restrict__ X,
                     const float* __restrict__ g, const float* __restrict__ bta) {
    int warp = (blockIdx.x * blockDim.x + threadIdx.x) >> 5;
    int lane = threadIdx.x & 31;
    const float* xr = X + (size_t)warp * DD;
    float4 v = *(const float4*)(xr + lane*4);
    float s = v.x + v.y + v.z + v.w;
    float sq = v.x*v.x + v.y*v.y + v.z*v.z + v.w*v.w;
    #pragma unroll
    for (int o = 16; o; o >>= 1) {
        s  += __shfl_xor_sync(~0u, s, o);
        sq += __shfl_xor_sync(~0u, sq, o);
    }
    float mu = s * (1.0f/DD);
    float var = sq * (1.0f/DD) - mu*mu;
    float rs = rsqrtf(var + 1e-5f);
    float4 gg = *(const float4*)(g + lane*4);
    float4 bb = *(const float4*)(bta + lane*4);
    float o0 = (v.x - mu)*rs*gg.x + bb.x;
    float o1 = (v.y - mu)*rs*gg.y + bb.y;
    float o2 = (v.z - mu)*rs*gg.z + bb.z;
    float o3 = (v.w - mu)*rs*gg.w + bb.w;
    uint32_t h01, l01, h23, l23;
    pack_split(o0, o1, h01, l01);
    pack_split(o2, o3, h23, l23);
    ((uint2*)d_hh)[(size_t)warp*32 + lane] = make_uint2(h01, h23);
    ((uint2*)d_hl)[(size_t)warp*32 + lane] = make_uint2(l01, l23);
}

// ---------------- per-sequence linear attention: (softmax_q @ softmax_k^T) @ v ----------------
#define SPAD 52
#define ATTN_SMEM ((6144*3 + LL*SPAD) * 4)    // 83712 B -> 2 CTAs/SM
__global__ void __launch_bounds__(256) k_attn() {
    extern __shared__ float sm[];
    float* Q  = sm;               // 48x128
    float* KK = sm + 6144;        // 48x128
    float* V  = sm + 12288;       // 48x128
    float* S  = sm + 18432;       // 48xSPAD
    int seq = blockIdx.x, tid = threadIdx.x;
    size_t base = (size_t)seq * 6144;
    for (int i = tid; i < 6144; i += 256) {
        Q[i] = d_qb[base+i]; KK[i] = d_kb[base+i]; V[i] = d_vb[base+i];
    }
    __syncthreads();
    int te = tid & 31, tg = tid >> 5;
    // Q row softmax * d^-0.5
    for (int l = tg*6; l < tg*6+6; ++l) {
        float4 v = *(float4*)&Q[l*128 + te*4];
        float mx = fmaxf(fmaxf(v.x, v.y), fmaxf(v.z, v.w));
        #pragma unroll
        for (int o = 16; o; o >>= 1) mx = fmaxf(mx, __shfl_xor_sync(~0u, mx, o));
        v.x = expf(v.x - mx); v.y = expf(v.y - mx);
        v.z = expf(v.z - mx); v.w = expf(v.w - mx);
        float s = v.x + v.y + v.z + v.w;
        #pragma unroll
        for (int o = 16; o; o >>= 1) s += __shfl_xor_sync(~0u, s, o);
        float f = 0.08838834764831845f / s;
        v.x *= f; v.y *= f; v.z *= f; v.w *= f;
        *(float4*)&Q[l*128 + te*4] = v;
    }
    // K col softmax over L
    if (tid < 128) {
        int c = tid;
        float mx = -1e30f;
        #pragma unroll
        for (int l = 0; l < LL; ++l) mx = fmaxf(mx, KK[l*128 + c]);
        float s = 0.f;
        float ev[LL];
        #pragma unroll
        for (int l = 0; l < LL; ++l) { ev[l] = expf(KK[l*128 + c] - mx); s += ev[l]; }
        float inv = 1.0f / s;
        #pragma unroll
        for (int l = 0; l < LL; ++l) KK[l*128 + c] = ev[l] * inv;
    }
    __syncthreads();
    // S[i][j] = sum_d Q[i][d]*KK[j][d]   (48x48, k=128)
    {
        int ty = tid >> 4, tx = tid & 15;
        int i0 = ty*3, j0 = tx*3;
        float a[3][3] = {};
        #pragma unroll
        for (int d4 = 0; d4 < 128; d4 += 4) {
            float4 q0 = *(float4*)&Q [(i0+0)*128 + d4];
            float4 q1 = *(float4*)&Q [(i0+1)*128 + d4];
            float4 q2 = *(float4*)&Q [(i0+2)*128 + d4];
            float4 k0 = *(float4*)&KK[(j0+0)*128 + d4];
            float4 k1 = *(float4*)&KK[(j0+1)*128 + d4];
            float4 k2 = *(float4*)&KK[(j0+2)*128 + d4];
            a[0][0] += q0.x*k0.x + q0.y*k0.y + q0.z*k0.z + q0.w*k0.w;
            a[0][1] += q0.x*k1.x + q0.y*k1.y + q0.z*k1.z + q0.w*k1.w;
            a[0][2] += q0.x*k2.x + q0.y*k2.y + q0.z*k2.z + q0.w*k2.w;
            a[1][0] += q1.x*k0.x + q1.y*k0.y + q1.z*k0.z + q1.w*k0.w;
            a[1][1] += q1.x*k1.x + q1.y*k1.y + q1.z*k1.z + q1.w*k1.w;
            a[1][2] += q1.x*k2.x + q1.y*k2.y + q1.z*k2.z + q1.w*k2.w;
            a[2][0] += q2.x*k0.x + q2.y*k0.y + q2.z*k0.z + q2.w*k0.w;
            a[2][1] += q2.x*k1.x + q2.y*k1.y + q2.z*k1.z + q2.w*k1.w;
            a[2][2] += q2.x*k2.x + q2.y*k2.y + q2.z*k2.z + q2.w*k2.w;
        }
        #pragma unroll
        for (int r = 0; r < 3; ++r)
            #pragma unroll
            for (int c = 0; c < 3; ++c)
                S[(i0+r)*SPAD + j0 + c] = a[r][c];
    }
    __syncthreads();
    // att[l][e] = sum_j S[l][j]*V[j][e]  -> split store to d_qh/d_ql
    {
        int ty = tid >> 4, tx = tid & 15;
        int l0 = ty*3, e0 = tx*8;
        float a[3][8] = {};
        #pragma unroll
        for (int j = 0; j < LL; ++j) {
            float s0 = S[(l0+0)*SPAD + j];
            float s1 = S[(l0+1)*SPAD + j];
            float s2 = S[(l0+2)*SPAD + j];
            float4 v0 = *(float4*)&V[j*128 + e0];
            float4 v1 = *(float4*)&V[j*128 + e0 + 4];
            a[0][0]+=s0*v0.x; a[0][1]+=s0*v0.y; a[0][2]+=s0*v0.z; a[0][3]+=s0*v0.w;
            a[0][4]+=s0*v1.x; a[0][5]+=s0*v1.y; a[0][6]+=s0*v1.z; a[0][7]+=s0*v1.w;
            a[1][0]+=s1*v0.x; a[1][1]+=s1*v0.y; a[1][2]+=s1*v0.z; a[1][3]+=s1*v0.w;
            a[1][4]+=s1*v1.x; a[1][5]+=s1*v1.y; a[1][6]+=s1*v1.z; a[1][7]+=s1*v1.w;
            a[2][0]+=s2*v0.x; a[2][1]+=s2*v0.y; a[2][2]+=s2*v0.z; a[2][3]+=s2*v0.w;
            a[2][4]+=s2*v1.x; a[2][5]+=s2*v1.y; a[2][6]+=s2*v1.z; a[2][7]+=s2*v1.w;
        }
        #pragma unroll
        for (int r = 0; r < 3; ++r) {
            #pragma unroll
            for (int c = 0; c < 8; c += 2) {
                uint32_t hp, lp;
                pack_split(a[r][c], a[r][c+1], hp, lp);
                size_t w2 = (base + (size_t)(l0+r)*128 + e0 + c) >> 1;
                ((uint32_t*)d_qh)[w2] = hp;
                ((uint32_t*)d_ql)[w2] = lp;
            }
        }
    }
}

// ---------------- 3x-bf16 split GEMM: cp.async + ldmatrix mainloop (R7, verified) ----------------
// epi: 0 store fp32 C; 2 gelu(+bias)->Oh/Ol; 3 C+= ; 5 ->Oh/Ol; 6 QKV route C/C2/C3
#define TGW 12
#define TG_SMEM (2*4*128*TGW*4)   // 49152 bytes
__global__ void __launch_bounds__(256) tgemm(
    const bf16* __restrict__ Ah, const bf16* __restrict__ Al,
    const bf16* __restrict__ Bh, const bf16* __restrict__ Bl,
    float* __restrict__ C, float* __restrict__ C2, float* __restrict__ C3,
    bf16* __restrict__ Oh, bf16* __restrict__ Ol,
    int M, int N, int K, const float* __restrict__ bias, int epi, int gswap)
{
    extern __shared__ uint32_t SMu[];
    const int tid = threadIdx.x;
    const int m0 = (gswap ? blockIdx.x : blockIdx.y) * 128;
    const int n0 = (gswap ? blockIdx.y : blockIdx.x) * 128;
    const int lrow = tid >> 1, comp = tid & 1;
    const int warp = tid >> 5, lane = tid & 31;
    const int wm = (warp >> 2) * 64, wn = (warp & 3) * 32;
    const int g = lane >> 2, tig = lane & 3;

    const bf16* Arow = (comp ? Al : Ah) + (size_t)(m0 + lrow) * K;
    const bf16* Brow = (comp ? Bl : Bh) + (size_t)(n0 + lrow) * K;
    const bool mok = (m0 + lrow) < M;

    const uint32_t smem_u32 = (uint32_t)__cvta_generic_to_shared(SMu);
    const int CSTR = 128*TGW*4;          // bytes per 128-row plane
    const int SBUF = 4*CSTR;             // bytes per double-buffer

    const uint32_t dstA = smem_u32 + (comp*128 + lrow)*(TGW*4);
    const uint32_t dstB = smem_u32 + ((2 + comp)*128 + lrow)*(TGW*4);

    const int arow_l = wm + (lane & 7) + ((lane >> 3) & 1)*8;
    const uint32_t aoff = smem_u32 + arow_l*(TGW*4) + (lane >> 4)*16;
    const int brow_l = wn + (lane & 7) + ((lane >> 4) & 1)*8;
    const uint32_t boff = smem_u32 + 2*CSTR + brow_l*(TGW*4) + ((lane >> 3) & 1)*16;

    float acc[4][4][4];
    #pragma unroll
    for (int a = 0; a < 4; ++a)
        #pragma unroll
        for (int b = 0; b < 4; ++b)
            #pragma unroll
            for (int c = 0; c < 4; ++c) acc[a][b][c] = 0.f;

    const int nk = (K + 15) / 16;

    #define FETCH(kt, buf) do { \
        int k_ = (kt)*16; \
        cp16(dstA + (buf)*SBUF,      Arow + k_,     mok && k_ + 8  <= K); \
        cp16(dstA + (buf)*SBUF + 16, Arow + k_ + 8, mok && k_ + 16 <= K); \
        cp16(dstB + (buf)*SBUF,      Brow + k_,     k_ + 8  <= K); \
        cp16(dstB + (buf)*SBUF + 16, Brow + k_ + 8, k_ + 16 <= K); \
        CP_COMMIT(); \
    } while (0)

    FETCH(0, 0);
    CP_WAIT0();
    __syncthreads();

    int s = 0;
    for (int kt = 0; kt < nk; ++kt) {
        bool nxt = (kt + 1) < nk;
        if (nxt) FETCH(kt + 1, s ^ 1);

        uint32_t ah[4][4], al[4][4], bh[4][2], bl[4][2];
        const uint32_t sb = s*SBUF;
        #pragma unroll
        for (int mi = 0; mi < 4; ++mi) {
            ldsm_x4(ah[mi][0], ah[mi][1], ah[mi][2], ah[mi][3],
                    aoff + sb + mi*(16*TGW*4));
            ldsm_x4(al[mi][0], al[mi][1], al[mi][2], al[mi][3],
                    aoff + sb + CSTR + mi*(16*TGW*4));
        }
        #pragma unroll
        for (int p = 0; p < 2; ++p) {
            ldsm_x4(bh[2*p][0], bh[2*p][1], bh[2*p+1][0], bh[2*p+1][1],
                    boff + sb + p*(16*TGW*4));
            ldsm_x4(bl[2*p][0], bl[2*p][1], bl[2*p+1][0], bl[2*p+1][1],
                    boff + sb + CSTR + p*(16*TGW*4));
        }
        #pragma unroll
        for (int mi = 0; mi < 4; ++mi)
            #pragma unroll
            for (int ni = 0; ni < 4; ++ni) {
                asm volatile(
                    "mma.sync.aligned.m16n8k16.row.col.f32.bf16.bf16.f32 "
                    "{%0,%1,%2,%3}, {%4,%5,%6,%7}, {%8,%9}, {%0,%1,%2,%3};"
                    : "+f"(acc[mi][ni][0]), "+f"(acc[mi][ni][1]),
                      "+f"(acc[mi][ni][2]), "+f"(acc[mi][ni][3])
                    : "r"(ah[mi][0]), "r"(ah[mi][1]), "r"(ah[mi][2]), "r"(ah[mi][3]),
                      "r"(bl[ni][0]), "r"(bl[ni][1]));
                asm volatile(
                    "mma.sync.aligned.m16n8k16.row.col.f32.bf16.bf16.f32 "
                    "{%0,%1,%2,%3}, {%4,%5,%6,%7}, {%8,%9}, {%0,%1,%2,%3};"
                    : "+f"(acc[mi][ni][0]), "+f"(acc[mi][ni][1]),
                      "+f"(acc[mi][ni][2]), "+f"(acc[mi][ni][3])
                    : "r"(al[mi][0]), "r"(al[mi][1]), "r"(al[mi][2]), "r"(al[mi][3]),
                      "r"(bh[ni][0]), "r"(bh[ni][1]));
                asm volatile(
                    "mma.sync.aligned.m16n8k16.row.col.f32.bf16.bf16.f32 "
                    "{%0,%1,%2,%3}, {%4,%5,%6,%7}, {%8,%9}, {%0,%1,%2,%3};"
                    : "+f"(acc[mi][ni][0]), "+f"(acc[mi][ni][1]),
                      "+f"(acc[mi][ni][2]), "+f"(acc[mi][ni][3])
                    : "r"(ah[mi][0]), "r"(ah[mi][1]), "r"(ah[mi][2]), "r"(ah[mi][3]),
                      "r"(bh[ni][0]), "r"(bh[ni][1]));
            }
        if (nxt) CP_WAIT0();
        __syncthreads();
        s ^= 1;
    }
    #undef FETCH

    // epilogue
    #pragma unroll
    for (int mi = 0; mi < 4; ++mi) {
        #pragma unroll
        for (int ni = 0; ni < 4; ++ni) {
            int n = n0 + wn + ni*8 + tig*2;
            float bv0 = 0.f, bv1 = 0.f;
            if (bias) { bv0 = bias[n]; bv1 = bias[n+1]; }
            #pragma unroll
            for (int half = 0; half < 2; ++half) {
                int m = m0 + wm + mi*16 + g + half*8;
                if (m >= M) continue;
                float r0 = acc[mi][ni][half*2+0] + bv0;
                float r1 = acc[mi][ni][half*2+1] + bv1;
                size_t off = (size_t)m * N + n;
                if (epi == 0) {
                    *(float2*)(C + off) = make_float2(r0, r1);
                } else if (epi == 2) {
                    r0 = gelu_exact(r0); r1 = gelu_exact(r1);
                    uint32_t hp, lp;
                    pack_split(r0, r1, hp, lp);
                    ((uint32_t*)Oh)[off >> 1] = hp;
                    ((uint32_t*)Ol)[off >> 1] = lp;
                } else if (epi == 3) {
                    float2 cur = *(float2*)(C + off);
                    *(float2*)(C + off) = make_float2(r0 + cur.x, r1 + cur.y);
                } else if (epi == 5) {
                    uint32_t hp, lp;
                    pack_split(r0, r1, hp, lp);
                    ((uint32_t*)Oh)[off >> 1] = hp;
                    ((uint32_t*)Ol)[off >> 1] = lp;
                } else { // 6: QKV routing
                    int buf = n >> 7, col = n & 127;
                    float* Cd = (buf == 0) ? C : (buf == 1 ? C2 : C3);
                    *(float2*)(Cd + ((size_t)m << 7) + col) = make_float2(r0, r1);
                }
            }
        }
    }
}

// ---------------- transpose enc -> X[(bl*128+d)][n], split bf16 out ----------------
__global__ void k_transpose() {   // grid (94, 96), 256 threads
    __shared__ float T[32*129];
    int n0 = blockIdx.x * 32;
    int bl = blockIdx.y;
    int b = bl / LL, l = bl % LL;
    int tid = threadIdx.x;
    int nrem = NN - n0; if (nrem > 32) nrem = 32;
    for (int i = tid; i < 32*128; i += 256) {
        int r = i >> 7, c = i & 127;
        if (r < nrem)
            T[r*129 + c] = d_enc[((size_t)(b*NN + n0 + r))*6144 + l*128 + c];
    }
    __syncthreads();
    for (int i = tid; i < 128*32; i += 256) {
        int dd = i >> 5, j = i & 31;
        if (j < nrem) {
            float v = T[j*129 + dd];
            size_t o = ((size_t)(bl*128 + dd))*NN + n0 + j;
            scalar_split(v, d_Xh[o], d_Xl[o]);
        }
    }
}

// ---------------- GroupNorm stat zero / finalize ----------------
__global__ void k_gzero() {
    int i = threadIdx.x;   // 384
    d_gsum[i] = 0.f; d_gsq[i] = 0.f;
}
__global__ void k_gnfin() {
    int i = threadIdx.x;   // 384
    const float inv = 1.0f / (float)(NN*32);
    float mu = d_gsum[i] * inv;
    float var = d_gsq[i] * inv - mu*mu;
    d_gmu[i] = mu;
    d_grs[i] = rsqrtf(var + 1e-5f);
}

// ---------------- tensorized per-node grouped GEMM + fused GN partial stats ----------------
#define SA 68
#define GRP2_STATS (2*96*SA + 2*128*SA)            // u32 offset of stats region
#define GRP2_SMEM ((GRP2_STATS + 768) * 4)         // +3KB for stats
__global__ void __launch_bounds__(256) k_grouped2() {
    extern __shared__ uint32_t SMu[];
    uint32_t* Ah_s = SMu;
    uint32_t* Al_s = SMu + 96*SA;
    uint32_t* Bh_s = SMu + 2*96*SA;
    uint32_t* Bl_s = SMu + 2*96*SA + 128*SA;
    float* s_sum = (float*)(SMu + GRP2_STATS);       // 384
    float* s_sq  = (float*)(SMu + GRP2_STATS + 384); // 384
    int node = blockIdx.x, tid = threadIdx.x;
    for (int i = tid; i < 384; i += 256) { s_sum[i] = 0.f; s_sq[i] = 0.f; }
    const uint4* agh = (const uint4*)(d_aggh + (size_t)node * 12288);
    const uint4* agl = (const uint4*)(d_aggl + (size_t)node * 12288);
    const uint4* pwh = (const uint4*)(d_pwh + (size_t)node * 16384);
    const uint4* pwl = (const uint4*)(d_pwl + (size_t)node * 16384);
    for (int i = tid; i < 1536; i += 256) {
        int r = i >> 4, c = (i & 15) * 4;
        *(uint4*)(Ah_s + r*SA + c) = agh[i];
        *(uint4*)(Al_s + r*SA + c) = agl[i];
    }
    for (int i = tid; i < 2048; i += 256) {
        int r = i >> 4, c = (i & 15) * 4;
        *(uint4*)(Bh_s + r*SA + c) = pwh[i];
        *(uint4*)(Bl_s + r*SA + c) = pwl[i];
    }
    __syncthreads();

    int warp = tid >> 5, lane = tid & 31;
    int wm = (warp >> 2) * 48, wn = (warp & 3) * 32;
    int g = lane >> 2, tig = lane & 3;
    float acc[3][4][4];
    #pragma unroll
    for (int a = 0; a < 3; ++a)
        #pragma unroll
        for (int b = 0; b < 4; ++b)
            #pragma unroll
            for (int c = 0; c < 4; ++c) acc[a][b][c] = 0.f;

    #pragma unroll
    for (int kt = 0; kt < 8; ++kt) {
        uint32_t ah[3][4], al[3][4], bh[4][2], bl[4][2];
        int kb = kt*8 + tig;
        #pragma unroll
        for (int mi = 0; mi < 3; ++mi) {
            int r = wm + mi*16 + g;
            ah[mi][0] = Ah_s[ r     *SA + kb    ];
            ah[mi][1] = Ah_s[(r + 8)*SA + kb    ];
            ah[mi][2] = Ah_s[ r     *SA + kb + 4];
            ah[mi][3] = Ah_s[(r + 8)*SA + kb + 4];
            al[mi][0] = Al_s[ r     *SA + kb    ];
            al[mi][1] = Al_s[(r + 8)*SA + kb    ];
            al[mi][2] = Al_s[ r     *SA + kb + 4];
            al[mi][3] = Al_s[(r + 8)*SA + kb + 4];
        }
        #pragma unroll
        for (int ni = 0; ni < 4; ++ni) {
            int r = wn + ni*8 + g;
            bh[ni][0] = Bh_s[r*SA + kb    ];
            bh[ni][1] = Bh_s[r*SA + kb + 4];
            bl[ni][0] = Bl_s[r*SA + kb    ];
            bl[ni][1] = Bl_s[r*SA + kb + 4];
        }
        #pragma unroll
        for (int mi = 0; mi < 3; ++mi)
            #pragma unroll
            for (int ni = 0; ni < 4; ++ni) {
                asm volatile(
                    "mma.sync.aligned.m16n8k16.row.col.f32.bf16.bf16.f32 "
                    "{%0,%1,%2,%3}, {%4,%5,%6,%7}, {%8,%9}, {%0,%1,%2,%3};"
                    : "+f"(acc[mi][ni][0]), "+f"(acc[mi][ni][1]),
                      "+f"(acc[mi][ni][2]), "+f"(acc[mi][ni][3])
                    : "r"(ah[mi][0]), "r"(ah[mi][1]), "r"(ah[mi][2]), "r"(ah[mi][3]),
                      "r"(bl[ni][0]), "r"(bl[ni][1]));
                asm volatile(
                    "mma.sync.aligned.m16n8k16.row.col.f32.bf16.bf16.f32 "
                    "{%0,%1,%2,%3}, {%4,%5,%6,%7}, {%8,%9}, {%0,%1,%2,%3};"
                    : "+f"(acc[mi][ni][0]), "+f"(acc[mi][ni][1]),
                      "+f"(acc[mi][ni][2]), "+f"(acc[mi][ni][3])
                    : "r"(al[mi][0]), "r"(al[mi][1]), "r"(al[mi][2]), "r"(al[mi][3]),
                      "r"(bh[ni][0]), "r"(bh[ni][1]));
                asm volatile(
                    "mma.sync.aligned.m16n8k16.row.col.f32.bf16.bf16.f32 "
                    "{%0,%1,%2,%3}, {%4,%5,%6,%7}, {%8,%9}, {%0,%1,%2,%3};"
                    : "+f"(acc[mi][ni][0]), "+f"(acc[mi][ni][1]),
                      "+f"(acc[mi][ni][2]), "+f"(acc[mi][ni][3])
                    : "r"(ah[mi][0]), "r"(ah[mi][1]), "r"(ah[mi][2]), "r"(ah[mi][3]),
                      "r"(bh[ni][0]), "r"(bh[ni][1]));
            }
    }

    float* outp = d_gout + (size_t)node * 12288;
    #pragma unroll
    for (int mi = 0; mi < 3; ++mi)
        #pragma unroll
        for (int ni = 0; ni < 4; ++ni) {
            int n = wn + ni*8 + tig*2;
            int sidx = (n >> 5);
            #pragma unroll
            for (int half = 0; half < 2; ++half) {
                int m = wm + mi*16 + g + half*8;
                float v0 = acc[mi][ni][half*2+0];
                float v1 = acc[mi][ni][half*2+1];
                *(float2*)(outp + m*128 + n) = make_float2(v0, v1);
                atomicAdd(&s_sum[m*4 + sidx], v0 + v1);
                atomicAdd(&s_sq [m*4 + sidx], v0*v0 + v1*v1);
            }
        }
    __syncthreads();
    for (int i = tid; i < 384; i += 256) {
        atomicAdd(&d_gsum[i], s_sum[i]);
        atomicAdd(&d_gsq [i], s_sq [i]);
    }
}

// ---------------- fused GN-apply + SiLU proj + time proj + mean add ----------------
__global__ void k_final(const float* __restrict__ gg, const float* __restrict__ gb,
                        const float* __restrict__ p2w, const float* __restrict__ p2b,
                        const float* __restrict__ p1w, const float* __restrict__ p1b,
                        float* __restrict__ out) {
    __shared__ float Xs[6144];
    __shared__ float Ss[LL];
    int bn = blockIdx.x;
    int b = bn / NN, n = bn % NN;
    int tid = threadIdx.x;   // 256
    for (int i = tid; i < 6144; i += 256) {
        int l = i >> 7, c = i & 127;
        int bl = b*LL + l, g = c >> 5;
        float v = d_gout[(size_t)n*12288 + bl*128 + c];
        Xs[i] = (v - d_gmu[bl*4+g]) * d_grs[bl*4+g] * gg[c] + gb[c];
    }
    __syncthreads();
    int lane = tid & 31, w = tid >> 5;
    for (int l = w*6; l < w*6+6; ++l) {
        float s = Xs[l*128+lane]*p2w[lane] + Xs[l*128+lane+32]*p2w[lane+32]
                + Xs[l*128+lane+64]*p2w[lane+64] + Xs[l*128+lane+96]*p2w[lane+96];
        #pragma unroll
        for (int o = 16; o; o >>= 1) s += __shfl_xor_sync(~0u, s, o);
        if (lane == 0) {
            float z = s + p2b[0];
            Ss[l] = z / (1.0f + expf(-z));
        }
    }
    __syncthreads();
    if (tid < L_OUT) {
        float acc = p1b[tid];
        #pragma unroll
        for (int l = 0; l < LL; ++l) acc += Ss[l] * p1w[tid*LL + l];
        out[((size_t)(b*L_OUT + tid))*NN + n] = acc + d_mean[bn];
    }
}

// ---------------- launcher ----------------
extern "C" void kernel_launch(void* const* d_in, const int* in_sizes, int n_in,
                              void* d_out, int out_size) {
    const float* x_enc   = (const float*)d_in[0];
    const float* adj     = (const float*)d_in[1];
    const float* pe_raw  = (const float*)d_in[2];
    const float* conv_w  = (const float*)d_in[3];
    const float* pos_w   = (const float*)d_in[4];
    const float* pos_b   = (const float*)d_in[5];
    const float* wq      = (const float*)d_in[6];
    const float* wk      = (const float*)d_in[7];
    const float* wv      = (const float*)d_in[8];
    const float* wo      = (const float*)d_in[9];
    const float* ln1_g   = (const float*)d_in[10];
    const float* ln1_b   = (const float*)d_in[11];
    const float* ff_w1   = (const float*)d_in[12];
    const float* ff_b1   = (const float*)d_in[13];
    const float* ff_w2   = (const float*)d_in[14];
    const float* ff_b2   = (const float*)d_in[15];
    const float* ln2_g   = (const float*)d_in[16];
    const float* ln2_b   = (const float*)d_in[17];
    const float* wpool   = (const float*)d_in[18];
    const float* gn_g    = (const float*)d_in[19];
    const float* gn_b    = (const float*)d_in[20];
    const float* p2_w    = (const float*)d_in[21];
    const float* p2_b    = (const float*)d_in[22];
    const float* p1_w    = (const float*)d_in[23];
    const float* p1_b    = (const float*)d_in[24];
    float* out = (float*)d_out;

    float *p_enc, *p_q, *p_k, *p_v;
    bf16 *p_hh, *p_hl, *p_qh, *p_ql, *p_ffh, *p_ffl, *p_adjh, *p_adjl;
    bf16 *p_Xh, *p_Xl, *p_peTh, *p_peTl, *p_WT2h, *p_WT2l, *p_pe2h, *p_pe2l;
    bf16 *p_aggh, *p_aggl, *p_pwh, *p_pwl, *p_wph, *p_wpl;
    cudaGetSymbolAddress((void**)&p_enc, d_enc);
    cudaGetSymbolAddress((void**)&p_q,   d_qb);
    cudaGetSymbolAddress((void**)&p_k,   d_kb);
    cudaGetSymbolAddress((void**)&p_v,   d_vb);
    cudaGetSymbolAddress((void**)&p_hh,  d_hh);
    cudaGetSymbolAddress((void**)&p_hl,  d_hl);
    cudaGetSymbolAddress((void**)&p_qh,  d_qh);
    cudaGetSymbolAddress((void**)&p_ql,  d_ql);
    cudaGetSymbolAddress((void**)&p_ffh, d_ffh);
    cudaGetSymbolAddress((void**)&p_ffl, d_ffl);
    cudaGetSymbolAddress((void**)&p_adjh, d_adjh);
    cudaGetSymbolAddress((void**)&p_adjl, d_adjl);
    cudaGetSymbolAddress((void**)&p_Xh,  d_Xh);
    cudaGetSymbolAddress((void**)&p_Xl,  d_Xl);
    cudaGetSymbolAddress((void**)&p_peTh, d_peTh);
    cudaGetSymbolAddress((void**)&p_peTl, d_peTl);
    cudaGetSymbolAddress((void**)&p_WT2h, d_WT2h);
    cudaGetSymbolAddress((void**)&p_WT2l, d_WT2l);
    cudaGetSymbolAddress((void**)&p_pe2h, d_pe2h);
    cudaGetSymbolAddress((void**)&p_pe2l, d_pe2l);
    cudaGetSymbolAddress((void**)&p_aggh, d_aggh);
    cudaGetSymbolAddress((void**)&p_aggl, d_aggl);
    cudaGetSymbolAddress((void**)&p_pwh, d_pwh);
    cudaGetSymbolAddress((void**)&p_pwl, d_pwl);
    cudaGetSymbolAddress((void**)&p_wph, d_wph);
    cudaGetSymbolAddress((void**)&p_wpl, d_wpl);

    cudaFuncSetAttribute(k_attn,     cudaFuncAttributeMaxDynamicSharedMemorySize, ATTN_SMEM);
    cudaFuncSetAttribute(tgemm,      cudaFuncAttributeMaxDynamicSharedMemorySize, TG_SMEM);
    cudaFuncSetAttribute(k_grouped2, cudaFuncAttributeMaxDynamicSharedMemorySize, GRP2_SMEM);

    // prep + splits
    k_mean<<<(BNN+255)/256, 256>>>(x_enc);
    k_peT<<<(DD*NN+255)/256, 256>>>(pe_raw, pos_w, pos_b);
    k_WT2<<<(DD*DD*DD+255)/256, 256>>>(wpool);
    k_conv<<<BNN, 128>>>(x_enc, conv_w);
    k_split<<<(NN*NN+255)/256, 256>>>(adj, p_adjh, p_adjl, NN*NN);
    k_splitW<<<768, 256>>>(wq, wk, wv, wo, ff_w1, ff_w2);
    k_gzero<<<1, 384>>>();

    // temporal transformer
    k_ln<<<ROWS/8, 256>>>(p_enc, ln1_g, ln1_b);
    tgemm<<<dim3(3, ROWS/128), 256, TG_SMEM>>>(p_hh, p_hl, p_wph+WPO_Q, p_wpl+WPO_Q,
        p_q, p_k, p_v, nullptr, nullptr, ROWS, 384, 128, nullptr, 6, 0);
    k_attn<<<BNN, 256, ATTN_SMEM>>>();
    tgemm<<<dim3(1, ROWS/128), 256, TG_SMEM>>>(p_qh, p_ql, p_wph+WPO_O, p_wpl+WPO_O,
        p_enc, nullptr, nullptr, nullptr, nullptr, ROWS, 128, 128, nullptr, 3, 0);
    k_ln<<<ROWS/8, 256>>>(p_enc, ln2_g, ln2_b);
    tgemm<<<dim3(4, ROWS/128), 256, TG_SMEM>>>(p_hh, p_hl, p_wph+WPO_F1, p_wpl+WPO_F1,
        nullptr, nullptr, nullptr, p_ffh, p_ffl, ROWS, 512, 128, ff_b1, 2, 0);
    tgemm<<<dim3(1, ROWS/128), 256, TG_SMEM>>>(p_ffh, p_ffl, p_wph+WPO_F2, p_wpl+WPO_F2,
        p_enc, nullptr, nullptr, nullptr, nullptr, ROWS, 128, 512, ff_b2, 3, 0);

    // spatial GCN
    k_transpose<<<dim3(94, BLL), 256>>>();
    tgemm<<<dim3(1, 24), 256, TG_SMEM>>>(p_adjh, p_adjl, p_peTh, p_peTl,
        nullptr, nullptr, nullptr, p_pe2h, p_pe2l, NN, 128, NN, nullptr, 5, 0);
    tgemm<<<dim3(128, 24), 256, TG_SMEM>>>(p_pe2h, p_pe2l, p_WT2h, p_WT2l,
        nullptr, nullptr, nullptr, p_pwh, p_pwl, NN, 16384, 128, nullptr, 5, 0);
    tgemm<<<dim3(24, 96), 256, TG_SMEM>>>(p_adjh, p_adjl, p_Xh, p_Xl,
        nullptr, nullptr, nullptr, p_aggh, p_aggl, NN, 12288, NN, nullptr, 5, 1);
    k_grouped2<<<NN, 256, GRP2_SMEM>>>();

    // groupnorm + head
    k_gnfin<<<1, 384>>>();
    k_final<<<BNN, 256>>>(gn_g, gn_b, p2_w, p2_b, p1_w, p1_b, out);
}

// round 13
// speedup vs baseline: 1.7994x; 1.0261x over previous
#include <cuda_runtime.h>
#include <cuda_bf16.h>
#include <math.h>
#include <stdint.h>

#define BB 2
#define LL 48
#define NN 3000
#define DD 128
#define L_OUT 24
#define BNN (BB*NN)          // 6000
#define BLL (BB*LL)          // 96
#define ROWS (BNN*LL)        // 288000 token rows
#define ENC_N (ROWS*DD)      // 36,864,000

typedef __nv_bfloat16 bf16;

// ---------------- scratch (device globals; no runtime allocation) ----------------
__device__ float d_mean[BNN];
__device__ float d_enc[ENC_N];           // enc[seq][l][c]
__device__ float d_qb[ENC_N];            // q fp32 (raw); later pe2 fp32 accumulator
__device__ float d_kb[ENC_N];
__device__ float d_vb[ENC_N];
__device__ float d_gout[NN*BLL*DD];      // gout[n][bl][o]
__device__ float d_gmu[BLL*4];
__device__ float d_grs[BLL*4];
__device__ float d_gsum[BLL*4];
__device__ float d_gsq[BLL*4];

// bf16 split pairs
__device__ bf16 d_hh[ENC_N],  d_hl[ENC_N];     // LN output
__device__ bf16 d_qh[ENC_N],  d_ql[ENC_N];     // att_pre
__device__ bf16 d_ffh[ROWS*512], d_ffl[ROWS*512];
__device__ bf16 d_adjh[NN*NN], d_adjl[NN*NN];
__device__ bf16 d_Xh[BLL*DD*NN], d_Xl[BLL*DD*NN];
__device__ bf16 d_peTh[DD*NN], d_peTl[DD*NN];
__device__ bf16 d_WT2h[DD*DD*DD], d_WT2l[DD*DD*DD];  // [(o*128+i)][d]
__device__ bf16 d_pe2h[NN*DD], d_pe2l[NN*DD];
__device__ bf16 d_aggh[NN*BLL*DD], d_aggl[NN*BLL*DD]; // [n][bl*128+i]
__device__ bf16 d_pwh[NN*DD*DD], d_pwl[NN*DD*DD];     // [n][o*128+i]
// weight pool: [wq|wk|wv|wo|ffw1|ffw2]
#define WPO_Q 0
#define WPO_K 16384
#define WPO_V 32768
#define WPO_O 49152
#define WPO_F1 65536
#define WPO_F2 131072
__device__ bf16 d_wph[196608], d_wpl[196608];

__device__ __forceinline__ float gelu_exact(float x) {
    return 0.5f * x * (1.0f + erff(x * 0.70710678118654752f));
}
__device__ __forceinline__ void pack_split(float x0, float x1, uint32_t& hi, uint32_t& lo) {
    uint32_t h;
    asm("cvt.rn.bf16x2.f32 %0, %1, %2;" : "=r"(h) : "f"(x1), "f"(x0));
    float h0 = __uint_as_float(h << 16);
    float h1 = __uint_as_float(h & 0xFFFF0000u);
    float r0 = x0 - h0, r1 = x1 - h1;
    uint32_t l;
    asm("cvt.rn.bf16x2.f32 %0, %1, %2;" : "=r"(l) : "f"(r1), "f"(r0));
    hi = h; lo = l;
}
__device__ __forceinline__ void scalar_split(float v, bf16& h, bf16& l) {
    h = __float2bfloat16_rn(v);
    l = __float2bfloat16_rn(v - __bfloat162float(h));
}
__device__ __forceinline__ void ldsm_x4(uint32_t& r0, uint32_t& r1, uint32_t& r2, uint32_t& r3,
                                        uint32_t addr) {
    asm volatile("ldmatrix.sync.aligned.m8n8.x4.shared.b16 {%0,%1,%2,%3}, [%4];"
                 : "=r"(r0), "=r"(r1), "=r"(r2), "=r"(r3) : "r"(addr));
}
__device__ __forceinline__ void cp16(uint32_t dst, const void* src, bool pred) {
    int sz = pred ? 16 : 0;
    asm volatile("cp.async.cg.shared.global [%0], [%1], 16, %2;\n"
                 :: "r"(dst), "l"(src), "r"(sz) : "memory");
}
#define CP_COMMIT() asm volatile("cp.async.commit_group;\n" ::: "memory")
#define CP_WAIT0()  asm volatile("cp.async.wait_group 0;\n" ::: "memory")

// ---------------- small prep kernels ----------------
__global__ void k_zero(float* __restrict__ p, int n) {
    int i = blockIdx.x * blockDim.x + threadIdx.x;
    if (i < n) p[i] = 0.f;
}

__global__ void k_split(const float* __restrict__ in, bf16* __restrict__ h,
                        bf16* __restrict__ l, int n) {
    int i = blockIdx.x * blockDim.x + threadIdx.x;
    if (i >= n) return;
    scalar_split(in[i], h[i], l[i]);
}

// merged split of all dense weights into the pool
__global__ void k_splitW(const float* __restrict__ wq, const float* __restrict__ wk,
                         const float* __restrict__ wv, const float* __restrict__ wo,
                         const float* __restrict__ f1, const float* __restrict__ f2) {
    int i = blockIdx.x * blockDim.x + threadIdx.x;
    if (i >= 196608) return;
    float v;
    if (i < 65536) {
        int j = i & 16383;
        v = (i < 16384) ? wq[j] : (i < 32768) ? wk[j] : (i < 49152) ? wv[j] : wo[j];
    } else if (i < 131072) {
        v = f1[i - 65536];
    } else {
        v = f2[i - 131072];
    }
    scalar_split(v, d_wph[i], d_wpl[i]);
}

__global__ void k_peT(const float* __restrict__ pr, const float* __restrict__ pw,
                      const float* __restrict__ pb) {
    int i = blockIdx.x * blockDim.x + threadIdx.x;
    if (i >= DD*NN) return;
    int d = i / NN, n = i % NN;
    float v = pr[n]*pw[d*3] + pr[NN+n]*pw[d*3+1] + pr[2*NN+n]*pw[d*3+2] + pb[d];
    scalar_split(v, d_peTh[i], d_peTl[i]);
}

// WT2[(o*128+i)][d] = wp[(d*128+i)][o]
__global__ void k_WT2(const float* __restrict__ wp) {
    int idx = blockIdx.x * blockDim.x + threadIdx.x;
    if (idx >= DD*DD*DD) return;
    int d = idx & 127;
    int nrow = idx >> 7;          // o*128+i
    int i = nrow & 127, o = nrow >> 7;
    scalar_split(wp[(d*128 + i)*128 + o], d_WT2h[idx], d_WT2l[idx]);
}

// circular conv1d k=3 + per-seq mean + fused LN1 (enc fp32 + split bf16 out)
__global__ void k_conv(const float* __restrict__ x, const float* __restrict__ cw,
                       const float* __restrict__ lg, const float* __restrict__ lb) {
    __shared__ float xs[LL + 2];
    __shared__ float red[384];    // [l*4 + warp] sums (0..191), sq (192..383)
    __shared__ float mrs[LL*2];
    __shared__ float mm;
    int seq = blockIdx.x;
    int b = seq / NN, n = seq % NN;
    int t = threadIdx.x;   // 128
    if (t < LL) xs[t + 1] = x[(b*LL + t)*NN + n];
    __syncthreads();
    if (t == 0) {
        float s = 0.f;
        #pragma unroll
        for (int l = 1; l <= LL; ++l) s += xs[l];
        float m = s * (1.0f / LL);
        mm = m; d_mean[seq] = m;
        xs[0] = xs[LL]; xs[LL+1] = xs[1];
    }
    __syncthreads();
    float m = mm;
    float w0 = cw[t*3], w1 = cw[t*3+1], w2 = cw[t*3+2];
    float wc = (w0 + w1 + w2) * m;
    float val[LL];
    #pragma unroll
    for (int l = 0; l < LL; ++l)
        val[l] = w0*xs[l] + w1*xs[l+1] + w2*xs[l+2] - wc;
    // per-row (over c=128) LN stats
    int lane = t & 31, w = t >> 5;
    #pragma unroll
    for (int l = 0; l < LL; ++l) {
        float s = val[l], q = val[l]*val[l];
        #pragma unroll
        for (int o = 16; o; o >>= 1) {
            s += __shfl_xor_sync(~0u, s, o);
            q += __shfl_xor_sync(~0u, q, o);
        }
        if (lane == 0) { red[l*4 + w] = s; red[192 + l*4 + w] = q; }
    }
    __syncthreads();
    if (t < LL) {
        float s = red[t*4] + red[t*4+1] + red[t*4+2] + red[t*4+3];
        float q = red[192+t*4] + red[192+t*4+1] + red[192+t*4+2] + red[192+t*4+3];
        float mu = s * (1.0f/128.0f);
        float var = q * (1.0f/128.0f) - mu*mu;
        mrs[t*2] = mu; mrs[t*2+1] = rsqrtf(var + 1e-5f);
    }
    __syncthreads();
    float gg = lg[t], bb = lb[t];
    float* out = d_enc + (size_t)seq * 6144;
    size_t base = (size_t)seq * 6144;
    #pragma unroll
    for (int l = 0; l < LL; ++l) {
        float v = val[l];
        out[l*128 + t] = v;
        float h = (v - mrs[l*2]) * mrs[l*2+1] * gg + bb;
        bf16 hh, ll;
        scalar_split(h, hh, ll);
        d_hh[base + l*128 + t] = hh;
        d_hl[base + l*128 + t] = ll;
    }
}

// ---------------- per-sequence linear attention: (softmax_q @ softmax_k^T) @ v ----------------
#define SPAD 52
#define ATTN_SMEM ((6144*3 + LL*SPAD) * 4)    // 83712 B -> 2 CTAs/SM
__global__ void __launch_bounds__(256) k_attn() {
    extern __shared__ float sm[];
    float* Q  = sm;               // 48x128
    float* KK = sm + 6144;        // 48x128
    float* V  = sm + 12288;       // 48x128
    float* S  = sm + 18432;       // 48xSPAD
    int seq = blockIdx.x, tid = threadIdx.x;
    size_t base = (size_t)seq * 6144;
    for (int i = tid; i < 6144; i += 256) {
        Q[i] = d_qb[base+i]; KK[i] = d_kb[base+i]; V[i] = d_vb[base+i];
    }
    __syncthreads();
    int te = tid & 31, tg = tid >> 5;
    // Q row softmax * d^-0.5
    for (int l = tg*6; l < tg*6+6; ++l) {
        float4 v = *(float4*)&Q[l*128 + te*4];
        float mx = fmaxf(fmaxf(v.x, v.y), fmaxf(v.z, v.w));
        #pragma unroll
        for (int o = 16; o; o >>= 1) mx = fmaxf(mx, __shfl_xor_sync(~0u, mx, o));
        v.x = expf(v.x - mx); v.y = expf(v.y - mx);
        v.z = expf(v.z - mx); v.w = expf(v.w - mx);
        float s = v.x + v.y + v.z + v.w;
        #pragma unroll
        for (int o = 16; o; o >>= 1) s += __shfl_xor_sync(~0u, s, o);
        float f = 0.08838834764831845f / s;
        v.x *= f; v.y *= f; v.z *= f; v.w *= f;
        *(float4*)&Q[l*128 + te*4] = v;
    }
    // K col softmax over L
    if (tid < 128) {
        int c = tid;
        float mx = -1e30f;
        #pragma unroll
        for (int l = 0; l < LL; ++l) mx = fmaxf(mx, KK[l*128 + c]);
        float s = 0.f;
        float ev[LL];
        #pragma unroll
        for (int l = 0; l < LL; ++l) { ev[l] = expf(KK[l*128 + c] - mx); s += ev[l]; }
        float inv = 1.0f / s;
        #pragma unroll
        for (int l = 0; l < LL; ++l) KK[l*128 + c] = ev[l] * inv;
    }
    __syncthreads();
    // S[i][j] = sum_d Q[i][d]*KK[j][d]   (48x48, k=128)
    {
        int ty = tid >> 4, tx = tid & 15;
        int i0 = ty*3, j0 = tx*3;
        float a[3][3] = {};
        #pragma unroll
        for (int d4 = 0; d4 < 128; d4 += 4) {
            float4 q0 = *(float4*)&Q [(i0+0)*128 + d4];
            float4 q1 = *(float4*)&Q [(i0+1)*128 + d4];
            float4 q2 = *(float4*)&Q [(i0+2)*128 + d4];
            float4 k0 = *(float4*)&KK[(j0+0)*128 + d4];
            float4 k1 = *(float4*)&KK[(j0+1)*128 + d4];
            float4 k2 = *(float4*)&KK[(j0+2)*128 + d4];
            a[0][0] += q0.x*k0.x + q0.y*k0.y + q0.z*k0.z + q0.w*k0.w;
            a[0][1] += q0.x*k1.x + q0.y*k1.y + q0.z*k1.z + q0.w*k1.w;
            a[0][2] += q0.x*k2.x + q0.y*k2.y + q0.z*k2.z + q0.w*k2.w;
            a[1][0] += q1.x*k0.x + q1.y*k0.y + q1.z*k0.z + q1.w*k0.w;
            a[1][1] += q1.x*k1.x + q1.y*k1.y + q1.z*k1.z + q1.w*k1.w;
            a[1][2] += q1.x*k2.x + q1.y*k2.y + q1.z*k2.z + q1.w*k2.w;
            a[2][0] += q2.x*k0.x + q2.y*k0.y + q2.z*k0.z + q2.w*k0.w;
            a[2][1] += q2.x*k1.x + q2.y*k1.y + q2.z*k1.z + q2.w*k1.w;
            a[2][2] += q2.x*k2.x + q2.y*k2.y + q2.z*k2.z + q2.w*k2.w;
        }
        #pragma unroll
        for (int r = 0; r < 3; ++r)
            #pragma unroll
            for (int c = 0; c < 3; ++c)
                S[(i0+r)*SPAD + j0 + c] = a[r][c];
    }
    __syncthreads();
    // att[l][e] = sum_j S[l][j]*V[j][e]  -> split store to d_qh/d_ql
    {
        int ty = tid >> 4, tx = tid & 15;
        int l0 = ty*3, e0 = tx*8;
        float a[3][8] = {};
        #pragma unroll
        for (int j = 0; j < LL; ++j) {
            float s0 = S[(l0+0)*SPAD + j];
            float s1 = S[(l0+1)*SPAD + j];
            float s2 = S[(l0+2)*SPAD + j];
            float4 v0 = *(float4*)&V[j*128 + e0];
            float4 v1 = *(float4*)&V[j*128 + e0 + 4];
            a[0][0]+=s0*v0.x; a[0][1]+=s0*v0.y; a[0][2]+=s0*v0.z; a[0][3]+=s0*v0.w;
            a[0][4]+=s0*v1.x; a[0][5]+=s0*v1.y; a[0][6]+=s0*v1.z; a[0][7]+=s0*v1.w;
            a[1][0]+=s1*v0.x; a[1][1]+=s1*v0.y; a[1][2]+=s1*v0.z; a[1][3]+=s1*v0.w;
            a[1][4]+=s1*v1.x; a[1][5]+=s1*v1.y; a[1][6]+=s1*v1.z; a[1][7]+=s1*v1.w;
            a[2][0]+=s2*v0.x; a[2][1]+=s2*v0.y; a[2][2]+=s2*v0.z; a[2][3]+=s2*v0.w;
            a[2][4]+=s2*v1.x; a[2][5]+=s2*v1.y; a[2][6]+=s2*v1.z; a[2][7]+=s2*v1.w;
        }
        #pragma unroll
        for (int r = 0; r < 3; ++r) {
            #pragma unroll
            for (int c = 0; c < 8; c += 2) {
                uint32_t hp, lp;
                pack_split(a[r][c], a[r][c+1], hp, lp);
                size_t w2 = (base + (size_t)(l0+r)*128 + e0 + c) >> 1;
                ((uint32_t*)d_qh)[w2] = hp;
                ((uint32_t*)d_ql)[w2] = lp;
            }
        }
    }
}

// ---------------- 3x-bf16 split GEMM: cp.async + ldmatrix mainloop ----------------
// epi: 0 store fp32 C; 2 gelu(+bias)->Oh/Ol; 3 C+= ; 5 ->Oh/Ol; 6 QKV route C/C2/C3;
//      7 C+= then LN(row)->Oh/Ol (N must be 128, full tiles); 8 atomicAdd fp32 C (split-K)
#define TGW 12
#define TG_SMEM (2*4*128*TGW*4)   // 49152 bytes
__global__ void __launch_bounds__(256) tgemm(
    const bf16* __restrict__ Ah, const bf16* __restrict__ Al,
    const bf16* __restrict__ Bh, const bf16* __restrict__ Bl,
    float* __restrict__ C, float* __restrict__ C2, float* __restrict__ C3,
    bf16* __restrict__ Oh, bf16* __restrict__ Ol,
    int M, int N, int K, const float* __restrict__ bias, int epi, int gswap,
    const float* __restrict__ lng, const float* __restrict__ lnb, int ksplit)
{
    extern __shared__ uint32_t SMu[];
    const int tid = threadIdx.x;
    const int m0 = (gswap ? blockIdx.x : blockIdx.y) * 128;
    const int n0 = (gswap ? blockIdx.y : blockIdx.x) * 128;
    const int lrow = tid >> 1, comp = tid & 1;
    const int warp = tid >> 5, lane = tid & 31;
    const int wm = (warp >> 2) * 64, wn = (warp & 3) * 32;
    const int g = lane >> 2, tig = lane & 3;

    const bf16* Arow = (comp ? Al : Ah) + (size_t)(m0 + lrow) * K;
    const bf16* Brow = (comp ? Bl : Bh) + (size_t)(n0 + lrow) * K;
    const bool mok = (m0 + lrow) < M;

    const uint32_t smem_u32 = (uint32_t)__cvta_generic_to_shared(SMu);
    const int CSTR = 128*TGW*4;          // bytes per 128-row plane
    const int SBUF = 4*CSTR;             // bytes per double-buffer

    const uint32_t dstA = smem_u32 + (comp*128 + lrow)*(TGW*4);
    const uint32_t dstB = smem_u32 + ((2 + comp)*128 + lrow)*(TGW*4);

    const int arow_l = wm + (lane & 7) + ((lane >> 3) & 1)*8;
    const uint32_t aoff = smem_u32 + arow_l*(TGW*4) + (lane >> 4)*16;
    const int brow_l = wn + (lane & 7) + ((lane >> 4) & 1)*8;
    const uint32_t boff = smem_u32 + 2*CSTR + brow_l*(TGW*4) + ((lane >> 3) & 1)*16;

    float acc[4][4][4];
    #pragma unroll
    for (int a = 0; a < 4; ++a)
        #pragma unroll
        for (int b = 0; b < 4; ++b)
            #pragma unroll
            for (int c = 0; c < 4; ++c) acc[a][b][c] = 0.f;

    int kt0 = 0, ktN = (K + 15) / 16;
    if (ksplit > 0) {
        int klo = blockIdx.z * ksplit;
        int khi = min(K, klo + ksplit);
        kt0 = klo >> 4;
        ktN = (khi + 15) >> 4;
    }

    #define FETCH(kt, buf) do { \
        int k_ = (kt)*16; \
        cp16(dstA + (buf)*SBUF,      Arow + k_,     mok && k_ + 8  <= K); \
        cp16(dstA + (buf)*SBUF + 16, Arow + k_ + 8, mok && k_ + 16 <= K); \
        cp16(dstB + (buf)*SBUF,      Brow + k_,     k_ + 8  <= K); \
        cp16(dstB + (buf)*SBUF + 16, Brow + k_ + 8, k_ + 16 <= K); \
        CP_COMMIT(); \
    } while (0)

    FETCH(kt0, 0);
    CP_WAIT0();
    __syncthreads();

    int s = 0;
    for (int kt = kt0; kt < ktN; ++kt) {
        bool nxt = (kt + 1) < ktN;
        if (nxt) FETCH(kt + 1, s ^ 1);

        uint32_t ah[4][4], al[4][4], bh[4][2], bl[4][2];
        const uint32_t sb = s*SBUF;
        #pragma unroll
        for (int mi = 0; mi < 4; ++mi) {
            ldsm_x4(ah[mi][0], ah[mi][1], ah[mi][2], ah[mi][3],
                    aoff + sb + mi*(16*TGW*4));
            ldsm_x4(al[mi][0], al[mi][1], al[mi][2], al[mi][3],
                    aoff + sb + CSTR + mi*(16*TGW*4));
        }
        #pragma unroll
        for (int p = 0; p < 2; ++p) {
            ldsm_x4(bh[2*p][0], bh[2*p][1], bh[2*p+1][0], bh[2*p+1][1],
                    boff + sb + p*(16*TGW*4));
            ldsm_x4(bl[2*p][0], bl[2*p][1], bl[2*p+1][0], bl[2*p+1][1],
                    boff + sb + CSTR + p*(16*TGW*4));
        }
        #pragma unroll
        for (int mi = 0; mi < 4; ++mi)
            #pragma unroll
            for (int ni = 0; ni < 4; ++ni) {
                asm volatile(
                    "mma.sync.aligned.m16n8k16.row.col.f32.bf16.bf16.f32 "
                    "{%0,%1,%2,%3}, {%4,%5,%6,%7}, {%8,%9}, {%0,%1,%2,%3};"
                    : "+f"(acc[mi][ni][0]), "+f"(acc[mi][ni][1]),
                      "+f"(acc[mi][ni][2]), "+f"(acc[mi][ni][3])
                    : "r"(ah[mi][0]), "r"(ah[mi][1]), "r"(ah[mi][2]), "r"(ah[mi][3]),
                      "r"(bl[ni][0]), "r"(bl[ni][1]));
                asm volatile(
                    "mma.sync.aligned.m16n8k16.row.col.f32.bf16.bf16.f32 "
                    "{%0,%1,%2,%3}, {%4,%5,%6,%7}, {%8,%9}, {%0,%1,%2,%3};"
                    : "+f"(acc[mi][ni][0]), "+f"(acc[mi][ni][1]),
                      "+f"(acc[mi][ni][2]), "+f"(acc[mi][ni][3])
                    : "r"(al[mi][0]), "r"(al[mi][1]), "r"(al[mi][2]), "r"(al[mi][3]),
                      "r"(bh[ni][0]), "r"(bh[ni][1]));
                asm volatile(
                    "mma.sync.aligned.m16n8k16.row.col.f32.bf16.bf16.f32 "
                    "{%0,%1,%2,%3}, {%4,%5,%6,%7}, {%8,%9}, {%0,%1,%2,%3};"
                    : "+f"(acc[mi][ni][0]), "+f"(acc[mi][ni][1]),
                      "+f"(acc[mi][ni][2]), "+f"(acc[mi][ni][3])
                    : "r"(ah[mi][0]), "r"(ah[mi][1]), "r"(ah[mi][2]), "r"(ah[mi][3]),
                      "r"(bh[ni][0]), "r"(bh[ni][1]));
            }
        if (nxt) CP_WAIT0();
        __syncthreads();
        s ^= 1;
    }
    #undef FETCH

    if (epi == 7) {
        // residual add + store enc, then fused LN over each row (N==128, full tiles)
        float* s_sum = (float*)SMu;        // 128*4
        float* s_sq  = s_sum + 512;        // 128*4
        float* s_mr  = s_sq + 512;         // 128*2
        #pragma unroll
        for (int mi = 0; mi < 4; ++mi)
            #pragma unroll
            for (int half = 0; half < 2; ++half) {
                int ml = wm + mi*16 + g + half*8;
                int m = m0 + ml;
                float rsum = 0.f, rsq = 0.f;
                #pragma unroll
                for (int ni = 0; ni < 4; ++ni) {
                    int n = wn + ni*8 + tig*2;
                    size_t off = (size_t)m * 128 + n;
                    float2 cur = *(float2*)(C + off);
                    float r0 = acc[mi][ni][half*2+0] + cur.x;
                    float r1 = acc[mi][ni][half*2+1] + cur.y;
                    *(float2*)(C + off) = make_float2(r0, r1);
                    acc[mi][ni][half*2+0] = r0; acc[mi][ni][half*2+1] = r1;
                    rsum += r0 + r1; rsq += r0*r0 + r1*r1;
                }
                rsum += __shfl_xor_sync(~0u, rsum, 1);
                rsum += __shfl_xor_sync(~0u, rsum, 2);
                rsq  += __shfl_xor_sync(~0u, rsq, 1);
                rsq  += __shfl_xor_sync(~0u, rsq, 2);
                if (tig == 0) {
                    s_sum[ml*4 + (warp & 3)] = rsum;
                    s_sq [ml*4 + (warp & 3)] = rsq;
                }
            }
        __syncthreads();
        if (tid < 128) {
            float s2 = s_sum[tid*4] + s_sum[tid*4+1] + s_sum[tid*4+2] + s_sum[tid*4+3];
            float q2 = s_sq[tid*4] + s_sq[tid*4+1] + s_sq[tid*4+2] + s_sq[tid*4+3];
            float mu = s2 * (1.0f/128.0f);
            float var = q2 * (1.0f/128.0f) - mu*mu;
            s_mr[tid*2] = mu; s_mr[tid*2+1] = rsqrtf(var + 1e-5f);
        }
        __syncthreads();
        #pragma unroll
        for (int mi = 0; mi < 4; ++mi)
            #pragma unroll
            for (int ni = 0; ni < 4; ++ni) {
                int n = wn + ni*8 + tig*2;
                float g0 = lng[n], g1 = lng[n+1];
                float b0 = lnb[n], b1 = lnb[n+1];
                #pragma unroll
                for (int half = 0; half < 2; ++half) {
                    int ml = wm + mi*16 + g + half*8;
                    int m = m0 + ml;
                    float mu = s_mr[ml*2], rg = s_mr[ml*2+1];
                    float v0 = (acc[mi][ni][half*2+0] - mu)*rg*g0 + b0;
                    float v1 = (acc[mi][ni][half*2+1] - mu)*rg*g1 + b1;
                    uint32_t hp, lp;
                    pack_split(v0, v1, hp, lp);
                    size_t off = (size_t)m * 128 + n;
                    ((uint32_t*)Oh)[off >> 1] = hp;
                    ((uint32_t*)Ol)[off >> 1] = lp;
                }
            }
        return;
    }

    // generic epilogue
    #pragma unroll
    for (int mi = 0; mi < 4; ++mi) {
        #pragma unroll
        for (int ni = 0; ni < 4; ++ni) {
            int n = n0 + wn + ni*8 + tig*2;
            float bv0 = 0.f, bv1 = 0.f;
            if (bias) { bv0 = bias[n]; bv1 = bias[n+1]; }
            #pragma unroll
            for (int half = 0; half < 2; ++half) {
                int m = m0 + wm + mi*16 + g + half*8;
                if (m >= M) continue;
                float r0 = acc[mi][ni][half*2+0] + bv0;
                float r1 = acc[mi][ni][half*2+1] + bv1;
                size_t off = (size_t)m * N + n;
                if (epi == 0) {
                    *(float2*)(C + off) = make_float2(r0, r1);
                } else if (epi == 2) {
                    r0 = gelu_exact(r0); r1 = gelu_exact(r1);
                    uint32_t hp, lp;
                    pack_split(r0, r1, hp, lp);
                    ((uint32_t*)Oh)[off >> 1] = hp;
                    ((uint32_t*)Ol)[off >> 1] = lp;
                } else if (epi == 3) {
                    float2 cur = *(float2*)(C + off);
                    *(float2*)(C + off) = make_float2(r0 + cur.x, r1 + cur.y);
                } else if (epi == 5) {
                    uint32_t hp, lp;
                    pack_split(r0, r1, hp, lp);
                    ((uint32_t*)Oh)[off >> 1] = hp;
                    ((uint32_t*)Ol)[off >> 1] = lp;
                } else if (epi == 8) {
                    atomicAdd(C + off, r0);
                    atomicAdd(C + off + 1, r1);
                } else { // 6: QKV routing
                    int buf = n >> 7, col = n & 127;
                    float* Cd = (buf == 0) ? C : (buf == 1 ? C2 : C3);
                    *(float2*)(Cd + ((size_t)m << 7) + col) = make_float2(r0, r1);
                }
            }
        }
    }
}

// ---------------- transpose enc -> X[(bl*128+d)][n], split bf16 out ----------------
__global__ void k_transpose() {   // grid (94, 96), 256 threads
    __shared__ float T[32*129];
    int n0 = blockIdx.x * 32;
    int bl = blockIdx.y;
    int b = bl / LL, l = bl % LL;
    int tid = threadIdx.x;
    int nrem = NN - n0; if (nrem > 32) nrem = 32;
    for (int i = tid; i < 32*128; i += 256) {
        int r = i >> 7, c = i & 127;
        if (r < nrem)
            T[r*129 + c] = d_enc[((size_t)(b*NN + n0 + r))*6144 + l*128 + c];
    }
    __syncthreads();
    for (int i = tid; i < 128*32; i += 256) {
        int dd = i >> 5, j = i & 31;
        if (j < nrem) {
            float v = T[j*129 + dd];
            size_t o = ((size_t)(bl*128 + dd))*NN + n0 + j;
            scalar_split(v, d_Xh[o], d_Xl[o]);
        }
    }
}

// ---------------- GroupNorm stat zero / finalize ----------------
__global__ void k_gzero() {
    int i = threadIdx.x;   // 384
    d_gsum[i] = 0.f; d_gsq[i] = 0.f;
}
__global__ void k_gnfin() {
    int i = threadIdx.x;   // 384
    const float inv = 1.0f / (float)(NN*32);
    float mu = d_gsum[i] * inv;
    float var = d_gsq[i] * inv - mu*mu;
    d_gmu[i] = mu;
    d_grs[i] = rsqrtf(var + 1e-5f);
}

// ---------------- tensorized per-node grouped GEMM + fused GN partial stats ----------------
#define SA 68
#define GRP2_STATS (2*96*SA + 2*128*SA)            // u32 offset of stats region
#define GRP2_SMEM ((GRP2_STATS + 768) * 4)         // +3KB for stats
__global__ void __launch_bounds__(256) k_grouped2() {
    extern __shared__ uint32_t SMu[];
    uint32_t* Ah_s = SMu;
    uint32_t* Al_s = SMu + 96*SA;
    uint32_t* Bh_s = SMu + 2*96*SA;
    uint32_t* Bl_s = SMu + 2*96*SA + 128*SA;
    float* s_sum = (float*)(SMu + GRP2_STATS);       // 384
    float* s_sq  = (float*)(SMu + GRP2_STATS + 384); // 384
    int node = blockIdx.x, tid = threadIdx.x;
    for (int i = tid; i < 384; i += 256) { s_sum[i] = 0.f; s_sq[i] = 0.f; }
    const uint4* agh = (const uint4*)(d_aggh + (size_t)node * 12288);
    const uint4* agl = (const uint4*)(d_aggl + (size_t)node * 12288);
    const uint4* pwh = (const uint4*)(d_pwh + (size_t)node * 16384);
    const uint4* pwl = (const uint4*)(d_pwl + (size_t)node * 16384);
    for (int i = tid; i < 1536; i += 256) {
        int r = i >> 4, c = (i & 15) * 4;
        *(uint4*)(Ah_s + r*SA + c) = agh[i];
        *(uint4*)(Al_s + r*SA + c) = agl[i];
    }
    for (int i = tid; i < 2048; i += 256) {
        int r = i >> 4, c = (i & 15) * 4;
        *(uint4*)(Bh_s + r*SA + c) = pwh[i];
        *(uint4*)(Bl_s + r*SA + c) = pwl[i];
    }
    __syncthreads();

    int warp = tid >> 5, lane = tid & 31;
    int wm = (warp >> 2) * 48, wn = (warp & 3) * 32;
    int g = lane >> 2, tig = lane & 3;
    float acc[3][4][4];
    #pragma unroll
    for (int a = 0; a < 3; ++a)
        #pragma unroll
        for (int b = 0; b < 4; ++b)
            #pragma unroll
            for (int c = 0; c < 4; ++c) acc[a][b][c] = 0.f;

    #pragma unroll
    for (int kt = 0; kt < 8; ++kt) {
        uint32_t ah[3][4], al[3][4], bh[4][2], bl[4][2];
        int kb = kt*8 + tig;
        #pragma unroll
        for (int mi = 0; mi < 3; ++mi) {
            int r = wm + mi*16 + g;
            ah[mi][0] = Ah_s[ r     *SA + kb    ];
            ah[mi][1] = Ah_s[(r + 8)*SA + kb    ];
            ah[mi][2] = Ah_s[ r     *SA + kb + 4];
            ah[mi][3] = Ah_s[(r + 8)*SA + kb + 4];
            al[mi][0] = Al_s[ r     *SA + kb    ];
            al[mi][1] = Al_s[(r + 8)*SA + kb    ];
            al[mi][2] = Al_s[ r     *SA + kb + 4];
            al[mi][3] = Al_s[(r + 8)*SA + kb + 4];
        }
        #pragma unroll
        for (int ni = 0; ni < 4; ++ni) {
            int r = wn + ni*8 + g;
            bh[ni][0] = Bh_s[r*SA + kb    ];
            bh[ni][1] = Bh_s[r*SA + kb + 4];
            bl[ni][0] = Bl_s[r*SA + kb    ];
            bl[ni][1] = Bl_s[r*SA + kb + 4];
        }
        #pragma unroll
        for (int mi = 0; mi < 3; ++mi)
            #pragma unroll
            for (int ni = 0; ni < 4; ++ni) {
                asm volatile(
                    "mma.sync.aligned.m16n8k16.row.col.f32.bf16.bf16.f32 "
                    "{%0,%1,%2,%3}, {%4,%5,%6,%7}, {%8,%9}, {%0,%1,%2,%3};"
                    : "+f"(acc[mi][ni][0]), "+f"(acc[mi][ni][1]),
                      "+f"(acc[mi][ni][2]), "+f"(acc[mi][ni][3])
                    : "r"(ah[mi][0]), "r"(ah[mi][1]), "r"(ah[mi][2]), "r"(ah[mi][3]),
                      "r"(bl[ni][0]), "r"(bl[ni][1]));
                asm volatile(
                    "mma.sync.aligned.m16n8k16.row.col.f32.bf16.bf16.f32 "
                    "{%0,%1,%2,%3}, {%4,%5,%6,%7}, {%8,%9}, {%0,%1,%2,%3};"
                    : "+f"(acc[mi][ni][0]), "+f"(acc[mi][ni][1]),
                      "+f"(acc[mi][ni][2]), "+f"(acc[mi][ni][3])
                    : "r"(al[mi][0]), "r"(al[mi][1]), "r"(al[mi][2]), "r"(al[mi][3]),
                      "r"(bh[ni][0]), "r"(bh[ni][1]));
                asm volatile(
                    "mma.sync.aligned.m16n8k16.row.col.f32.bf16.bf16.f32 "
                    "{%0,%1,%2,%3}, {%4,%5,%6,%7}, {%8,%9}, {%0,%1,%2,%3};"
                    : "+f"(acc[mi][ni][0]), "+f"(acc[mi][ni][1]),
                      "+f"(acc[mi][ni][2]), "+f"(acc[mi][ni][3])
                    : "r"(ah[mi][0]), "r"(ah[mi][1]), "r"(ah[mi][2]), "r"(ah[mi][3]),
                      "r"(bh[ni][0]), "r"(bh[ni][1]));
            }
    }

    float* outp = d_gout + (size_t)node * 12288;
    #pragma unroll
    for (int mi = 0; mi < 3; ++mi)
        #pragma unroll
        for (int ni = 0; ni < 4; ++ni) {
            int n = wn + ni*8 + tig*2;
            int sidx = (n >> 5);
            #pragma unroll
            for (int half = 0; half < 2; ++half) {
                int m = wm + mi*16 + g + half*8;
                float v0 = acc[mi][ni][half*2+0];
                float v1 = acc[mi][ni][half*2+1];
                *(float2*)(outp + m*128 + n) = make_float2(v0, v1);
                atomicAdd(&s_sum[m*4 + sidx], v0 + v1);
                atomicAdd(&s_sq [m*4 + sidx], v0*v0 + v1*v1);
            }
        }
    __syncthreads();
    for (int i = tid; i < 384; i += 256) {
        atomicAdd(&d_gsum[i], s_sum[i]);
        atomicAdd(&d_gsq [i], s_sq [i]);
    }
}

// ---------------- fused GN-apply + SiLU proj + time proj + mean add ----------------
__global__ void k_final(const float* __restrict__ gg, const float* __restrict__ gb,
                        const float* __restrict__ p2w, const float* __restrict__ p2b,
                        const float* __restrict__ p1w, const float* __restrict__ p1b,
                        float* __restrict__ out) {
    __shared__ float Xs[6144];
    __shared__ float Ss[LL];
    int bn = blockIdx.x;
    int b = bn / NN, n = bn % NN;
    int tid = threadIdx.x;   // 256
    for (int i = tid; i < 6144; i += 256) {
        int l = i >> 7, c = i & 127;
        int bl = b*LL + l, g = c >> 5;
        float v = d_gout[(size_t)n*12288 + bl*128 + c];
        Xs[i] = (v - d_gmu[bl*4+g]) * d_grs[bl*4+g] * gg[c] + gb[c];
    }
    __syncthreads();
    int lane = tid & 31, w = tid >> 5;
    for (int l = w*6; l < w*6+6; ++l) {
        float s = Xs[l*128+lane]*p2w[lane] + Xs[l*128+lane+32]*p2w[lane+32]
                + Xs[l*128+lane+64]*p2w[lane+64] + Xs[l*128+lane+96]*p2w[lane+96];
        #pragma unroll
        for (int o = 16; o; o >>= 1) s += __shfl_xor_sync(~0u, s, o);
        if (lane == 0) {
            float z = s + p2b[0];
            Ss[l] = z / (1.0f + expf(-z));
        }
    }
    __syncthreads();
    if (tid < L_OUT) {
        float acc = p1b[tid];
        #pragma unroll
        for (int l = 0; l < LL; ++l) acc += Ss[l] * p1w[tid*LL + l];
        out[((size_t)(b*L_OUT + tid))*NN + n] = acc + d_mean[bn];
    }
}

// ---------------- launcher ----------------
extern "C" void kernel_launch(void* const* d_in, const int* in_sizes, int n_in,
                              void* d_out, int out_size) {
    const float* x_enc   = (const float*)d_in[0];
    const float* adj     = (const float*)d_in[1];
    const float* pe_raw  = (const float*)d_in[2];
    const float* conv_w  = (const float*)d_in[3];
    const float* pos_w   = (const float*)d_in[4];
    const float* pos_b   = (const float*)d_in[5];
    const float* wq      = (const float*)d_in[6];
    const float* wk      = (const float*)d_in[7];
    const float* wv      = (const float*)d_in[8];
    const float* wo      = (const float*)d_in[9];
    const float* ln1_g   = (const float*)d_in[10];
    const float* ln1_b   = (const float*)d_in[11];
    const float* ff_w1   = (const float*)d_in[12];
    const float* ff_b1   = (const float*)d_in[13];
    const float* ff_w2   = (const float*)d_in[14];
    const float* ff_b2   = (const float*)d_in[15];
    const float* ln2_g   = (const float*)d_in[16];
    const float* ln2_b   = (const float*)d_in[17];
    const float* wpool   = (const float*)d_in[18];
    const float* gn_g    = (const float*)d_in[19];
    const float* gn_b    = (const float*)d_in[20];
    const float* p2_w    = (const float*)d_in[21];
    const float* p2_b    = (const float*)d_in[22];
    const float* p1_w    = (const float*)d_in[23];
    const float* p1_b    = (const float*)d_in[24];
    float* out = (float*)d_out;

    float *p_enc, *p_q, *p_k, *p_v;
    bf16 *p_hh, *p_hl, *p_qh, *p_ql, *p_ffh, *p_ffl, *p_adjh, *p_adjl;
    bf16 *p_Xh, *p_Xl, *p_peTh, *p_peTl, *p_WT2h, *p_WT2l, *p_pe2h, *p_pe2l;
    bf16 *p_aggh, *p_aggl, *p_pwh, *p_pwl, *p_wph, *p_wpl;
    cudaGetSymbolAddress((void**)&p_enc, d_enc);
    cudaGetSymbolAddress((void**)&p_q,   d_qb);
    cudaGetSymbolAddress((void**)&p_k,   d_kb);
    cudaGetSymbolAddress((void**)&p_v,   d_vb);
    cudaGetSymbolAddress((void**)&p_hh,  d_hh);
    cudaGetSymbolAddress((void**)&p_hl,  d_hl);
    cudaGetSymbolAddress((void**)&p_qh,  d_qh);
    cudaGetSymbolAddress((void**)&p_ql,  d_ql);
    cudaGetSymbolAddress((void**)&p_ffh, d_ffh);
    cudaGetSymbolAddress((void**)&p_ffl, d_ffl);
    cudaGetSymbolAddress((void**)&p_adjh, d_adjh);
    cudaGetSymbolAddress((void**)&p_adjl, d_adjl);
    cudaGetSymbolAddress((void**)&p_Xh,  d_Xh);
    cudaGetSymbolAddress((void**)&p_Xl,  d_Xl);
    cudaGetSymbolAddress((void**)&p_peTh, d_peTh);
    cudaGetSymbolAddress((void**)&p_peTl, d_peTl);
    cudaGetSymbolAddress((void**)&p_WT2h, d_WT2h);
    cudaGetSymbolAddress((void**)&p_WT2l, d_WT2l);
    cudaGetSymbolAddress((void**)&p_pe2h, d_pe2h);
    cudaGetSymbolAddress((void**)&p_pe2l, d_pe2l);
    cudaGetSymbolAddress((void**)&p_aggh, d_aggh);
    cudaGetSymbolAddress((void**)&p_aggl, d_aggl);
    cudaGetSymbolAddress((void**)&p_pwh, d_pwh);
    cudaGetSymbolAddress((void**)&p_pwl, d_pwl);
    cudaGetSymbolAddress((void**)&p_wph, d_wph);
    cudaGetSymbolAddress((void**)&p_wpl, d_wpl);

    cudaFuncSetAttribute(k_attn,     cudaFuncAttributeMaxDynamicSharedMemorySize, ATTN_SMEM);
    cudaFuncSetAttribute(tgemm,      cudaFuncAttributeMaxDynamicSharedMemorySize, TG_SMEM);
    cudaFuncSetAttribute(k_grouped2, cudaFuncAttributeMaxDynamicSharedMemorySize, GRP2_SMEM);

    // prep + splits
    k_peT<<<(DD*NN+255)/256, 256>>>(pe_raw, pos_w, pos_b);
    k_WT2<<<(DD*DD*DD+255)/256, 256>>>(wpool);
    k_conv<<<BNN, 128>>>(x_enc, conv_w, ln1_g, ln1_b);   // conv + mean + LN1 fused
    k_split<<<(NN*NN+255)/256, 256>>>(adj, p_adjh, p_adjl, NN*NN);
    k_splitW<<<768, 256>>>(wq, wk, wv, wo, ff_w1, ff_w2);
    k_gzero<<<1, 384>>>();

    // temporal transformer
    tgemm<<<dim3(3, ROWS/128), 256, TG_SMEM>>>(p_hh, p_hl, p_wph+WPO_Q, p_wpl+WPO_Q,
        p_q, p_k, p_v, nullptr, nullptr, ROWS, 384, 128, nullptr, 6, 0, nullptr, nullptr, 0);
    k_attn<<<BNN, 256, ATTN_SMEM>>>();
    // attn-out: enc += att@wo^T, fused LN2 -> hh/hl
    tgemm<<<dim3(1, ROWS/128), 256, TG_SMEM>>>(p_qh, p_ql, p_wph+WPO_O, p_wpl+WPO_O,
        p_enc, nullptr, nullptr, p_hh, p_hl, ROWS, 128, 128, nullptr, 7, 0, ln2_g, ln2_b, 0);
    tgemm<<<dim3(4, ROWS/128), 256, TG_SMEM>>>(p_hh, p_hl, p_wph+WPO_F1, p_wpl+WPO_F1,
        nullptr, nullptr, nullptr, p_ffh, p_ffl, ROWS, 512, 128, ff_b1, 2, 0, nullptr, nullptr, 0);
    tgemm<<<dim3(1, ROWS/128), 256, TG_SMEM>>>(p_ffh, p_ffl, p_wph+WPO_F2, p_wpl+WPO_F2,
        p_enc, nullptr, nullptr, nullptr, nullptr, ROWS, 128, 512, ff_b2, 3, 0, nullptr, nullptr, 0);

    // spatial GCN
    k_zero<<<(NN*DD+255)/256, 256>>>(p_q, NN*DD);        // pe2 fp32 accumulator
    k_transpose<<<dim3(94, BLL), 256>>>();
    tgemm<<<dim3(1, 24, 8), 256, TG_SMEM>>>(p_adjh, p_adjl, p_peTh, p_peTl,
        p_q, nullptr, nullptr, nullptr, nullptr, NN, 128, NN, nullptr, 8, 0, nullptr, nullptr, 384);
    k_split<<<(NN*DD+255)/256, 256>>>(p_q, p_pe2h, p_pe2l, NN*DD);
    tgemm<<<dim3(128, 24), 256, TG_SMEM>>>(p_pe2h, p_pe2l, p_WT2h, p_WT2l,
        nullptr, nullptr, nullptr, p_pwh, p_pwl, NN, 16384, 128, nullptr, 5, 0, nullptr, nullptr, 0);
    tgemm<<<dim3(24, 96), 256, TG_SMEM>>>(p_adjh, p_adjl, p_Xh, p_Xl,
        nullptr, nullptr, nullptr, p_aggh, p_aggl, NN, 12288, NN, nullptr, 5, 1, nullptr, nullptr, 0);
    k_grouped2<<<NN, 256, GRP2_SMEM>>>();

    // groupnorm + head
    k_gnfin<<<1, 384>>>();
    k_final<<<BNN, 256>>>(gn_g, gn_b, p2_w, p2_b, p1_w, p1_b, out);
}

// round 14
// speedup vs baseline: 1.8004x; 1.0005x over previous
#include <cuda_runtime.h>
#include <cuda_bf16.h>
#include <math.h>
#include <stdint.h>

#define BB 2
#define LL 48
#define NN 3000
#define DD 128
#define L_OUT 24
#define BNN (BB*NN)          // 6000
#define BLL (BB*LL)          // 96
#define ROWS (BNN*LL)        // 288000 token rows
#define ENC_N (ROWS*DD)      // 36,864,000

typedef __nv_bfloat16 bf16;

// ---------------- scratch (device globals; no runtime allocation) ----------------
__device__ float d_mean[BNN];
__device__ float d_enc[ENC_N];           // enc[seq][l][c]
__device__ float d_qb[ENC_N];            // q fp32 (raw); later pe2 fp32 accumulator
__device__ float d_kb[ENC_N];
__device__ float d_vb[ENC_N];
__device__ float d_gout[NN*BLL*DD];      // gout[n][bl][o]
__device__ float d_gmu[BLL*4];
__device__ float d_grs[BLL*4];
__device__ float d_gsum[BLL*4];
__device__ float d_gsq[BLL*4];

// bf16 split pairs
__device__ bf16 d_hh[ENC_N],  d_hl[ENC_N];     // LN output
__device__ bf16 d_qh[ENC_N],  d_ql[ENC_N];     // att_pre
__device__ bf16 d_ffh[ROWS*512], d_ffl[ROWS*512];
__device__ bf16 d_adjh[NN*NN], d_adjl[NN*NN];
__device__ bf16 d_Xh[BLL*DD*NN], d_Xl[BLL*DD*NN];
__device__ bf16 d_peTh[DD*NN], d_peTl[DD*NN];
__device__ bf16 d_WT2h[DD*DD*DD], d_WT2l[DD*DD*DD];  // [(o*128+i)][d]
__device__ bf16 d_pe2h[NN*DD], d_pe2l[NN*DD];
__device__ bf16 d_aggh[NN*BLL*DD], d_aggl[NN*BLL*DD]; // [n][bl*128+i]
__device__ bf16 d_pwh[NN*DD*DD], d_pwl[NN*DD*DD];     // [n][o*128+i]
// weight pool: [wq|wk|wv|wo|ffw1|ffw2]
#define WPO_Q 0
#define WPO_K 16384
#define WPO_V 32768
#define WPO_O 49152
#define WPO_F1 65536
#define WPO_F2 131072
__device__ bf16 d_wph[196608], d_wpl[196608];

__device__ __forceinline__ float gelu_exact(float x) {
    return 0.5f * x * (1.0f + erff(x * 0.70710678118654752f));
}
__device__ __forceinline__ void pack_split(float x0, float x1, uint32_t& hi, uint32_t& lo) {
    uint32_t h;
    asm("cvt.rn.bf16x2.f32 %0, %1, %2;" : "=r"(h) : "f"(x1), "f"(x0));
    float h0 = __uint_as_float(h << 16);
    float h1 = __uint_as_float(h & 0xFFFF0000u);
    float r0 = x0 - h0, r1 = x1 - h1;
    uint32_t l;
    asm("cvt.rn.bf16x2.f32 %0, %1, %2;" : "=r"(l) : "f"(r1), "f"(r0));
    hi = h; lo = l;
}
__device__ __forceinline__ void scalar_split(float v, bf16& h, bf16& l) {
    h = __float2bfloat16_rn(v);
    l = __float2bfloat16_rn(v - __bfloat162float(h));
}
__device__ __forceinline__ void ldsm_x4(uint32_t& r0, uint32_t& r1, uint32_t& r2, uint32_t& r3,
                                        uint32_t addr) {
    asm volatile("ldmatrix.sync.aligned.m8n8.x4.shared.b16 {%0,%1,%2,%3}, [%4];"
                 : "=r"(r0), "=r"(r1), "=r"(r2), "=r"(r3) : "r"(addr));
}
__device__ __forceinline__ void cp16(uint32_t dst, const void* src, bool pred) {
    int sz = pred ? 16 : 0;
    asm volatile("cp.async.cg.shared.global [%0], [%1], 16, %2;\n"
                 :: "r"(dst), "l"(src), "r"(sz) : "memory");
}
#define CP_COMMIT() asm volatile("cp.async.commit_group;\n" ::: "memory")
#define CP_WAIT0()  asm volatile("cp.async.wait_group 0;\n" ::: "memory")

// ---------------- small prep kernels ----------------
__global__ void k_zero(float* __restrict__ p, int n) {
    int i = blockIdx.x * blockDim.x + threadIdx.x;
    if (i < n) p[i] = 0.f;
}

// vectorized split: 4 floats -> 2x bf16x2 per array (n must be divisible by 4)
__global__ void k_split4(const float* __restrict__ in, bf16* __restrict__ h,
                         bf16* __restrict__ l, int n4) {
    int i = blockIdx.x * blockDim.x + threadIdx.x;
    if (i >= n4) return;
    float4 v = ((const float4*)in)[i];
    uint32_t h01, l01, h23, l23;
    pack_split(v.x, v.y, h01, l01);
    pack_split(v.z, v.w, h23, l23);
    ((uint2*)h)[i] = make_uint2(h01, h23);
    ((uint2*)l)[i] = make_uint2(l01, l23);
}

// merged split of all dense weights into the pool
__global__ void k_splitW(const float* __restrict__ wq, const float* __restrict__ wk,
                         const float* __restrict__ wv, const float* __restrict__ wo,
                         const float* __restrict__ f1, const float* __restrict__ f2) {
    int i = blockIdx.x * blockDim.x + threadIdx.x;
    if (i >= 196608) return;
    float v;
    if (i < 65536) {
        int j = i & 16383;
        v = (i < 16384) ? wq[j] : (i < 32768) ? wk[j] : (i < 49152) ? wv[j] : wo[j];
    } else if (i < 131072) {
        v = f1[i - 65536];
    } else {
        v = f2[i - 131072];
    }
    scalar_split(v, d_wph[i], d_wpl[i]);
}

__global__ void k_peT(const float* __restrict__ pr, const float* __restrict__ pw,
                      const float* __restrict__ pb) {
    int i = blockIdx.x * blockDim.x + threadIdx.x;
    if (i >= DD*NN) return;
    int d = i / NN, n = i % NN;
    float v = pr[n]*pw[d*3] + pr[NN+n]*pw[d*3+1] + pr[2*NN+n]*pw[d*3+2] + pb[d];
    scalar_split(v, d_peTh[i], d_peTl[i]);
}

// tiled transpose: wp[d][i][o] -> WT2[(o*128+i)][d]; 32x32 (d,o) tiles per fixed i
__global__ void k_WT2t(const float* __restrict__ wp) {
    __shared__ float T[32][33];
    int i  = blockIdx.x;                 // 0..127
    int d0 = (blockIdx.y & 3) * 32;
    int o0 = (blockIdx.y >> 2) * 32;
    int tx = threadIdx.x & 31, ty = threadIdx.x >> 5;   // 32x8
    #pragma unroll
    for (int r = ty; r < 32; r += 8)
        T[r][tx] = wp[(size_t)(d0 + r)*16384 + i*128 + o0 + tx];
    __syncthreads();
    #pragma unroll
    for (int r = ty; r < 32; r += 8) {
        int o = o0 + r;
        int oi = (o*128 + i)*128 + d0 + tx;
        scalar_split(T[tx][r], d_WT2h[oi], d_WT2l[oi]);
    }
}

// circular conv1d k=3 + per-seq mean + fused LN1 (enc fp32 + split bf16 out)
__global__ void k_conv(const float* __restrict__ x, const float* __restrict__ cw,
                       const float* __restrict__ lg, const float* __restrict__ lb) {
    __shared__ float xs[LL + 2];
    __shared__ float red[384];
    __shared__ float mrs[LL*2];
    __shared__ float mm;
    int seq = blockIdx.x;
    int b = seq / NN, n = seq % NN;
    int t = threadIdx.x;   // 128
    if (t < LL) xs[t + 1] = x[(b*LL + t)*NN + n];
    __syncthreads();
    if (t == 0) {
        float s = 0.f;
        #pragma unroll
        for (int l = 1; l <= LL; ++l) s += xs[l];
        float m = s * (1.0f / LL);
        mm = m; d_mean[seq] = m;
        xs[0] = xs[LL]; xs[LL+1] = xs[1];
    }
    __syncthreads();
    float m = mm;
    float w0 = cw[t*3], w1 = cw[t*3+1], w2 = cw[t*3+2];
    float wc = (w0 + w1 + w2) * m;
    float val[LL];
    #pragma unroll
    for (int l = 0; l < LL; ++l)
        val[l] = w0*xs[l] + w1*xs[l+1] + w2*xs[l+2] - wc;
    int lane = t & 31, w = t >> 5;
    #pragma unroll
    for (int l = 0; l < LL; ++l) {
        float s = val[l], q = val[l]*val[l];
        #pragma unroll
        for (int o = 16; o; o >>= 1) {
            s += __shfl_xor_sync(~0u, s, o);
            q += __shfl_xor_sync(~0u, q, o);
        }
        if (lane == 0) { red[l*4 + w] = s; red[192 + l*4 + w] = q; }
    }
    __syncthreads();
    if (t < LL) {
        float s = red[t*4] + red[t*4+1] + red[t*4+2] + red[t*4+3];
        float q = red[192+t*4] + red[192+t*4+1] + red[192+t*4+2] + red[192+t*4+3];
        float mu = s * (1.0f/128.0f);
        float var = q * (1.0f/128.0f) - mu*mu;
        mrs[t*2] = mu; mrs[t*2+1] = rsqrtf(var + 1e-5f);
    }
    __syncthreads();
    float gg = lg[t], bb = lb[t];
    float* out = d_enc + (size_t)seq * 6144;
    size_t base = (size_t)seq * 6144;
    #pragma unroll
    for (int l = 0; l < LL; ++l) {
        float v = val[l];
        out[l*128 + t] = v;
        float h = (v - mrs[l*2]) * mrs[l*2+1] * gg + bb;
        bf16 hh, ll;
        scalar_split(h, hh, ll);
        d_hh[base + l*128 + t] = hh;
        d_hl[base + l*128 + t] = ll;
    }
}

// ---------------- per-sequence linear attention: (softmax_q @ softmax_k^T) @ v ----------------
#define SPAD 52
#define ATTN_SMEM ((6144*3 + LL*SPAD) * 4)    // 83712 B -> 2 CTAs/SM
__global__ void __launch_bounds__(256) k_attn() {
    extern __shared__ float sm[];
    float* Q  = sm;               // 48x128
    float* KK = sm + 6144;        // 48x128
    float* V  = sm + 12288;       // 48x128
    float* S  = sm + 18432;       // 48xSPAD
    int seq = blockIdx.x, tid = threadIdx.x;
    size_t base = (size_t)seq * 6144;
    for (int i = tid; i < 6144; i += 256) {
        Q[i] = d_qb[base+i]; KK[i] = d_kb[base+i]; V[i] = d_vb[base+i];
    }
    __syncthreads();
    int te = tid & 31, tg = tid >> 5;
    // Q row softmax * d^-0.5
    for (int l = tg*6; l < tg*6+6; ++l) {
        float4 v = *(float4*)&Q[l*128 + te*4];
        float mx = fmaxf(fmaxf(v.x, v.y), fmaxf(v.z, v.w));
        #pragma unroll
        for (int o = 16; o; o >>= 1) mx = fmaxf(mx, __shfl_xor_sync(~0u, mx, o));
        v.x = expf(v.x - mx); v.y = expf(v.y - mx);
        v.z = expf(v.z - mx); v.w = expf(v.w - mx);
        float s = v.x + v.y + v.z + v.w;
        #pragma unroll
        for (int o = 16; o; o >>= 1) s += __shfl_xor_sync(~0u, s, o);
        float f = 0.08838834764831845f / s;
        v.x *= f; v.y *= f; v.z *= f; v.w *= f;
        *(float4*)&Q[l*128 + te*4] = v;
    }
    // K col softmax over L
    if (tid < 128) {
        int c = tid;
        float mx = -1e30f;
        #pragma unroll
        for (int l = 0; l < LL; ++l) mx = fmaxf(mx, KK[l*128 + c]);
        float s = 0.f;
        float ev[LL];
        #pragma unroll
        for (int l = 0; l < LL; ++l) { ev[l] = expf(KK[l*128 + c] - mx); s += ev[l]; }
        float inv = 1.0f / s;
        #pragma unroll
        for (int l = 0; l < LL; ++l) KK[l*128 + c] = ev[l] * inv;
    }
    __syncthreads();
    // S[i][j] = sum_d Q[i][d]*KK[j][d]   (48x48, k=128)
    {
        int ty = tid >> 4, tx = tid & 15;
        int i0 = ty*3, j0 = tx*3;
        float a[3][3] = {};
        #pragma unroll
        for (int d4 = 0; d4 < 128; d4 += 4) {
            float4 q0 = *(float4*)&Q [(i0+0)*128 + d4];
            float4 q1 = *(float4*)&Q [(i0+1)*128 + d4];
            float4 q2 = *(float4*)&Q [(i0+2)*128 + d4];
            float4 k0 = *(float4*)&KK[(j0+0)*128 + d4];
            float4 k1 = *(float4*)&KK[(j0+1)*128 + d4];
            float4 k2 = *(float4*)&KK[(j0+2)*128 + d4];
            a[0][0] += q0.x*k0.x + q0.y*k0.y + q0.z*k0.z + q0.w*k0.w;
            a[0][1] += q0.x*k1.x + q0.y*k1.y + q0.z*k1.z + q0.w*k1.w;
            a[0][2] += q0.x*k2.x + q0.y*k2.y + q0.z*k2.z + q0.w*k2.w;
            a[1][0] += q1.x*k0.x + q1.y*k0.y + q1.z*k0.z + q1.w*k0.w;
            a[1][1] += q1.x*k1.x + q1.y*k1.y + q1.z*k1.z + q1.w*k1.w;
            a[1][2] += q1.x*k2.x + q1.y*k2.y + q1.z*k2.z + q1.w*k2.w;
            a[2][0] += q2.x*k0.x + q2.y*k0.y + q2.z*k0.z + q2.w*k0.w;
            a[2][1] += q2.x*k1.x + q2.y*k1.y + q2.z*k1.z + q2.w*k1.w;
            a[2][2] += q2.x*k2.x + q2.y*k2.y + q2.z*k2.z + q2.w*k2.w;
        }
        #pragma unroll
        for (int r = 0; r < 3; ++r)
            #pragma unroll
            for (int c = 0; c < 3; ++c)
                S[(i0+r)*SPAD + j0 + c] = a[r][c];
    }
    __syncthreads();
    // att[l][e] = sum_j S[l][j]*V[j][e]  -> split store to d_qh/d_ql
    {
        int ty = tid >> 4, tx = tid & 15;
        int l0 = ty*3, e0 = tx*8;
        float a[3][8] = {};
        #pragma unroll
        for (int j = 0; j < LL; ++j) {
            float s0 = S[(l0+0)*SPAD + j];
            float s1 = S[(l0+1)*SPAD + j];
            float s2 = S[(l0+2)*SPAD + j];
            float4 v0 = *(float4*)&V[j*128 + e0];
            float4 v1 = *(float4*)&V[j*128 + e0 + 4];
            a[0][0]+=s0*v0.x; a[0][1]+=s0*v0.y; a[0][2]+=s0*v0.z; a[0][3]+=s0*v0.w;
            a[0][4]+=s0*v1.x; a[0][5]+=s0*v1.y; a[0][6]+=s0*v1.z; a[0][7]+=s0*v1.w;
            a[1][0]+=s1*v0.x; a[1][1]+=s1*v0.y; a[1][2]+=s1*v0.z; a[1][3]+=s1*v0.w;
            a[1][4]+=s1*v1.x; a[1][5]+=s1*v1.y; a[1][6]+=s1*v1.z; a[1][7]+=s1*v1.w;
            a[2][0]+=s2*v0.x; a[2][1]+=s2*v0.y; a[2][2]+=s2*v0.z; a[2][3]+=s2*v0.w;
            a[2][4]+=s2*v1.x; a[2][5]+=s2*v1.y; a[2][6]+=s2*v1.z; a[2][7]+=s2*v1.w;
        }
        #pragma unroll
        for (int r = 0; r < 3; ++r) {
            #pragma unroll
            for (int c = 0; c < 8; c += 2) {
                uint32_t hp, lp;
                pack_split(a[r][c], a[r][c+1], hp, lp);
                size_t w2 = (base + (size_t)(l0+r)*128 + e0 + c) >> 1;
                ((uint32_t*)d_qh)[w2] = hp;
                ((uint32_t*)d_ql)[w2] = lp;
            }
        }
    }
}

// ---------------- 3x-bf16 split GEMM: cp.async + ldmatrix mainloop ----------------
// epi: 0 store fp32 C; 2 gelu(+bias)->Oh/Ol; 3 C+= ; 5 ->Oh/Ol; 6 QKV route C/C2/C3;
//      7 C+= then LN(row)->Oh/Ol (N must be 128, full tiles); 8 atomicAdd fp32 C (split-K)
#define TGW 12
#define TG_SMEM (2*4*128*TGW*4)   // 49152 bytes
__global__ void __launch_bounds__(256) tgemm(
    const bf16* __restrict__ Ah, const bf16* __restrict__ Al,
    const bf16* __restrict__ Bh, const bf16* __restrict__ Bl,
    float* __restrict__ C, float* __restrict__ C2, float* __restrict__ C3,
    bf16* __restrict__ Oh, bf16* __restrict__ Ol,
    int M, int N, int K, const float* __restrict__ bias, int epi, int gswap,
    const float* __restrict__ lng, const float* __restrict__ lnb, int ksplit)
{
    extern __shared__ uint32_t SMu[];
    const int tid = threadIdx.x;
    const int m0 = (gswap ? blockIdx.x : blockIdx.y) * 128;
    const int n0 = (gswap ? blockIdx.y : blockIdx.x) * 128;
    const int lrow = tid >> 1, comp = tid & 1;
    const int warp = tid >> 5, lane = tid & 31;
    const int wm = (warp >> 2) * 64, wn = (warp & 3) * 32;
    const int g = lane >> 2, tig = lane & 3;

    const bf16* Arow = (comp ? Al : Ah) + (size_t)(m0 + lrow) * K;
    const bf16* Brow = (comp ? Bl : Bh) + (size_t)(n0 + lrow) * K;
    const bool mok = (m0 + lrow) < M;

    const uint32_t smem_u32 = (uint32_t)__cvta_generic_to_shared(SMu);
    const int CSTR = 128*TGW*4;          // bytes per 128-row plane
    const int SBUF = 4*CSTR;             // bytes per double-buffer

    const uint32_t dstA = smem_u32 + (comp*128 + lrow)*(TGW*4);
    const uint32_t dstB = smem_u32 + ((2 + comp)*128 + lrow)*(TGW*4);

    const int arow_l = wm + (lane & 7) + ((lane >> 3) & 1)*8;
    const uint32_t aoff = smem_u32 + arow_l*(TGW*4) + (lane >> 4)*16;
    const int brow_l = wn + (lane & 7) + ((lane >> 4) & 1)*8;
    const uint32_t boff = smem_u32 + 2*CSTR + brow_l*(TGW*4) + ((lane >> 3) & 1)*16;

    float acc[4][4][4];
    #pragma unroll
    for (int a = 0; a < 4; ++a)
        #pragma unroll
        for (int b = 0; b < 4; ++b)
            #pragma unroll
            for (int c = 0; c < 4; ++c) acc[a][b][c] = 0.f;

    int kt0 = 0, ktN = (K + 15) / 16;
    if (ksplit > 0) {
        int klo = blockIdx.z * ksplit;
        int khi = min(K, klo + ksplit);
        kt0 = klo >> 4;
        ktN = (khi + 15) >> 4;
    }

    #define FETCH(kt, buf) do { \
        int k_ = (kt)*16; \
        cp16(dstA + (buf)*SBUF,      Arow + k_,     mok && k_ + 8  <= K); \
        cp16(dstA + (buf)*SBUF + 16, Arow + k_ + 8, mok && k_ + 16 <= K); \
        cp16(dstB + (buf)*SBUF,      Brow + k_,     k_ + 8  <= K); \
        cp16(dstB + (buf)*SBUF + 16, Brow + k_ + 8, k_ + 16 <= K); \
        CP_COMMIT(); \
    } while (0)

    FETCH(kt0, 0);
    CP_WAIT0();
    __syncthreads();

    int s = 0;
    for (int kt = kt0; kt < ktN; ++kt) {
        bool nxt = (kt + 1) < ktN;
        if (nxt) FETCH(kt + 1, s ^ 1);

        uint32_t ah[4][4], al[4][4], bh[4][2], bl[4][2];
        const uint32_t sb = s*SBUF;
        #pragma unroll
        for (int mi = 0; mi < 4; ++mi) {
            ldsm_x4(ah[mi][0], ah[mi][1], ah[mi][2], ah[mi][3],
                    aoff + sb + mi*(16*TGW*4));
            ldsm_x4(al[mi][0], al[mi][1], al[mi][2], al[mi][3],
                    aoff + sb + CSTR + mi*(16*TGW*4));
        }
        #pragma unroll
        for (int p = 0; p < 2; ++p) {
            ldsm_x4(bh[2*p][0], bh[2*p][1], bh[2*p+1][0], bh[2*p+1][1],
                    boff + sb + p*(16*TGW*4));
            ldsm_x4(bl[2*p][0], bl[2*p][1], bl[2*p+1][0], bl[2*p+1][1],
                    boff + sb + CSTR + p*(16*TGW*4));
        }
        #pragma unroll
        for (int mi = 0; mi < 4; ++mi)
            #pragma unroll
            for (int ni = 0; ni < 4; ++ni) {
                asm volatile(
                    "mma.sync.aligned.m16n8k16.row.col.f32.bf16.bf16.f32 "
                    "{%0,%1,%2,%3}, {%4,%5,%6,%7}, {%8,%9}, {%0,%1,%2,%3};"
                    : "+f"(acc[mi][ni][0]), "+f"(acc[mi][ni][1]),
                      "+f"(acc[mi][ni][2]), "+f"(acc[mi][ni][3])
                    : "r"(ah[mi][0]), "r"(ah[mi][1]), "r"(ah[mi][2]), "r"(ah[mi][3]),
                      "r"(bl[ni][0]), "r"(bl[ni][1]));
                asm volatile(
                    "mma.sync.aligned.m16n8k16.row.col.f32.bf16.bf16.f32 "
                    "{%0,%1,%2,%3}, {%4,%5,%6,%7}, {%8,%9}, {%0,%1,%2,%3};"
                    : "+f"(acc[mi][ni][0]), "+f"(acc[mi][ni][1]),
                      "+f"(acc[mi][ni][2]), "+f"(acc[mi][ni][3])
                    : "r"(al[mi][0]), "r"(al[mi][1]), "r"(al[mi][2]), "r"(al[mi][3]),
                      "r"(bh[ni][0]), "r"(bh[ni][1]));
                asm volatile(
                    "mma.sync.aligned.m16n8k16.row.col.f32.bf16.bf16.f32 "
                    "{%0,%1,%2,%3}, {%4,%5,%6,%7}, {%8,%9}, {%0,%1,%2,%3};"
                    : "+f"(acc[mi][ni][0]), "+f"(acc[mi][ni][1]),
                      "+f"(acc[mi][ni][2]), "+f"(acc[mi][ni][3])
                    : "r"(ah[mi][0]), "r"(ah[mi][1]), "r"(ah[mi][2]), "r"(ah[mi][3]),
                      "r"(bh[ni][0]), "r"(bh[ni][1]));
            }
        if (nxt) CP_WAIT0();
        __syncthreads();
        s ^= 1;
    }
    #undef FETCH

    if (epi == 7) {
        float* s_sum = (float*)SMu;
        float* s_sq  = s_sum + 512;
        float* s_mr  = s_sq + 512;
        #pragma unroll
        for (int mi = 0; mi < 4; ++mi)
            #pragma unroll
            for (int half = 0; half < 2; ++half) {
                int ml = wm + mi*16 + g + half*8;
                int m = m0 + ml;
                float rsum = 0.f, rsq = 0.f;
                #pragma unroll
                for (int ni = 0; ni < 4; ++ni) {
                    int n = wn + ni*8 + tig*2;
                    size_t off = (size_t)m * 128 + n;
                    float2 cur = *(float2*)(C + off);
                    float r0 = acc[mi][ni][half*2+0] + cur.x;
                    float r1 = acc[mi][ni][half*2+1] + cur.y;
                    *(float2*)(C + off) = make_float2(r0, r1);
                    acc[mi][ni][half*2+0] = r0; acc[mi][ni][half*2+1] = r1;
                    rsum += r0 + r1; rsq += r0*r0 + r1*r1;
                }
                rsum += __shfl_xor_sync(~0u, rsum, 1);
                rsum += __shfl_xor_sync(~0u, rsum, 2);
                rsq  += __shfl_xor_sync(~0u, rsq, 1);
                rsq  += __shfl_xor_sync(~0u, rsq, 2);
                if (tig == 0) {
                    s_sum[ml*4 + (warp & 3)] = rsum;
                    s_sq [ml*4 + (warp & 3)] = rsq;
                }
            }
        __syncthreads();
        if (tid < 128) {
            float s2 = s_sum[tid*4] + s_sum[tid*4+1] + s_sum[tid*4+2] + s_sum[tid*4+3];
            float q2 = s_sq[tid*4] + s_sq[tid*4+1] + s_sq[tid*4+2] + s_sq[tid*4+3];
            float mu = s2 * (1.0f/128.0f);
            float var = q2 * (1.0f/128.0f) - mu*mu;
            s_mr[tid*2] = mu; s_mr[tid*2+1] = rsqrtf(var + 1e-5f);
        }
        __syncthreads();
        #pragma unroll
        for (int mi = 0; mi < 4; ++mi)
            #pragma unroll
            for (int ni = 0; ni < 4; ++ni) {
                int n = wn + ni*8 + tig*2;
                float g0 = lng[n], g1 = lng[n+1];
                float b0 = lnb[n], b1 = lnb[n+1];
                #pragma unroll
                for (int half = 0; half < 2; ++half) {
                    int ml = wm + mi*16 + g + half*8;
                    int m = m0 + ml;
                    float mu = s_mr[ml*2], rg = s_mr[ml*2+1];
                    float v0 = (acc[mi][ni][half*2+0] - mu)*rg*g0 + b0;
                    float v1 = (acc[mi][ni][half*2+1] - mu)*rg*g1 + b1;
                    uint32_t hp, lp;
                    pack_split(v0, v1, hp, lp);
                    size_t off = (size_t)m * 128 + n;
                    ((uint32_t*)Oh)[off >> 1] = hp;
                    ((uint32_t*)Ol)[off >> 1] = lp;
                }
            }
        return;
    }

    // generic epilogue
    #pragma unroll
    for (int mi = 0; mi < 4; ++mi) {
        #pragma unroll
        for (int ni = 0; ni < 4; ++ni) {
            int n = n0 + wn + ni*8 + tig*2;
            float bv0 = 0.f, bv1 = 0.f;
            if (bias) { bv0 = bias[n]; bv1 = bias[n+1]; }
            #pragma unroll
            for (int half = 0; half < 2; ++half) {
                int m = m0 + wm + mi*16 + g + half*8;
                if (m >= M) continue;
                float r0 = acc[mi][ni][half*2+0] + bv0;
                float r1 = acc[mi][ni][half*2+1] + bv1;
                size_t off = (size_t)m * N + n;
                if (epi == 0) {
                    *(float2*)(C + off) = make_float2(r0, r1);
                } else if (epi == 2) {
                    r0 = gelu_exact(r0); r1 = gelu_exact(r1);
                    uint32_t hp, lp;
                    pack_split(r0, r1, hp, lp);
                    ((uint32_t*)Oh)[off >> 1] = hp;
                    ((uint32_t*)Ol)[off >> 1] = lp;
                } else if (epi == 3) {
                    float2 cur = *(float2*)(C + off);
                    *(float2*)(C + off) = make_float2(r0 + cur.x, r1 + cur.y);
                } else if (epi == 5) {
                    uint32_t hp, lp;
                    pack_split(r0, r1, hp, lp);
                    ((uint32_t*)Oh)[off >> 1] = hp;
                    ((uint32_t*)Ol)[off >> 1] = lp;
                } else if (epi == 8) {
                    atomicAdd(C + off, r0);
                    atomicAdd(C + off + 1, r1);
                } else { // 6: QKV routing
                    int buf = n >> 7, col = n & 127;
                    float* Cd = (buf == 0) ? C : (buf == 1 ? C2 : C3);
                    *(float2*)(Cd + ((size_t)m << 7) + col) = make_float2(r0, r1);
                }
            }
        }
    }
}

// ---------------- transpose enc -> X[(bl*128+d)][n], paired bf16x2 stores ----------------
__global__ void k_transpose() {   // grid (94, 96), 256 threads
    __shared__ float T[32*129];
    int n0 = blockIdx.x * 32;
    int bl = blockIdx.y;
    int b = bl / LL, l = bl % LL;
    int tid = threadIdx.x;
    int nrem = NN - n0; if (nrem > 32) nrem = 32;   // 32 or 24, always even
    for (int i = tid; i < 32*128; i += 256) {
        int r = i >> 7, c = i & 127;
        if (r < nrem)
            T[r*129 + c] = d_enc[((size_t)(b*NN + n0 + r))*6144 + l*128 + c];
    }
    __syncthreads();
    for (int i = tid; i < 128*16; i += 256) {
        int dd = i >> 4, j2 = (i & 15) * 2;
        if (j2 < nrem) {
            uint32_t hp, lp;
            pack_split(T[j2*129 + dd], T[(j2+1)*129 + dd], hp, lp);
            size_t o = ((size_t)(bl*128 + dd))*NN + n0 + j2;   // even
            ((uint32_t*)d_Xh)[o >> 1] = hp;
            ((uint32_t*)d_Xl)[o >> 1] = lp;
        }
    }
}

// ---------------- GroupNorm stat zero / finalize ----------------
__global__ void k_gzero() {
    int i = threadIdx.x;   // 384
    d_gsum[i] = 0.f; d_gsq[i] = 0.f;
}
__global__ void k_gnfin() {
    int i = threadIdx.x;   // 384
    const float inv = 1.0f / (float)(NN*32);
    float mu = d_gsum[i] * inv;
    float var = d_gsq[i] * inv - mu*mu;
    d_gmu[i] = mu;
    d_grs[i] = rsqrtf(var + 1e-5f);
}

// ---------------- tensorized per-node grouped GEMM + fused GN partial stats ----------------
#define SA 68
#define GRP2_STATS (2*96*SA + 2*128*SA)
#define GRP2_SMEM ((GRP2_STATS + 768) * 4)
__global__ void __launch_bounds__(256) k_grouped2() {
    extern __shared__ uint32_t SMu[];
    uint32_t* Ah_s = SMu;
    uint32_t* Al_s = SMu + 96*SA;
    uint32_t* Bh_s = SMu + 2*96*SA;
    uint32_t* Bl_s = SMu + 2*96*SA + 128*SA;
    float* s_sum = (float*)(SMu + GRP2_STATS);
    float* s_sq  = (float*)(SMu + GRP2_STATS + 384);
    int node = blockIdx.x, tid = threadIdx.x;
    for (int i = tid; i < 384; i += 256) { s_sum[i] = 0.f; s_sq[i] = 0.f; }
    const uint4* agh = (const uint4*)(d_aggh + (size_t)node * 12288);
    const uint4* agl = (const uint4*)(d_aggl + (size_t)node * 12288);
    const uint4* pwh = (const uint4*)(d_pwh + (size_t)node * 16384);
    const uint4* pwl = (const uint4*)(d_pwl + (size_t)node * 16384);
    for (int i = tid; i < 1536; i += 256) {
        int r = i >> 4, c = (i & 15) * 4;
        *(uint4*)(Ah_s + r*SA + c) = agh[i];
        *(uint4*)(Al_s + r*SA + c) = agl[i];
    }
    for (int i = tid; i < 2048; i += 256) {
        int r = i >> 4, c = (i & 15) * 4;
        *(uint4*)(Bh_s + r*SA + c) = pwh[i];
        *(uint4*)(Bl_s + r*SA + c) = pwl[i];
    }
    __syncthreads();

    int warp = tid >> 5, lane = tid & 31;
    int wm = (warp >> 2) * 48, wn = (warp & 3) * 32;
    int g = lane >> 2, tig = lane & 3;
    float acc[3][4][4];
    #pragma unroll
    for (int a = 0; a < 3; ++a)
        #pragma unroll
        for (int b = 0; b < 4; ++b)
            #pragma unroll
            for (int c = 0; c < 4; ++c) acc[a][b][c] = 0.f;

    #pragma unroll
    for (int kt = 0; kt < 8; ++kt) {
        uint32_t ah[3][4], al[3][4], bh[4][2], bl[4][2];
        int kb = kt*8 + tig;
        #pragma unroll
        for (int mi = 0; mi < 3; ++mi) {
            int r = wm + mi*16 + g;
            ah[mi][0] = Ah_s[ r     *SA + kb    ];
            ah[mi][1] = Ah_s[(r + 8)*SA + kb    ];
            ah[mi][2] = Ah_s[ r     *SA + kb + 4];
            ah[mi][3] = Ah_s[(r + 8)*SA + kb + 4];
            al[mi][0] = Al_s[ r     *SA + kb    ];
            al[mi][1] = Al_s[(r + 8)*SA + kb    ];
            al[mi][2] = Al_s[ r     *SA + kb + 4];
            al[mi][3] = Al_s[(r + 8)*SA + kb + 4];
        }
        #pragma unroll
        for (int ni = 0; ni < 4; ++ni) {
            int r = wn + ni*8 + g;
            bh[ni][0] = Bh_s[r*SA + kb    ];
            bh[ni][1] = Bh_s[r*SA + kb + 4];
            bl[ni][0] = Bl_s[r*SA + kb    ];
            bl[ni][1] = Bl_s[r*SA + kb + 4];
        }
        #pragma unroll
        for (int mi = 0; mi < 3; ++mi)
            #pragma unroll
            for (int ni = 0; ni < 4; ++ni) {
                asm volatile(
                    "mma.sync.aligned.m16n8k16.row.col.f32.bf16.bf16.f32 "
                    "{%0,%1,%2,%3}, {%4,%5,%6,%7}, {%8,%9}, {%0,%1,%2,%3};"
                    : "+f"(acc[mi][ni][0]), "+f"(acc[mi][ni][1]),
                      "+f"(acc[mi][ni][2]), "+f"(acc[mi][ni][3])
                    : "r"(ah[mi][0]), "r"(ah[mi][1]), "r"(ah[mi][2]), "r"(ah[mi][3]),
                      "r"(bl[ni][0]), "r"(bl[ni][1]));
                asm volatile(
                    "mma.sync.aligned.m16n8k16.row.col.f32.bf16.bf16.f32 "
                    "{%0,%1,%2,%3}, {%4,%5,%6,%7}, {%8,%9}, {%0,%1,%2,%3};"
                    : "+f"(acc[mi][ni][0]), "+f"(acc[mi][ni][1]),
                      "+f"(acc[mi][ni][2]), "+f"(acc[mi][ni][3])
                    : "r"(al[mi][0]), "r"(al[mi][1]), "r"(al[mi][2]), "r"(al[mi][3]),
                      "r"(bh[ni][0]), "r"(bh[ni][1]));
                asm volatile(
                    "mma.sync.aligned.m16n8k16.row.col.f32.bf16.bf16.f32 "
                    "{%0,%1,%2,%3}, {%4,%5,%6,%7}, {%8,%9}, {%0,%1,%2,%3};"
                    : "+f"(acc[mi][ni][0]), "+f"(acc[mi][ni][1]),
                      "+f"(acc[mi][ni][2]), "+f"(acc[mi][ni][3])
                    : "r"(ah[mi][0]), "r"(ah[mi][1]), "r"(ah[mi][2]), "r"(ah[mi][3]),
                      "r"(bh[ni][0]), "r"(bh[ni][1]));
            }
    }

    float* outp = d_gout + (size_t)node * 12288;
    #pragma unroll
    for (int mi = 0; mi < 3; ++mi)
        #pragma unroll
        for (int ni = 0; ni < 4; ++ni) {
            int n = wn + ni*8 + tig*2;
            int sidx = (n >> 5);
            #pragma unroll
            for (int half = 0; half < 2; ++half) {
                int m = wm + mi*16 + g + half*8;
                float v0 = acc[mi][ni][half*2+0];
                float v1 = acc[mi][ni][half*2+1];
                *(float2*)(outp + m*128 + n) = make_float2(v0, v1);
                atomicAdd(&s_sum[m*4 + sidx], v0 + v1);
                atomicAdd(&s_sq [m*4 + sidx], v0*v0 + v1*v1);
            }
        }
    __syncthreads();
    for (int i = tid; i < 384; i += 256) {
        atomicAdd(&d_gsum[i], s_sum[i]);
        atomicAdd(&d_gsq [i], s_sq [i]);
    }
}

// ---------------- fused GN-apply + SiLU proj + time proj + mean add ----------------
__global__ void k_final(const float* __restrict__ gg, const float* __restrict__ gb,
                        const float* __restrict__ p2w, const float* __restrict__ p2b,
                        const float* __restrict__ p1w, const float* __restrict__ p1b,
                        float* __restrict__ out) {
    __shared__ float Xs[6144];
    __shared__ float Ss[LL];
    int bn = blockIdx.x;
    int b = bn / NN, n = bn % NN;
    int tid = threadIdx.x;   // 256
    for (int i = tid; i < 6144; i += 256) {
        int l = i >> 7, c = i & 127;
        int bl = b*LL + l, g = c >> 5;
        float v = d_gout[(size_t)n*12288 + bl*128 + c];
        Xs[i] = (v - d_gmu[bl*4+g]) * d_grs[bl*4+g] * gg[c] + gb[c];
    }
    __syncthreads();
    int lane = tid & 31, w = tid >> 5;
    for (int l = w*6; l < w*6+6; ++l) {
        float s = Xs[l*128+lane]*p2w[lane] + Xs[l*128+lane+32]*p2w[lane+32]
                + Xs[l*128+lane+64]*p2w[lane+64] + Xs[l*128+lane+96]*p2w[lane+96];
        #pragma unroll
        for (int o = 16; o; o >>= 1) s += __shfl_xor_sync(~0u, s, o);
        if (lane == 0) {
            float z = s + p2b[0];
            Ss[l] = z / (1.0f + expf(-z));
        }
    }
    __syncthreads();
    if (tid < L_OUT) {
        float acc = p1b[tid];
        #pragma unroll
        for (int l = 0; l < LL; ++l) acc += Ss[l] * p1w[tid*LL + l];
        out[((size_t)(b*L_OUT + tid))*NN + n] = acc + d_mean[bn];
    }
}

// ---------------- launcher ----------------
extern "C" void kernel_launch(void* const* d_in, const int* in_sizes, int n_in,
                              void* d_out, int out_size) {
    const float* x_enc   = (const float*)d_in[0];
    const float* adj     = (const float*)d_in[1];
    const float* pe_raw  = (const float*)d_in[2];
    const float* conv_w  = (const float*)d_in[3];
    const float* pos_w   = (const float*)d_in[4];
    const float* pos_b   = (const float*)d_in[5];
    const float* wq      = (const float*)d_in[6];
    const float* wk      = (const float*)d_in[7];
    const float* wv      = (const float*)d_in[8];
    const float* wo      = (const float*)d_in[9];
    const float* ln1_g   = (const float*)d_in[10];
    const float* ln1_b   = (const float*)d_in[11];
    const float* ff_w1   = (const float*)d_in[12];
    const float* ff_b1   = (const float*)d_in[13];
    const float* ff_w2   = (const float*)d_in[14];
    const float* ff_b2   = (const float*)d_in[15];
    const float* ln2_g   = (const float*)d_in[16];
    const float* ln2_b   = (const float*)d_in[17];
    const float* wpool   = (const float*)d_in[18];
    const float* gn_g    = (const float*)d_in[19];
    const float* gn_b    = (const float*)d_in[20];
    const float* p2_w    = (const float*)d_in[21];
    const float* p2_b    = (const float*)d_in[22];
    const float* p1_w    = (const float*)d_in[23];
    const float* p1_b    = (const float*)d_in[24];
    float* out = (float*)d_out;

    float *p_enc, *p_q, *p_k, *p_v;
    bf16 *p_hh, *p_hl, *p_qh, *p_ql, *p_ffh, *p_ffl, *p_adjh, *p_adjl;
    bf16 *p_Xh, *p_Xl, *p_peTh, *p_peTl, *p_WT2h, *p_WT2l, *p_pe2h, *p_pe2l;
    bf16 *p_aggh, *p_aggl, *p_pwh, *p_pwl, *p_wph, *p_wpl;
    cudaGetSymbolAddress((void**)&p_enc, d_enc);
    cudaGetSymbolAddress((void**)&p_q,   d_qb);
    cudaGetSymbolAddress((void**)&p_k,   d_kb);
    cudaGetSymbolAddress((void**)&p_v,   d_vb);
    cudaGetSymbolAddress((void**)&p_hh,  d_hh);
    cudaGetSymbolAddress((void**)&p_hl,  d_hl);
    cudaGetSymbolAddress((void**)&p_qh,  d_qh);
    cudaGetSymbolAddress((void**)&p_ql,  d_ql);
    cudaGetSymbolAddress((void**)&p_ffh, d_ffh);
    cudaGetSymbolAddress((void**)&p_ffl, d_ffl);
    cudaGetSymbolAddress((void**)&p_adjh, d_adjh);
    cudaGetSymbolAddress((void**)&p_adjl, d_adjl);
    cudaGetSymbolAddress((void**)&p_Xh,  d_Xh);
    cudaGetSymbolAddress((void**)&p_Xl,  d_Xl);
    cudaGetSymbolAddress((void**)&p_peTh, d_peTh);
    cudaGetSymbolAddress((void**)&p_peTl, d_peTl);
    cudaGetSymbolAddress((void**)&p_WT2h, d_WT2h);
    cudaGetSymbolAddress((void**)&p_WT2l, d_WT2l);
    cudaGetSymbolAddress((void**)&p_pe2h, d_pe2h);
    cudaGetSymbolAddress((void**)&p_pe2l, d_pe2l);
    cudaGetSymbolAddress((void**)&p_aggh, d_aggh);
    cudaGetSymbolAddress((void**)&p_aggl, d_aggl);
    cudaGetSymbolAddress((void**)&p_pwh, d_pwh);
    cudaGetSymbolAddress((void**)&p_pwl, d_pwl);
    cudaGetSymbolAddress((void**)&p_wph, d_wph);
    cudaGetSymbolAddress((void**)&p_wpl, d_wpl);

    cudaFuncSetAttribute(k_attn,     cudaFuncAttributeMaxDynamicSharedMemorySize, ATTN_SMEM);
    cudaFuncSetAttribute(tgemm,      cudaFuncAttributeMaxDynamicSharedMemorySize, TG_SMEM);
    cudaFuncSetAttribute(k_grouped2, cudaFuncAttributeMaxDynamicSharedMemorySize, GRP2_SMEM);

    // prep + splits
    k_peT<<<(DD*NN+255)/256, 256>>>(pe_raw, pos_w, pos_b);
    k_WT2t<<<dim3(128, 16), 256>>>(wpool);
    k_conv<<<BNN, 128>>>(x_enc, conv_w, ln1_g, ln1_b);   // conv + mean + LN1 fused
    k_split4<<<(NN*NN/4+255)/256, 256>>>(adj, p_adjh, p_adjl, NN*NN/4);
    k_splitW<<<768, 256>>>(wq, wk, wv, wo, ff_w1, ff_w2);
    k_gzero<<<1, 384>>>();

    // temporal transformer
    tgemm<<<dim3(3, ROWS/128), 256, TG_SMEM>>>(p_hh, p_hl, p_wph+WPO_Q, p_wpl+WPO_Q,
        p_q, p_k, p_v, nullptr, nullptr, ROWS, 384, 128, nullptr, 6, 0, nullptr, nullptr, 0);
    k_attn<<<BNN, 256, ATTN_SMEM>>>();
    tgemm<<<dim3(1, ROWS/128), 256, TG_SMEM>>>(p_qh, p_ql, p_wph+WPO_O, p_wpl+WPO_O,
        p_enc, nullptr, nullptr, p_hh, p_hl, ROWS, 128, 128, nullptr, 7, 0, ln2_g, ln2_b, 0);
    tgemm<<<dim3(4, ROWS/128), 256, TG_SMEM>>>(p_hh, p_hl, p_wph+WPO_F1, p_wpl+WPO_F1,
        nullptr, nullptr, nullptr, p_ffh, p_ffl, ROWS, 512, 128, ff_b1, 2, 0, nullptr, nullptr, 0);
    tgemm<<<dim3(1, ROWS/128), 256, TG_SMEM>>>(p_ffh, p_ffl, p_wph+WPO_F2, p_wpl+WPO_F2,
        p_enc, nullptr, nullptr, nullptr, nullptr, ROWS, 128, 512, ff_b2, 3, 0, nullptr, nullptr, 0);

    // spatial GCN
    k_zero<<<(NN*DD+255)/256, 256>>>(p_q, NN*DD);        // pe2 fp32 accumulator
    k_transpose<<<dim3(94, BLL), 256>>>();
    tgemm<<<dim3(1, 24, 8), 256, TG_SMEM>>>(p_adjh, p_adjl, p_peTh, p_peTl,
        p_q, nullptr, nullptr, nullptr, nullptr, NN, 128, NN, nullptr, 8, 0, nullptr, nullptr, 384);
    k_split4<<<(NN*DD/4+255)/256, 256>>>(p_q, p_pe2h, p_pe2l, NN*DD/4);
    tgemm<<<dim3(128, 24), 256, TG_SMEM>>>(p_pe2h, p_pe2l, p_WT2h, p_WT2l,
        nullptr, nullptr, nullptr, p_pwh, p_pwl, NN, 16384, 128, nullptr, 5, 0, nullptr, nullptr, 0);
    tgemm<<<dim3(24, 96), 256, TG_SMEM>>>(p_adjh, p_adjl, p_Xh, p_Xl,
        nullptr, nullptr, nullptr, p_aggh, p_aggl, NN, 12288, NN, nullptr, 5, 1, nullptr, nullptr, 0);
    k_grouped2<<<NN, 256, GRP2_SMEM>>>();

    // groupnorm + head
    k_gnfin<<<1, 384>>>();
    k_final<<<BNN, 256>>>(gn_g, gn_b, p2_w, p2_b, p1_w, p1_b, out);
}

// round 15
// speedup vs baseline: 1.8884x; 1.0489x over previous
#include <cuda_runtime.h>
#include <cuda_bf16.h>
#include <math.h>
#include <stdint.h>

#define BB 2
#define LL 48
#define NN 3000
#define DD 128
#define L_OUT 24
#define BNN (BB*NN)          // 6000
#define BLL (BB*LL)          // 96
#define ROWS (BNN*LL)        // 288000 token rows
#define ENC_N (ROWS*DD)      // 36,864,000

typedef __nv_bfloat16 bf16;

// ---------------- scratch (device globals; no runtime allocation) ----------------
__device__ float d_mean[BNN];
__device__ float d_enc[ENC_N];           // enc[seq][l][c]
__device__ float d_qb[ENC_N];            // q fp32 (raw); later pe2 fp32 accumulator
__device__ float d_kb[ENC_N];
__device__ float d_vb[ENC_N];
__device__ float d_gout[NN*BLL*DD];      // gout[n][bl][o]
__device__ float d_gmu[BLL*4];
__device__ float d_grs[BLL*4];
__device__ float d_gsum[BLL*4];
__device__ float d_gsq[BLL*4];

// bf16 split pairs
__device__ bf16 d_hh[ENC_N],  d_hl[ENC_N];     // LN output
__device__ bf16 d_qh[ENC_N],  d_ql[ENC_N];     // att_pre
__device__ bf16 d_ffh[ROWS*512], d_ffl[ROWS*512];
__device__ bf16 d_adjh[NN*NN], d_adjl[NN*NN];
__device__ bf16 d_Xh[BLL*DD*NN], d_Xl[BLL*DD*NN];
__device__ bf16 d_peTh[DD*NN], d_peTl[DD*NN];
__device__ bf16 d_WT2h[DD*DD*DD], d_WT2l[DD*DD*DD];  // [(o*128+i)][d]
__device__ bf16 d_pe2h[NN*DD], d_pe2l[NN*DD];
__device__ bf16 d_aggh[NN*BLL*DD], d_aggl[NN*BLL*DD]; // [n][bl*128+i]
__device__ bf16 d_pwh[NN*DD*DD], d_pwl[NN*DD*DD];     // [n][o*128+i]
// weight pool: [wq|wk|wv|wo|ffw1|ffw2]
#define WPO_Q 0
#define WPO_K 16384
#define WPO_V 32768
#define WPO_O 49152
#define WPO_F1 65536
#define WPO_F2 131072
__device__ bf16 d_wph[196608], d_wpl[196608];

__device__ __forceinline__ float gelu_exact(float x) {
    return 0.5f * x * (1.0f + erff(x * 0.70710678118654752f));
}
__device__ __forceinline__ void pack_split(float x0, float x1, uint32_t& hi, uint32_t& lo) {
    uint32_t h;
    asm("cvt.rn.bf16x2.f32 %0, %1, %2;" : "=r"(h) : "f"(x1), "f"(x0));
    float h0 = __uint_as_float(h << 16);
    float h1 = __uint_as_float(h & 0xFFFF0000u);
    float r0 = x0 - h0, r1 = x1 - h1;
    uint32_t l;
    asm("cvt.rn.bf16x2.f32 %0, %1, %2;" : "=r"(l) : "f"(r1), "f"(r0));
    hi = h; lo = l;
}
__device__ __forceinline__ void scalar_split(float v, bf16& h, bf16& l) {
    h = __float2bfloat16_rn(v);
    l = __float2bfloat16_rn(v - __bfloat162float(h));
}
__device__ __forceinline__ void ldsm_x4(uint32_t& r0, uint32_t& r1, uint32_t& r2, uint32_t& r3,
                                        uint32_t addr) {
    asm volatile("ldmatrix.sync.aligned.m8n8.x4.shared.b16 {%0,%1,%2,%3}, [%4];"
                 : "=r"(r0), "=r"(r1), "=r"(r2), "=r"(r3) : "r"(addr));
}
__device__ __forceinline__ void cp16(uint32_t dst, const void* src, bool pred) {
    int sz = pred ? 16 : 0;
    asm volatile("cp.async.cg.shared.global [%0], [%1], 16, %2;\n"
                 :: "r"(dst), "l"(src), "r"(sz) : "memory");
}
#define CP_COMMIT() asm volatile("cp.async.commit_group;\n" ::: "memory")
#define CP_WAIT0()  asm volatile("cp.async.wait_group 0;\n" ::: "memory")
#define CP_WAIT1()  asm volatile("cp.async.wait_group 1;\n" ::: "memory")

// ---------------- small prep kernels ----------------
__global__ void k_zero(float* __restrict__ p, int n) {
    int i = blockIdx.x * blockDim.x + threadIdx.x;
    if (i < n) p[i] = 0.f;
}

// vectorized split: 4 floats -> 2x bf16x2 per array (n must be divisible by 4)
__global__ void k_split4(const float* __restrict__ in, bf16* __restrict__ h,
                         bf16* __restrict__ l, int n4) {
    int i = blockIdx.x * blockDim.x + threadIdx.x;
    if (i >= n4) return;
    float4 v = ((const float4*)in)[i];
    uint32_t h01, l01, h23, l23;
    pack_split(v.x, v.y, h01, l01);
    pack_split(v.z, v.w, h23, l23);
    ((uint2*)h)[i] = make_uint2(h01, h23);
    ((uint2*)l)[i] = make_uint2(l01, l23);
}

// merged split of all dense weights into the pool
__global__ void k_splitW(const float* __restrict__ wq, const float* __restrict__ wk,
                         const float* __restrict__ wv, const float* __restrict__ wo,
                         const float* __restrict__ f1, const float* __restrict__ f2) {
    int i = blockIdx.x * blockDim.x + threadIdx.x;
    if (i >= 196608) return;
    float v;
    if (i < 65536) {
        int j = i & 16383;
        v = (i < 16384) ? wq[j] : (i < 32768) ? wk[j] : (i < 49152) ? wv[j] : wo[j];
    } else if (i < 131072) {
        v = f1[i - 65536];
    } else {
        v = f2[i - 131072];
    }
    scalar_split(v, d_wph[i], d_wpl[i]);
}

__global__ void k_peT(const float* __restrict__ pr, const float* __restrict__ pw,
                      const float* __restrict__ pb) {
    int i = blockIdx.x * blockDim.x + threadIdx.x;
    if (i >= DD*NN) return;
    int d = i / NN, n = i % NN;
    float v = pr[n]*pw[d*3] + pr[NN+n]*pw[d*3+1] + pr[2*NN+n]*pw[d*3+2] + pb[d];
    scalar_split(v, d_peTh[i], d_peTl[i]);
}

// tiled transpose: wp[d][i][o] -> WT2[(o*128+i)][d]; 32x32 (d,o) tiles per fixed i
__global__ void k_WT2t(const float* __restrict__ wp) {
    __shared__ float T[32][33];
    int i  = blockIdx.x;                 // 0..127
    int d0 = (blockIdx.y & 3) * 32;
    int o0 = (blockIdx.y >> 2) * 32;
    int tx = threadIdx.x & 31, ty = threadIdx.x >> 5;   // 32x8
    #pragma unroll
    for (int r = ty; r < 32; r += 8)
        T[r][tx] = wp[(size_t)(d0 + r)*16384 + i*128 + o0 + tx];
    __syncthreads();
    #pragma unroll
    for (int r = ty; r < 32; r += 8) {
        int o = o0 + r;
        int oi = (o*128 + i)*128 + d0 + tx;
        scalar_split(T[tx][r], d_WT2h[oi], d_WT2l[oi]);
    }
}

// circular conv1d k=3 + per-seq mean + fused LN1 (enc fp32 + split bf16 out)
__global__ void k_conv(const float* __restrict__ x, const float* __restrict__ cw,
                       const float* __restrict__ lg, const float* __restrict__ lb) {
    __shared__ float xs[LL + 2];
    __shared__ float red[384];
    __shared__ float mrs[LL*2];
    __shared__ float mm;
    int seq = blockIdx.x;
    int b = seq / NN, n = seq % NN;
    int t = threadIdx.x;   // 128
    if (t < LL) xs[t + 1] = x[(b*LL + t)*NN + n];
    __syncthreads();
    if (t == 0) {
        float s = 0.f;
        #pragma unroll
        for (int l = 1; l <= LL; ++l) s += xs[l];
        float m = s * (1.0f / LL);
        mm = m; d_mean[seq] = m;
        xs[0] = xs[LL]; xs[LL+1] = xs[1];
    }
    __syncthreads();
    float m = mm;
    float w0 = cw[t*3], w1 = cw[t*3+1], w2 = cw[t*3+2];
    float wc = (w0 + w1 + w2) * m;
    float val[LL];
    #pragma unroll
    for (int l = 0; l < LL; ++l)
        val[l] = w0*xs[l] + w1*xs[l+1] + w2*xs[l+2] - wc;
    int lane = t & 31, w = t >> 5;
    #pragma unroll
    for (int l = 0; l < LL; ++l) {
        float s = val[l], q = val[l]*val[l];
        #pragma unroll
        for (int o = 16; o; o >>= 1) {
            s += __shfl_xor_sync(~0u, s, o);
            q += __shfl_xor_sync(~0u, q, o);
        }
        if (lane == 0) { red[l*4 + w] = s; red[192 + l*4 + w] = q; }
    }
    __syncthreads();
    if (t < LL) {
        float s = red[t*4] + red[t*4+1] + red[t*4+2] + red[t*4+3];
        float q = red[192+t*4] + red[192+t*4+1] + red[192+t*4+2] + red[192+t*4+3];
        float mu = s * (1.0f/128.0f);
        float var = q * (1.0f/128.0f) - mu*mu;
        mrs[t*2] = mu; mrs[t*2+1] = rsqrtf(var + 1e-5f);
    }
    __syncthreads();
    float gg = lg[t], bb = lb[t];
    float* out = d_enc + (size_t)seq * 6144;
    size_t base = (size_t)seq * 6144;
    #pragma unroll
    for (int l = 0; l < LL; ++l) {
        float v = val[l];
        out[l*128 + t] = v;
        float h = (v - mrs[l*2]) * mrs[l*2+1] * gg + bb;
        bf16 hh, ll;
        scalar_split(h, hh, ll);
        d_hh[base + l*128 + t] = hh;
        d_hl[base + l*128 + t] = ll;
    }
}

// ---------------- per-sequence linear attention: (softmax_q @ softmax_k^T) @ v ----------------
#define SPAD 52
#define ATTN_SMEM ((6144*3 + LL*SPAD) * 4)    // 83712 B -> 2 CTAs/SM
__global__ void __launch_bounds__(256) k_attn() {
    extern __shared__ float sm[];
    float* Q  = sm;               // 48x128
    float* KK = sm + 6144;        // 48x128
    float* V  = sm + 12288;       // 48x128
    float* S  = sm + 18432;       // 48xSPAD
    int seq = blockIdx.x, tid = threadIdx.x;
    size_t base = (size_t)seq * 6144;
    for (int i = tid; i < 6144; i += 256) {
        Q[i] = d_qb[base+i]; KK[i] = d_kb[base+i]; V[i] = d_vb[base+i];
    }
    __syncthreads();
    int te = tid & 31, tg = tid >> 5;
    // Q row softmax * d^-0.5
    for (int l = tg*6; l < tg*6+6; ++l) {
        float4 v = *(float4*)&Q[l*128 + te*4];
        float mx = fmaxf(fmaxf(v.x, v.y), fmaxf(v.z, v.w));
        #pragma unroll
        for (int o = 16; o; o >>= 1) mx = fmaxf(mx, __shfl_xor_sync(~0u, mx, o));
        v.x = expf(v.x - mx); v.y = expf(v.y - mx);
        v.z = expf(v.z - mx); v.w = expf(v.w - mx);
        float s = v.x + v.y + v.z + v.w;
        #pragma unroll
        for (int o = 16; o; o >>= 1) s += __shfl_xor_sync(~0u, s, o);
        float f = 0.08838834764831845f / s;
        v.x *= f; v.y *= f; v.z *= f; v.w *= f;
        *(float4*)&Q[l*128 + te*4] = v;
    }
    // K col softmax over L
    if (tid < 128) {
        int c = tid;
        float mx = -1e30f;
        #pragma unroll
        for (int l = 0; l < LL; ++l) mx = fmaxf(mx, KK[l*128 + c]);
        float s = 0.f;
        float ev[LL];
        #pragma unroll
        for (int l = 0; l < LL; ++l) { ev[l] = expf(KK[l*128 + c] - mx); s += ev[l]; }
        float inv = 1.0f / s;
        #pragma unroll
        for (int l = 0; l < LL; ++l) KK[l*128 + c] = ev[l] * inv;
    }
    __syncthreads();
    // S[i][j] = sum_d Q[i][d]*KK[j][d]   (48x48, k=128)
    {
        int ty = tid >> 4, tx = tid & 15;
        int i0 = ty*3, j0 = tx*3;
        float a[3][3] = {};
        #pragma unroll
        for (int d4 = 0; d4 < 128; d4 += 4) {
            float4 q0 = *(float4*)&Q [(i0+0)*128 + d4];
            float4 q1 = *(float4*)&Q [(i0+1)*128 + d4];
            float4 q2 = *(float4*)&Q [(i0+2)*128 + d4];
            float4 k0 = *(float4*)&KK[(j0+0)*128 + d4];
            float4 k1 = *(float4*)&KK[(j0+1)*128 + d4];
            float4 k2 = *(float4*)&KK[(j0+2)*128 + d4];
            a[0][0] += q0.x*k0.x + q0.y*k0.y + q0.z*k0.z + q0.w*k0.w;
            a[0][1] += q0.x*k1.x + q0.y*k1.y + q0.z*k1.z + q0.w*k1.w;
            a[0][2] += q0.x*k2.x + q0.y*k2.y + q0.z*k2.z + q0.w*k2.w;
            a[1][0] += q1.x*k0.x + q1.y*k0.y + q1.z*k0.z + q1.w*k0.w;
            a[1][1] += q1.x*k1.x + q1.y*k1.y + q1.z*k1.z + q1.w*k1.w;
            a[1][2] += q1.x*k2.x + q1.y*k2.y + q1.z*k2.z + q1.w*k2.w;
            a[2][0] += q2.x*k0.x + q2.y*k0.y + q2.z*k0.z + q2.w*k0.w;
            a[2][1] += q2.x*k1.x + q2.y*k1.y + q2.z*k1.z + q2.w*k1.w;
            a[2][2] += q2.x*k2.x + q2.y*k2.y + q2.z*k2.z + q2.w*k2.w;
        }
        #pragma unroll
        for (int r = 0; r < 3; ++r)
            #pragma unroll
            for (int c = 0; c < 3; ++c)
                S[(i0+r)*SPAD + j0 + c] = a[r][c];
    }
    __syncthreads();
    // att[l][e] = sum_j S[l][j]*V[j][e]  -> split store to d_qh/d_ql
    {
        int ty = tid >> 4, tx = tid & 15;
        int l0 = ty*3, e0 = tx*8;
        float a[3][8] = {};
        #pragma unroll
        for (int j = 0; j < LL; ++j) {
            float s0 = S[(l0+0)*SPAD + j];
            float s1 = S[(l0+1)*SPAD + j];
            float s2 = S[(l0+2)*SPAD + j];
            float4 v0 = *(float4*)&V[j*128 + e0];
            float4 v1 = *(float4*)&V[j*128 + e0 + 4];
            a[0][0]+=s0*v0.x; a[0][1]+=s0*v0.y; a[0][2]+=s0*v0.z; a[0][3]+=s0*v0.w;
            a[0][4]+=s0*v1.x; a[0][5]+=s0*v1.y; a[0][6]+=s0*v1.z; a[0][7]+=s0*v1.w;
            a[1][0]+=s1*v0.x; a[1][1]+=s1*v0.y; a[1][2]+=s1*v0.z; a[1][3]+=s1*v0.w;
            a[1][4]+=s1*v1.x; a[1][5]+=s1*v1.y; a[1][6]+=s1*v1.z; a[1][7]+=s1*v1.w;
            a[2][0]+=s2*v0.x; a[2][1]+=s2*v0.y; a[2][2]+=s2*v0.z; a[2][3]+=s2*v0.w;
            a[2][4]+=s2*v1.x; a[2][5]+=s2*v1.y; a[2][6]+=s2*v1.z; a[2][7]+=s2*v1.w;
        }
        #pragma unroll
        for (int r = 0; r < 3; ++r) {
            #pragma unroll
            for (int c = 0; c < 8; c += 2) {
                uint32_t hp, lp;
                pack_split(a[r][c], a[r][c+1], hp, lp);
                size_t w2 = (base + (size_t)(l0+r)*128 + e0 + c) >> 1;
                ((uint32_t*)d_qh)[w2] = hp;
                ((uint32_t*)d_ql)[w2] = lp;
            }
        }
    }
}

// ---------------- 3x-bf16 split GEMM: 3-stage cp.async + ldmatrix mainloop ----------------
// epi: 0 store fp32 C; 2 gelu(+bias)->Oh/Ol; 3 C+= ; 5 ->Oh/Ol; 6 QKV route C/C2/C3;
//      7 C+= then LN(row)->Oh/Ol (N must be 128, full tiles); 8 atomicAdd fp32 C (split-K)
#define TGW 12
#define TG_SMEM (3*4*128*TGW*4)   // 73728 bytes (3 stages)
__global__ void __launch_bounds__(256) tgemm(
    const bf16* __restrict__ Ah, const bf16* __restrict__ Al,
    const bf16* __restrict__ Bh, const bf16* __restrict__ Bl,
    float* __restrict__ C, float* __restrict__ C2, float* __restrict__ C3,
    bf16* __restrict__ Oh, bf16* __restrict__ Ol,
    int M, int N, int K, const float* __restrict__ bias, int epi, int gswap,
    const float* __restrict__ lng, const float* __restrict__ lnb, int ksplit)
{
    extern __shared__ uint32_t SMu[];
    const int tid = threadIdx.x;
    const int m0 = (gswap ? blockIdx.x : blockIdx.y) * 128;
    const int n0 = (gswap ? blockIdx.y : blockIdx.x) * 128;
    const int lrow = tid >> 1, comp = tid & 1;
    const int warp = tid >> 5, lane = tid & 31;
    const int wm = (warp >> 2) * 64, wn = (warp & 3) * 32;
    const int g = lane >> 2, tig = lane & 3;

    const bf16* Arow = (comp ? Al : Ah) + (size_t)(m0 + lrow) * K;
    const bf16* Brow = (comp ? Bl : Bh) + (size_t)(n0 + lrow) * K;
    const bool mok = (m0 + lrow) < M;

    const uint32_t smem_u32 = (uint32_t)__cvta_generic_to_shared(SMu);
    const int CSTR = 128*TGW*4;          // bytes per 128-row plane
    const int SBUF = 4*CSTR;             // bytes per stage

    const uint32_t dstA = smem_u32 + (comp*128 + lrow)*(TGW*4);
    const uint32_t dstB = smem_u32 + ((2 + comp)*128 + lrow)*(TGW*4);

    const int arow_l = wm + (lane & 7) + ((lane >> 3) & 1)*8;
    const uint32_t aoff = smem_u32 + arow_l*(TGW*4) + (lane >> 4)*16;
    const int brow_l = wn + (lane & 7) + ((lane >> 4) & 1)*8;
    const uint32_t boff = smem_u32 + 2*CSTR + brow_l*(TGW*4) + ((lane >> 3) & 1)*16;

    float acc[4][4][4];
    #pragma unroll
    for (int a = 0; a < 4; ++a)
        #pragma unroll
        for (int b = 0; b < 4; ++b)
            #pragma unroll
            for (int c = 0; c < 4; ++c) acc[a][b][c] = 0.f;

    int kt0 = 0, ktN = (K + 15) / 16;
    if (ksplit > 0) {
        int klo = blockIdx.z * ksplit;
        int khi = min(K, klo + ksplit);
        kt0 = klo >> 4;
        ktN = (khi + 15) >> 4;
    }

    #define FETCH(kt, buf) do { \
        int k_ = (kt)*16; \
        cp16(dstA + (buf)*SBUF,      Arow + k_,     mok && k_ + 8  <= K); \
        cp16(dstA + (buf)*SBUF + 16, Arow + k_ + 8, mok && k_ + 16 <= K); \
        cp16(dstB + (buf)*SBUF,      Brow + k_,     k_ + 8  <= K); \
        cp16(dstB + (buf)*SBUF + 16, Brow + k_ + 8, k_ + 16 <= K); \
        CP_COMMIT(); \
    } while (0)

    // 3-stage prologue: prefetch kt0 and kt0+1
    FETCH(kt0, 0);
    if (kt0 + 1 < ktN) { FETCH(kt0 + 1, 1); CP_WAIT1(); }
    else CP_WAIT0();
    __syncthreads();

    for (int kt = kt0; kt < ktN; ++kt) {
        const int s = (kt - kt0) % 3;

        uint32_t ah[4][4], al[4][4], bh[4][2], bl[4][2];
        const uint32_t sb = s*SBUF;
        #pragma unroll
        for (int mi = 0; mi < 4; ++mi) {
            ldsm_x4(ah[mi][0], ah[mi][1], ah[mi][2], ah[mi][3],
                    aoff + sb + mi*(16*TGW*4));
            ldsm_x4(al[mi][0], al[mi][1], al[mi][2], al[mi][3],
                    aoff + sb + CSTR + mi*(16*TGW*4));
        }
        #pragma unroll
        for (int p = 0; p < 2; ++p) {
            ldsm_x4(bh[2*p][0], bh[2*p][1], bh[2*p+1][0], bh[2*p+1][1],
                    boff + sb + p*(16*TGW*4));
            ldsm_x4(bl[2*p][0], bl[2*p][1], bl[2*p+1][0], bl[2*p+1][1],
                    boff + sb + CSTR + p*(16*TGW*4));
        }
        #pragma unroll
        for (int mi = 0; mi < 4; ++mi)
            #pragma unroll
            for (int ni = 0; ni < 4; ++ni) {
                asm volatile(
                    "mma.sync.aligned.m16n8k16.row.col.f32.bf16.bf16.f32 "
                    "{%0,%1,%2,%3}, {%4,%5,%6,%7}, {%8,%9}, {%0,%1,%2,%3};"
                    : "+f"(acc[mi][ni][0]), "+f"(acc[mi][ni][1]),
                      "+f"(acc[mi][ni][2]), "+f"(acc[mi][ni][3])
                    : "r"(ah[mi][0]), "r"(ah[mi][1]), "r"(ah[mi][2]), "r"(ah[mi][3]),
                      "r"(bl[ni][0]), "r"(bl[ni][1]));
                asm volatile(
                    "mma.sync.aligned.m16n8k16.row.col.f32.bf16.bf16.f32 "
                    "{%0,%1,%2,%3}, {%4,%5,%6,%7}, {%8,%9}, {%0,%1,%2,%3};"
                    : "+f"(acc[mi][ni][0]), "+f"(acc[mi][ni][1]),
                      "+f"(acc[mi][ni][2]), "+f"(acc[mi][ni][3])
                    : "r"(al[mi][0]), "r"(al[mi][1]), "r"(al[mi][2]), "r"(al[mi][3]),
                      "r"(bh[ni][0]), "r"(bh[ni][1]));
                asm volatile(
                    "mma.sync.aligned.m16n8k16.row.col.f32.bf16.bf16.f32 "
                    "{%0,%1,%2,%3}, {%4,%5,%6,%7}, {%8,%9}, {%0,%1,%2,%3};"
                    : "+f"(acc[mi][ni][0]), "+f"(acc[mi][ni][1]),
                      "+f"(acc[mi][ni][2]), "+f"(acc[mi][ni][3])
                    : "r"(ah[mi][0]), "r"(ah[mi][1]), "r"(ah[mi][2]), "r"(ah[mi][3]),
                      "r"(bh[ni][0]), "r"(bh[ni][1]));
            }

        const bool f2 = (kt + 2) < ktN;
        if (f2) FETCH(kt + 2, (kt + 2 - kt0) % 3);
        if ((kt + 1) < ktN) { if (f2) CP_WAIT1(); else CP_WAIT0(); }
        __syncthreads();
    }
    #undef FETCH

    if (epi == 7) {
        float* s_sum = (float*)SMu;
        float* s_sq  = s_sum + 512;
        float* s_mr  = s_sq + 512;
        #pragma unroll
        for (int mi = 0; mi < 4; ++mi)
            #pragma unroll
            for (int half = 0; half < 2; ++half) {
                int ml = wm + mi*16 + g + half*8;
                int m = m0 + ml;
                float rsum = 0.f, rsq = 0.f;
                #pragma unroll
                for (int ni = 0; ni < 4; ++ni) {
                    int n = wn + ni*8 + tig*2;
                    size_t off = (size_t)m * 128 + n;
                    float2 cur = *(float2*)(C + off);
                    float r0 = acc[mi][ni][half*2+0] + cur.x;
                    float r1 = acc[mi][ni][half*2+1] + cur.y;
                    *(float2*)(C + off) = make_float2(r0, r1);
                    acc[mi][ni][half*2+0] = r0; acc[mi][ni][half*2+1] = r1;
                    rsum += r0 + r1; rsq += r0*r0 + r1*r1;
                }
                rsum += __shfl_xor_sync(~0u, rsum, 1);
                rsum += __shfl_xor_sync(~0u, rsum, 2);
                rsq  += __shfl_xor_sync(~0u, rsq, 1);
                rsq  += __shfl_xor_sync(~0u, rsq, 2);
                if (tig == 0) {
                    s_sum[ml*4 + (warp & 3)] = rsum;
                    s_sq [ml*4 + (warp & 3)] = rsq;
                }
            }
        __syncthreads();
        if (tid < 128) {
            float s2 = s_sum[tid*4] + s_sum[tid*4+1] + s_sum[tid*4+2] + s_sum[tid*4+3];
            float q2 = s_sq[tid*4] + s_sq[tid*4+1] + s_sq[tid*4+2] + s_sq[tid*4+3];
            float mu = s2 * (1.0f/128.0f);
            float var = q2 * (1.0f/128.0f) - mu*mu;
            s_mr[tid*2] = mu; s_mr[tid*2+1] = rsqrtf(var + 1e-5f);
        }
        __syncthreads();
        #pragma unroll
        for (int mi = 0; mi < 4; ++mi)
            #pragma unroll
            for (int ni = 0; ni < 4; ++ni) {
                int n = wn + ni*8 + tig*2;
                float g0 = lng[n], g1 = lng[n+1];
                float b0 = lnb[n], b1 = lnb[n+1];
                #pragma unroll
                for (int half = 0; half < 2; ++half) {
                    int ml = wm + mi*16 + g + half*8;
                    int m = m0 + ml;
                    float mu = s_mr[ml*2], rg = s_mr[ml*2+1];
                    float v0 = (acc[mi][ni][half*2+0] - mu)*rg*g0 + b0;
                    float v1 = (acc[mi][ni][half*2+1] - mu)*rg*g1 + b1;
                    uint32_t hp, lp;
                    pack_split(v0, v1, hp, lp);
                    size_t off = (size_t)m * 128 + n;
                    ((uint32_t*)Oh)[off >> 1] = hp;
                    ((uint32_t*)Ol)[off >> 1] = lp;
                }
            }
        return;
    }

    // generic epilogue
    #pragma unroll
    for (int mi = 0; mi < 4; ++mi) {
        #pragma unroll
        for (int ni = 0; ni < 4; ++ni) {
            int n = n0 + wn + ni*8 + tig*2;
            float bv0 = 0.f, bv1 = 0.f;
            if (bias) { bv0 = bias[n]; bv1 = bias[n+1]; }
            #pragma unroll
            for (int half = 0; half < 2; ++half) {
                int m = m0 + wm + mi*16 + g + half*8;
                if (m >= M) continue;
                float r0 = acc[mi][ni][half*2+0] + bv0;
                float r1 = acc[mi][ni][half*2+1] + bv1;
                size_t off = (size_t)m * N + n;
                if (epi == 0) {
                    *(float2*)(C + off) = make_float2(r0, r1);
                } else if (epi == 2) {
                    r0 = gelu_exact(r0); r1 = gelu_exact(r1);
                    uint32_t hp, lp;
                    pack_split(r0, r1, hp, lp);
                    ((uint32_t*)Oh)[off >> 1] = hp;
                    ((uint32_t*)Ol)[off >> 1] = lp;
                } else if (epi == 3) {
                    float2 cur = *(float2*)(C + off);
                    *(float2*)(C + off) = make_float2(r0 + cur.x, r1 + cur.y);
                } else if (epi == 5) {
                    uint32_t hp, lp;
                    pack_split(r0, r1, hp, lp);
                    ((uint32_t*)Oh)[off >> 1] = hp;
                    ((uint32_t*)Ol)[off >> 1] = lp;
                } else if (epi == 8) {
                    atomicAdd(C + off, r0);
                    atomicAdd(C + off + 1, r1);
                } else { // 6: QKV routing
                    int buf = n >> 7, col = n & 127;
                    float* Cd = (buf == 0) ? C : (buf == 1 ? C2 : C3);
                    *(float2*)(Cd + ((size_t)m << 7) + col) = make_float2(r0, r1);
                }
            }
        }
    }
}

// ---------------- transpose enc -> X[(bl*128+d)][n], paired bf16x2 stores ----------------
__global__ void k_transpose() {   // grid (94, 96), 256 threads
    __shared__ float T[32*129];
    int n0 = blockIdx.x * 32;
    int bl = blockIdx.y;
    int b = bl / LL, l = bl % LL;
    int tid = threadIdx.x;
    int nrem = NN - n0; if (nrem > 32) nrem = 32;   // 32 or 24, always even
    for (int i = tid; i < 32*128; i += 256) {
        int r = i >> 7, c = i & 127;
        if (r < nrem)
            T[r*129 + c] = d_enc[((size_t)(b*NN + n0 + r))*6144 + l*128 + c];
    }
    __syncthreads();
    for (int i = tid; i < 128*16; i += 256) {
        int dd = i >> 4, j2 = (i & 15) * 2;
        if (j2 < nrem) {
            uint32_t hp, lp;
            pack_split(T[j2*129 + dd], T[(j2+1)*129 + dd], hp, lp);
            size_t o = ((size_t)(bl*128 + dd))*NN + n0 + j2;   // even
            ((uint32_t*)d_Xh)[o >> 1] = hp;
            ((uint32_t*)d_Xl)[o >> 1] = lp;
        }
    }
}

// ---------------- GroupNorm stat zero / finalize ----------------
__global__ void k_gzero() {
    int i = threadIdx.x;   // 384
    d_gsum[i] = 0.f; d_gsq[i] = 0.f;
}
__global__ void k_gnfin() {
    int i = threadIdx.x;   // 384
    const float inv = 1.0f / (float)(NN*32);
    float mu = d_gsum[i] * inv;
    float var = d_gsq[i] * inv - mu*mu;
    d_gmu[i] = mu;
    d_grs[i] = rsqrtf(var + 1e-5f);
}

// ---------------- tensorized per-node grouped GEMM + fused GN partial stats ----------------
#define SA 68
#define GRP2_STATS (2*96*SA + 2*128*SA)
#define GRP2_SMEM ((GRP2_STATS + 768) * 4)
__global__ void __launch_bounds__(256) k_grouped2() {
    extern __shared__ uint32_t SMu[];
    uint32_t* Ah_s = SMu;
    uint32_t* Al_s = SMu + 96*SA;
    uint32_t* Bh_s = SMu + 2*96*SA;
    uint32_t* Bl_s = SMu + 2*96*SA + 128*SA;
    float* s_sum = (float*)(SMu + GRP2_STATS);
    float* s_sq  = (float*)(SMu + GRP2_STATS + 384);
    int node = blockIdx.x, tid = threadIdx.x;
    for (int i = tid; i < 384; i += 256) { s_sum[i] = 0.f; s_sq[i] = 0.f; }
    const uint4* agh = (const uint4*)(d_aggh + (size_t)node * 12288);
    const uint4* agl = (const uint4*)(d_aggl + (size_t)node * 12288);
    const uint4* pwh = (const uint4*)(d_pwh + (size_t)node * 16384);
    const uint4* pwl = (const uint4*)(d_pwl + (size_t)node * 16384);
    for (int i = tid; i < 1536; i += 256) {
        int r = i >> 4, c = (i & 15) * 4;
        *(uint4*)(Ah_s + r*SA + c) = agh[i];
        *(uint4*)(Al_s + r*SA + c) = agl[i];
    }
    for (int i = tid; i < 2048; i += 256) {
        int r = i >> 4, c = (i & 15) * 4;
        *(uint4*)(Bh_s + r*SA + c) = pwh[i];
        *(uint4*)(Bl_s + r*SA + c) = pwl[i];
    }
    __syncthreads();

    int warp = tid >> 5, lane = tid & 31;
    int wm = (warp >> 2) * 48, wn = (warp & 3) * 32;
    int g = lane >> 2, tig = lane & 3;
    float acc[3][4][4];
    #pragma unroll
    for (int a = 0; a < 3; ++a)
        #pragma unroll
        for (int b = 0; b < 4; ++b)
            #pragma unroll
            for (int c = 0; c < 4; ++c) acc[a][b][c] = 0.f;

    #pragma unroll
    for (int kt = 0; kt < 8; ++kt) {
        uint32_t ah[3][4], al[3][4], bh[4][2], bl[4][2];
        int kb = kt*8 + tig;
        #pragma unroll
        for (int mi = 0; mi < 3; ++mi) {
            int r = wm + mi*16 + g;
            ah[mi][0] = Ah_s[ r     *SA + kb    ];
            ah[mi][1] = Ah_s[(r + 8)*SA + kb    ];
            ah[mi][2] = Ah_s[ r     *SA + kb + 4];
            ah[mi][3] = Ah_s[(r + 8)*SA + kb + 4];
            al[mi][0] = Al_s[ r     *SA + kb    ];
            al[mi][1] = Al_s[(r + 8)*SA + kb    ];
            al[mi][2] = Al_s[ r     *SA + kb + 4];
            al[mi][3] = Al_s[(r + 8)*SA + kb + 4];
        }
        #pragma unroll
        for (int ni = 0; ni < 4; ++ni) {
            int r = wn + ni*8 + g;
            bh[ni][0] = Bh_s[r*SA + kb    ];
            bh[ni][1] = Bh_s[r*SA + kb + 4];
            bl[ni][0] = Bl_s[r*SA + kb    ];
            bl[ni][1] = Bl_s[r*SA + kb + 4];
        }
        #pragma unroll
        for (int mi = 0; mi < 3; ++mi)
            #pragma unroll
            for (int ni = 0; ni < 4; ++ni) {
                asm volatile(
                    "mma.sync.aligned.m16n8k16.row.col.f32.bf16.bf16.f32 "
                    "{%0,%1,%2,%3}, {%4,%5,%6,%7}, {%8,%9}, {%0,%1,%2,%3};"
                    : "+f"(acc[mi][ni][0]), "+f"(acc[mi][ni][1]),
                      "+f"(acc[mi][ni][2]), "+f"(acc[mi][ni][3])
                    : "r"(ah[mi][0]), "r"(ah[mi][1]), "r"(ah[mi][2]), "r"(ah[mi][3]),
                      "r"(bl[ni][0]), "r"(bl[ni][1]));
                asm volatile(
                    "mma.sync.aligned.m16n8k16.row.col.f32.bf16.bf16.f32 "
                    "{%0,%1,%2,%3}, {%4,%5,%6,%7}, {%8,%9}, {%0,%1,%2,%3};"
                    : "+f"(acc[mi][ni][0]), "+f"(acc[mi][ni][1]),
                      "+f"(acc[mi][ni][2]), "+f"(acc[mi][ni][3])
                    : "r"(al[mi][0]), "r"(al[mi][1]), "r"(al[mi][2]), "r"(al[mi][3]),
                      "r"(bh[ni][0]), "r"(bh[ni][1]));
                asm volatile(
                    "mma.sync.aligned.m16n8k16.row.col.f32.bf16.bf16.f32 "
                    "{%0,%1,%2,%3}, {%4,%5,%6,%7}, {%8,%9}, {%0,%1,%2,%3};"
                    : "+f"(acc[mi][ni][0]), "+f"(acc[mi][ni][1]),
                      "+f"(acc[mi][ni][2]), "+f"(acc[mi][ni][3])
                    : "r"(ah[mi][0]), "r"(ah[mi][1]), "r"(ah[mi][2]), "r"(ah[mi][3]),
                      "r"(bh[ni][0]), "r"(bh[ni][1]));
            }
    }

    float* outp = d_gout + (size_t)node * 12288;
    #pragma unroll
    for (int mi = 0; mi < 3; ++mi)
        #pragma unroll
        for (int ni = 0; ni < 4; ++ni) {
            int n = wn + ni*8 + tig*2;
            int sidx = (n >> 5);
            #pragma unroll
            for (int half = 0; half < 2; ++half) {
                int m = wm + mi*16 + g + half*8;
                float v0 = acc[mi][ni][half*2+0];
                float v1 = acc[mi][ni][half*2+1];
                *(float2*)(outp + m*128 + n) = make_float2(v0, v1);
                atomicAdd(&s_sum[m*4 + sidx], v0 + v1);
                atomicAdd(&s_sq [m*4 + sidx], v0*v0 + v1*v1);
            }
        }
    __syncthreads();
    for (int i = tid; i < 384; i += 256) {
        atomicAdd(&d_gsum[i], s_sum[i]);
        atomicAdd(&d_gsq [i], s_sq [i]);
    }
}

// ---------------- fused GN-apply + SiLU proj + time proj + mean add ----------------
__global__ void k_final(const float* __restrict__ gg, const float* __restrict__ gb,
                        const float* __restrict__ p2w, const float* __restrict__ p2b,
                        const float* __restrict__ p1w, const float* __restrict__ p1b,
                        float* __restrict__ out) {
    __shared__ float Xs[6144];
    __shared__ float Ss[LL];
    int bn = blockIdx.x;
    int b = bn / NN, n = bn % NN;
    int tid = threadIdx.x;   // 256
    for (int i = tid; i < 6144; i += 256) {
        int l = i >> 7, c = i & 127;
        int bl = b*LL + l, g = c >> 5;
        float v = d_gout[(size_t)n*12288 + bl*128 + c];
        Xs[i] = (v - d_gmu[bl*4+g]) * d_grs[bl*4+g] * gg[c] + gb[c];
    }
    __syncthreads();
    int lane = tid & 31, w = tid >> 5;
    for (int l = w*6; l < w*6+6; ++l) {
        float s = Xs[l*128+lane]*p2w[lane] + Xs[l*128+lane+32]*p2w[lane+32]
                + Xs[l*128+lane+64]*p2w[lane+64] + Xs[l*128+lane+96]*p2w[lane+96];
        #pragma unroll
        for (int o = 16; o; o >>= 1) s += __shfl_xor_sync(~0u, s, o);
        if (lane == 0) {
            float z = s + p2b[0];
            Ss[l] = z / (1.0f + expf(-z));
        }
    }
    __syncthreads();
    if (tid < L_OUT) {
        float acc = p1b[tid];
        #pragma unroll
        for (int l = 0; l < LL; ++l) acc += Ss[l] * p1w[tid*LL + l];
        out[((size_t)(b*L_OUT + tid))*NN + n] = acc + d_mean[bn];
    }
}

// ---------------- launcher ----------------
extern "C" void kernel_launch(void* const* d_in, const int* in_sizes, int n_in,
                              void* d_out, int out_size) {
    const float* x_enc   = (const float*)d_in[0];
    const float* adj     = (const float*)d_in[1];
    const float* pe_raw  = (const float*)d_in[2];
    const float* conv_w  = (const float*)d_in[3];
    const float* pos_w   = (const float*)d_in[4];
    const float* pos_b   = (const float*)d_in[5];
    const float* wq      = (const float*)d_in[6];
    const float* wk      = (const float*)d_in[7];
    const float* wv      = (const float*)d_in[8];
    const float* wo      = (const float*)d_in[9];
    const float* ln1_g   = (const float*)d_in[10];
    const float* ln1_b   = (const float*)d_in[11];
    const float* ff_w1   = (const float*)d_in[12];
    const float* ff_b1   = (const float*)d_in[13];
    const float* ff_w2   = (const float*)d_in[14];
    const float* ff_b2   = (const float*)d_in[15];
    const float* ln2_g   = (const float*)d_in[16];
    const float* ln2_b   = (const float*)d_in[17];
    const float* wpool   = (const float*)d_in[18];
    const float* gn_g    = (const float*)d_in[19];
    const float* gn_b    = (const float*)d_in[20];
    const float* p2_w    = (const float*)d_in[21];
    const float* p2_b    = (const float*)d_in[22];
    const float* p1_w    = (const float*)d_in[23];
    const float* p1_b    = (const float*)d_in[24];
    float* out = (float*)d_out;

    float *p_enc, *p_q, *p_k, *p_v;
    bf16 *p_hh, *p_hl, *p_qh, *p_ql, *p_ffh, *p_ffl, *p_adjh, *p_adjl;
    bf16 *p_Xh, *p_Xl, *p_peTh, *p_peTl, *p_WT2h, *p_WT2l, *p_pe2h, *p_pe2l;
    bf16 *p_aggh, *p_aggl, *p_pwh, *p_pwl, *p_wph, *p_wpl;
    cudaGetSymbolAddress((void**)&p_enc, d_enc);
    cudaGetSymbolAddress((void**)&p_q,   d_qb);
    cudaGetSymbolAddress((void**)&p_k,   d_kb);
    cudaGetSymbolAddress((void**)&p_v,   d_vb);
    cudaGetSymbolAddress((void**)&p_hh,  d_hh);
    cudaGetSymbolAddress((void**)&p_hl,  d_hl);
    cudaGetSymbolAddress((void**)&p_qh,  d_qh);
    cudaGetSymbolAddress((void**)&p_ql,  d_ql);
    cudaGetSymbolAddress((void**)&p_ffh, d_ffh);
    cudaGetSymbolAddress((void**)&p_ffl, d_ffl);
    cudaGetSymbolAddress((void**)&p_adjh, d_adjh);
    cudaGetSymbolAddress((void**)&p_adjl, d_adjl);
    cudaGetSymbolAddress((void**)&p_Xh,  d_Xh);
    cudaGetSymbolAddress((void**)&p_Xl,  d_Xl);
    cudaGetSymbolAddress((void**)&p_peTh, d_peTh);
    cudaGetSymbolAddress((void**)&p_peTl, d_peTl);
    cudaGetSymbolAddress((void**)&p_WT2h, d_WT2h);
    cudaGetSymbolAddress((void**)&p_WT2l, d_WT2l);
    cudaGetSymbolAddress((void**)&p_pe2h, d_pe2h);
    cudaGetSymbolAddress((void**)&p_pe2l, d_pe2l);
    cudaGetSymbolAddress((void**)&p_aggh, d_aggh);
    cudaGetSymbolAddress((void**)&p_aggl, d_aggl);
    cudaGetSymbolAddress((void**)&p_pwh, d_pwh);
    cudaGetSymbolAddress((void**)&p_pwl, d_pwl);
    cudaGetSymbolAddress((void**)&p_wph, d_wph);
    cudaGetSymbolAddress((void**)&p_wpl, d_wpl);

    cudaFuncSetAttribute(k_attn,     cudaFuncAttributeMaxDynamicSharedMemorySize, ATTN_SMEM);
    cudaFuncSetAttribute(tgemm,      cudaFuncAttributeMaxDynamicSharedMemorySize, TG_SMEM);
    cudaFuncSetAttribute(k_grouped2, cudaFuncAttributeMaxDynamicSharedMemorySize, GRP2_SMEM);

    // prep + splits
    k_peT<<<(DD*NN+255)/256, 256>>>(pe_raw, pos_w, pos_b);
    k_WT2t<<<dim3(128, 16), 256>>>(wpool);
    k_conv<<<BNN, 128>>>(x_enc, conv_w, ln1_g, ln1_b);   // conv + mean + LN1 fused
    k_split4<<<(NN*NN/4+255)/256, 256>>>(adj, p_adjh, p_adjl, NN*NN/4);
    k_splitW<<<768, 256>>>(wq, wk, wv, wo, ff_w1, ff_w2);
    k_gzero<<<1, 384>>>();

    // temporal transformer
    tgemm<<<dim3(3, ROWS/128), 256, TG_SMEM>>>(p_hh, p_hl, p_wph+WPO_Q, p_wpl+WPO_Q,
        p_q, p_k, p_v, nullptr, nullptr, ROWS, 384, 128, nullptr, 6, 0, nullptr, nullptr, 0);
    k_attn<<<BNN, 256, ATTN_SMEM>>>();
    tgemm<<<dim3(1, ROWS/128), 256, TG_SMEM>>>(p_qh, p_ql, p_wph+WPO_O, p_wpl+WPO_O,
        p_enc, nullptr, nullptr, p_hh, p_hl, ROWS, 128, 128, nullptr, 7, 0, ln2_g, ln2_b, 0);
    tgemm<<<dim3(4, ROWS/128), 256, TG_SMEM>>>(p_hh, p_hl, p_wph+WPO_F1, p_wpl+WPO_F1,
        nullptr, nullptr, nullptr, p_ffh, p_ffl, ROWS, 512, 128, ff_b1, 2, 0, nullptr, nullptr, 0);
    tgemm<<<dim3(1, ROWS/128), 256, TG_SMEM>>>(p_ffh, p_ffl, p_wph+WPO_F2, p_wpl+WPO_F2,
        p_enc, nullptr, nullptr, nullptr, nullptr, ROWS, 128, 512, ff_b2, 3, 0, nullptr, nullptr, 0);

    // spatial GCN
    k_zero<<<(NN*DD+255)/256, 256>>>(p_q, NN*DD);        // pe2 fp32 accumulator
    k_transpose<<<dim3(94, BLL), 256>>>();
    tgemm<<<dim3(1, 24, 8), 256, TG_SMEM>>>(p_adjh, p_adjl, p_peTh, p_peTl,
        p_q, nullptr, nullptr, nullptr, nullptr, NN, 128, NN, nullptr, 8, 0, nullptr, nullptr, 384);
    k_split4<<<(NN*DD/4+255)/256, 256>>>(p_q, p_pe2h, p_pe2l, NN*DD/4);
    tgemm<<<dim3(128, 24), 256, TG_SMEM>>>(p_pe2h, p_pe2l, p_WT2h, p_WT2l,
        nullptr, nullptr, nullptr, p_pwh, p_pwl, NN, 16384, 128, nullptr, 5, 0, nullptr, nullptr, 0);
    tgemm<<<dim3(24, 96), 256, TG_SMEM>>>(p_adjh, p_adjl, p_Xh, p_Xl,
        nullptr, nullptr, nullptr, p_aggh, p_aggl, NN, 12288, NN, nullptr, 5, 1, nullptr, nullptr, 0);
    k_grouped2<<<NN, 256, GRP2_SMEM>>>();

    // groupnorm + head
    k_gnfin<<<1, 384>>>();
    k_final<<<BNN, 256>>>(gn_g, gn_b, p2_w, p2_b, p1_w, p1_b, out);
}

// round 16
// speedup vs baseline: 1.9582x; 1.0369x over previous
#include <cuda_runtime.h>
#include <cuda_bf16.h>
#include <math.h>
#include <stdint.h>

#define BB 2
#define LL 48
#define NN 3000
#define DD 128
#define L_OUT 24
#define BNN (BB*NN)          // 6000
#define BLL (BB*LL)          // 96
#define ROWS (BNN*LL)        // 288000 token rows
#define ENC_N (ROWS*DD)      // 36,864,000

typedef __nv_bfloat16 bf16;

// ---------------- scratch (device globals; no runtime allocation) ----------------
__device__ float d_mean[BNN];
__device__ float d_enc[ENC_N];           // enc[seq][l][c]
__device__ float d_qb[ENC_N];            // q fp32 (raw); later pe2 fp32 accumulator
__device__ float d_kb[ENC_N];
__device__ float d_vb[ENC_N];
__device__ float d_gout[NN*BLL*DD];      // gout[n][bl][o]
__device__ float d_gmu[BLL*4];
__device__ float d_grs[BLL*4];
__device__ float d_gsum[BLL*4];
__device__ float d_gsq[BLL*4];

// bf16 split pairs
__device__ bf16 d_hh[ENC_N],  d_hl[ENC_N];     // LN output
__device__ bf16 d_qh[ENC_N],  d_ql[ENC_N];     // att_pre
__device__ bf16 d_ffh[ROWS*512], d_ffl[ROWS*512];
__device__ bf16 d_adjh[NN*NN], d_adjl[NN*NN];
__device__ bf16 d_Xh[BLL*DD*NN], d_Xl[BLL*DD*NN];
__device__ bf16 d_peTh[DD*NN], d_peTl[DD*NN];
__device__ bf16 d_WT2h[DD*DD*DD], d_WT2l[DD*DD*DD];  // [(o*128+i)][d]
__device__ bf16 d_pe2h[NN*DD], d_pe2l[NN*DD];
__device__ bf16 d_aggh[NN*BLL*DD], d_aggl[NN*BLL*DD]; // [n][bl*128+i]
__device__ bf16 d_pwh[NN*DD*DD], d_pwl[NN*DD*DD];     // [n][o*128+i]
// weight pool: [wq|wk|wv|wo|ffw1|ffw2]
#define WPO_Q 0
#define WPO_K 16384
#define WPO_V 32768
#define WPO_O 49152
#define WPO_F1 65536
#define WPO_F2 131072
__device__ bf16 d_wph[196608], d_wpl[196608];

__device__ __forceinline__ float gelu_exact(float x) {
    return 0.5f * x * (1.0f + erff(x * 0.70710678118654752f));
}
__device__ __forceinline__ void pack_split(float x0, float x1, uint32_t& hi, uint32_t& lo) {
    uint32_t h;
    asm("cvt.rn.bf16x2.f32 %0, %1, %2;" : "=r"(h) : "f"(x1), "f"(x0));
    float h0 = __uint_as_float(h << 16);
    float h1 = __uint_as_float(h & 0xFFFF0000u);
    float r0 = x0 - h0, r1 = x1 - h1;
    uint32_t l;
    asm("cvt.rn.bf16x2.f32 %0, %1, %2;" : "=r"(l) : "f"(r1), "f"(r0));
    hi = h; lo = l;
}
__device__ __forceinline__ void scalar_split(float v, bf16& h, bf16& l) {
    h = __float2bfloat16_rn(v);
    l = __float2bfloat16_rn(v - __bfloat162float(h));
}
__device__ __forceinline__ void ldsm_x4(uint32_t& r0, uint32_t& r1, uint32_t& r2, uint32_t& r3,
                                        uint32_t addr) {
    asm volatile("ldmatrix.sync.aligned.m8n8.x4.shared.b16 {%0,%1,%2,%3}, [%4];"
                 : "=r"(r0), "=r"(r1), "=r"(r2), "=r"(r3) : "r"(addr));
}
__device__ __forceinline__ void cp16(uint32_t dst, const void* src, bool pred) {
    int sz = pred ? 16 : 0;
    asm volatile("cp.async.cg.shared.global [%0], [%1], 16, %2;\n"
                 :: "r"(dst), "l"(src), "r"(sz) : "memory");
}
#define CP_COMMIT() asm volatile("cp.async.commit_group;\n" ::: "memory")
#define CP_WAITN(n) asm volatile("cp.async.wait_group %0;\n" :: "n"(n) : "memory")

// ---------------- small prep kernels ----------------
__global__ void k_zero(float* __restrict__ p, int n) {
    int i = blockIdx.x * blockDim.x + threadIdx.x;
    if (i < n) p[i] = 0.f;
}

// vectorized split: 4 floats -> 2x bf16x2 per array (n must be divisible by 4)
__global__ void k_split4(const float* __restrict__ in, bf16* __restrict__ h,
                         bf16* __restrict__ l, int n4) {
    int i = blockIdx.x * blockDim.x + threadIdx.x;
    if (i >= n4) return;
    float4 v = ((const float4*)in)[i];
    uint32_t h01, l01, h23, l23;
    pack_split(v.x, v.y, h01, l01);
    pack_split(v.z, v.w, h23, l23);
    ((uint2*)h)[i] = make_uint2(h01, h23);
    ((uint2*)l)[i] = make_uint2(l01, l23);
}

// merged split of all dense weights into the pool
__global__ void k_splitW(const float* __restrict__ wq, const float* __restrict__ wk,
                         const float* __restrict__ wv, const float* __restrict__ wo,
                         const float* __restrict__ f1, const float* __restrict__ f2) {
    int i = blockIdx.x * blockDim.x + threadIdx.x;
    if (i >= 196608) return;
    float v;
    if (i < 65536) {
        int j = i & 16383;
        v = (i < 16384) ? wq[j] : (i < 32768) ? wk[j] : (i < 49152) ? wv[j] : wo[j];
    } else if (i < 131072) {
        v = f1[i - 65536];
    } else {
        v = f2[i - 131072];
    }
    scalar_split(v, d_wph[i], d_wpl[i]);
}

__global__ void k_peT(const float* __restrict__ pr, const float* __restrict__ pw,
                      const float* __restrict__ pb) {
    int i = blockIdx.x * blockDim.x + threadIdx.x;
    if (i >= DD*NN) return;
    int d = i / NN, n = i % NN;
    float v = pr[n]*pw[d*3] + pr[NN+n]*pw[d*3+1] + pr[2*NN+n]*pw[d*3+2] + pb[d];
    scalar_split(v, d_peTh[i], d_peTl[i]);
}

// tiled transpose: wp[d][i][o] -> WT2[(o*128+i)][d]; 32x32 (d,o) tiles per fixed i
__global__ void k_WT2t(const float* __restrict__ wp) {
    __shared__ float T[32][33];
    int i  = blockIdx.x;                 // 0..127
    int d0 = (blockIdx.y & 3) * 32;
    int o0 = (blockIdx.y >> 2) * 32;
    int tx = threadIdx.x & 31, ty = threadIdx.x >> 5;   // 32x8
    #pragma unroll
    for (int r = ty; r < 32; r += 8)
        T[r][tx] = wp[(size_t)(d0 + r)*16384 + i*128 + o0 + tx];
    __syncthreads();
    #pragma unroll
    for (int r = ty; r < 32; r += 8) {
        int o = o0 + r;
        int oi = (o*128 + i)*128 + d0 + tx;
        scalar_split(T[tx][r], d_WT2h[oi], d_WT2l[oi]);
    }
}

// circular conv1d k=3 + per-seq mean + fused LN1 (enc fp32 + split bf16 out)
__global__ void k_conv(const float* __restrict__ x, const float* __restrict__ cw,
                       const float* __restrict__ lg, const float* __restrict__ lb) {
    __shared__ float xs[LL + 2];
    __shared__ float red[384];
    __shared__ float mrs[LL*2];
    __shared__ float mm;
    int seq = blockIdx.x;
    int b = seq / NN, n = seq % NN;
    int t = threadIdx.x;   // 128
    if (t < LL) xs[t + 1] = x[(b*LL + t)*NN + n];
    __syncthreads();
    if (t == 0) {
        float s = 0.f;
        #pragma unroll
        for (int l = 1; l <= LL; ++l) s += xs[l];
        float m = s * (1.0f / LL);
        mm = m; d_mean[seq] = m;
        xs[0] = xs[LL]; xs[LL+1] = xs[1];
    }
    __syncthreads();
    float m = mm;
    float w0 = cw[t*3], w1 = cw[t*3+1], w2 = cw[t*3+2];
    float wc = (w0 + w1 + w2) * m;
    float val[LL];
    #pragma unroll
    for (int l = 0; l < LL; ++l)
        val[l] = w0*xs[l] + w1*xs[l+1] + w2*xs[l+2] - wc;
    int lane = t & 31, w = t >> 5;
    #pragma unroll
    for (int l = 0; l < LL; ++l) {
        float s = val[l], q = val[l]*val[l];
        #pragma unroll
        for (int o = 16; o; o >>= 1) {
            s += __shfl_xor_sync(~0u, s, o);
            q += __shfl_xor_sync(~0u, q, o);
        }
        if (lane == 0) { red[l*4 + w] = s; red[192 + l*4 + w] = q; }
    }
    __syncthreads();
    if (t < LL) {
        float s = red[t*4] + red[t*4+1] + red[t*4+2] + red[t*4+3];
        float q = red[192+t*4] + red[192+t*4+1] + red[192+t*4+2] + red[192+t*4+3];
        float mu = s * (1.0f/128.0f);
        float var = q * (1.0f/128.0f) - mu*mu;
        mrs[t*2] = mu; mrs[t*2+1] = rsqrtf(var + 1e-5f);
    }
    __syncthreads();
    float gg = lg[t], bb = lb[t];
    float* out = d_enc + (size_t)seq * 6144;
    size_t base = (size_t)seq * 6144;
    #pragma unroll
    for (int l = 0; l < LL; ++l) {
        float v = val[l];
        out[l*128 + t] = v;
        float h = (v - mrs[l*2]) * mrs[l*2+1] * gg + bb;
        bf16 hh, ll;
        scalar_split(h, hh, ll);
        d_hh[base + l*128 + t] = hh;
        d_hl[base + l*128 + t] = ll;
    }
}

// ---------------- per-sequence linear attention: (softmax_q @ softmax_k^T) @ v ----------------
#define SPAD 52
#define ATTN_SMEM ((6144*3 + LL*SPAD) * 4)    // 83712 B -> 2 CTAs/SM
__global__ void __launch_bounds__(256) k_attn() {
    extern __shared__ float sm[];
    float* Q  = sm;               // 48x128
    float* KK = sm + 6144;        // 48x128
    float* V  = sm + 12288;       // 48x128
    float* S  = sm + 18432;       // 48xSPAD
    int seq = blockIdx.x, tid = threadIdx.x;
    size_t base = (size_t)seq * 6144;
    for (int i = tid; i < 6144; i += 256) {
        Q[i] = d_qb[base+i]; KK[i] = d_kb[base+i]; V[i] = d_vb[base+i];
    }
    __syncthreads();
    int te = tid & 31, tg = tid >> 5;
    // Q row softmax * d^-0.5
    for (int l = tg*6; l < tg*6+6; ++l) {
        float4 v = *(float4*)&Q[l*128 + te*4];
        float mx = fmaxf(fmaxf(v.x, v.y), fmaxf(v.z, v.w));
        #pragma unroll
        for (int o = 16; o; o >>= 1) mx = fmaxf(mx, __shfl_xor_sync(~0u, mx, o));
        v.x = expf(v.x - mx); v.y = expf(v.y - mx);
        v.z = expf(v.z - mx); v.w = expf(v.w - mx);
        float s = v.x + v.y + v.z + v.w;
        #pragma unroll
        for (int o = 16; o; o >>= 1) s += __shfl_xor_sync(~0u, s, o);
        float f = 0.08838834764831845f / s;
        v.x *= f; v.y *= f; v.z *= f; v.w *= f;
        *(float4*)&Q[l*128 + te*4] = v;
    }
    // K col softmax over L
    if (tid < 128) {
        int c = tid;
        float mx = -1e30f;
        #pragma unroll
        for (int l = 0; l < LL; ++l) mx = fmaxf(mx, KK[l*128 + c]);
        float s = 0.f;
        float ev[LL];
        #pragma unroll
        for (int l = 0; l < LL; ++l) { ev[l] = expf(KK[l*128 + c] - mx); s += ev[l]; }
        float inv = 1.0f / s;
        #pragma unroll
        for (int l = 0; l < LL; ++l) KK[l*128 + c] = ev[l] * inv;
    }
    __syncthreads();
    // S[i][j] = sum_d Q[i][d]*KK[j][d]   (48x48, k=128)
    {
        int ty = tid >> 4, tx = tid & 15;
        int i0 = ty*3, j0 = tx*3;
        float a[3][3] = {};
        #pragma unroll
        for (int d4 = 0; d4 < 128; d4 += 4) {
            float4 q0 = *(float4*)&Q [(i0+0)*128 + d4];
            float4 q1 = *(float4*)&Q [(i0+1)*128 + d4];
            float4 q2 = *(float4*)&Q [(i0+2)*128 + d4];
            float4 k0 = *(float4*)&KK[(j0+0)*128 + d4];
            float4 k1 = *(float4*)&KK[(j0+1)*128 + d4];
            float4 k2 = *(float4*)&KK[(j0+2)*128 + d4];
            a[0][0] += q0.x*k0.x + q0.y*k0.y + q0.z*k0.z + q0.w*k0.w;
            a[0][1] += q0.x*k1.x + q0.y*k1.y + q0.z*k1.z + q0.w*k1.w;
            a[0][2] += q0.x*k2.x + q0.y*k2.y + q0.z*k2.z + q0.w*k2.w;
            a[1][0] += q1.x*k0.x + q1.y*k0.y + q1.z*k0.z + q1.w*k0.w;
            a[1][1] += q1.x*k1.x + q1.y*k1.y + q1.z*k1.z + q1.w*k1.w;
            a[1][2] += q1.x*k2.x + q1.y*k2.y + q1.z*k2.z + q1.w*k2.w;
            a[2][0] += q2.x*k0.x + q2.y*k0.y + q2.z*k0.z + q2.w*k0.w;
            a[2][1] += q2.x*k1.x + q2.y*k1.y + q2.z*k1.z + q2.w*k1.w;
            a[2][2] += q2.x*k2.x + q2.y*k2.y + q2.z*k2.z + q2.w*k2.w;
        }
        #pragma unroll
        for (int r = 0; r < 3; ++r)
            #pragma unroll
            for (int c = 0; c < 3; ++c)
                S[(i0+r)*SPAD + j0 + c] = a[r][c];
    }
    __syncthreads();
    // att[l][e] = sum_j S[l][j]*V[j][e]  -> split store to d_qh/d_ql
    {
        int ty = tid >> 4, tx = tid & 15;
        int l0 = ty*3, e0 = tx*8;
        float a[3][8] = {};
        #pragma unroll
        for (int j = 0; j < LL; ++j) {
            float s0 = S[(l0+0)*SPAD + j];
            float s1 = S[(l0+1)*SPAD + j];
            float s2 = S[(l0+2)*SPAD + j];
            float4 v0 = *(float4*)&V[j*128 + e0];
            float4 v1 = *(float4*)&V[j*128 + e0 + 4];
            a[0][0]+=s0*v0.x; a[0][1]+=s0*v0.y; a[0][2]+=s0*v0.z; a[0][3]+=s0*v0.w;
            a[0][4]+=s0*v1.x; a[0][5]+=s0*v1.y; a[0][6]+=s0*v1.z; a[0][7]+=s0*v1.w;
            a[1][0]+=s1*v0.x; a[1][1]+=s1*v0.y; a[1][2]+=s1*v0.z; a[1][3]+=s1*v0.w;
            a[1][4]+=s1*v1.x; a[1][5]+=s1*v1.y; a[1][6]+=s1*v1.z; a[1][7]+=s1*v1.w;
            a[2][0]+=s2*v0.x; a[2][1]+=s2*v0.y; a[2][2]+=s2*v0.z; a[2][3]+=s2*v0.w;
            a[2][4]+=s2*v1.x; a[2][5]+=s2*v1.y; a[2][6]+=s2*v1.z; a[2][7]+=s2*v1.w;
        }
        #pragma unroll
        for (int r = 0; r < 3; ++r) {
            #pragma unroll
            for (int c = 0; c < 8; c += 2) {
                uint32_t hp, lp;
                pack_split(a[r][c], a[r][c+1], hp, lp);
                size_t w2 = (base + (size_t)(l0+r)*128 + e0 + c) >> 1;
                ((uint32_t*)d_qh)[w2] = hp;
                ((uint32_t*)d_ql)[w2] = lp;
            }
        }
    }
}

// ---------------- 3x-bf16 split GEMM: 4-stage cp.async + ldmatrix mainloop ----------------
// epi: 0 store fp32 C; 2 gelu(+bias)->Oh/Ol; 3 C+= ; 5 ->Oh/Ol; 6 QKV route C/C2/C3;
//      7 C+= then LN(row)->Oh/Ol (N must be 128, full tiles); 8 atomicAdd fp32 C (split-K)
#define TGW 12
#define TG_SMEM (4*4*128*TGW*4)   // 98304 bytes (4 stages)
__global__ void __launch_bounds__(256) tgemm(
    const bf16* __restrict__ Ah, const bf16* __restrict__ Al,
    const bf16* __restrict__ Bh, const bf16* __restrict__ Bl,
    float* __restrict__ C, float* __restrict__ C2, float* __restrict__ C3,
    bf16* __restrict__ Oh, bf16* __restrict__ Ol,
    int M, int N, int K, const float* __restrict__ bias, int epi, int gswap,
    const float* __restrict__ lng, const float* __restrict__ lnb, int ksplit)
{
    extern __shared__ uint32_t SMu[];
    const int tid = threadIdx.x;
    const int m0 = (gswap ? blockIdx.x : blockIdx.y) * 128;
    const int n0 = (gswap ? blockIdx.y : blockIdx.x) * 128;
    const int lrow = tid >> 1, comp = tid & 1;
    const int warp = tid >> 5, lane = tid & 31;
    const int wm = (warp >> 2) * 64, wn = (warp & 3) * 32;
    const int g = lane >> 2, tig = lane & 3;

    const bf16* Arow = (comp ? Al : Ah) + (size_t)(m0 + lrow) * K;
    const bf16* Brow = (comp ? Bl : Bh) + (size_t)(n0 + lrow) * K;
    const bool mok = (m0 + lrow) < M;

    const uint32_t smem_u32 = (uint32_t)__cvta_generic_to_shared(SMu);
    const int CSTR = 128*TGW*4;          // bytes per 128-row plane
    const int SBUF = 4*CSTR;             // bytes per stage

    const uint32_t dstA = smem_u32 + (comp*128 + lrow)*(TGW*4);
    const uint32_t dstB = smem_u32 + ((2 + comp)*128 + lrow)*(TGW*4);

    const int arow_l = wm + (lane & 7) + ((lane >> 3) & 1)*8;
    const uint32_t aoff = smem_u32 + arow_l*(TGW*4) + (lane >> 4)*16;
    const int brow_l = wn + (lane & 7) + ((lane >> 4) & 1)*8;
    const uint32_t boff = smem_u32 + 2*CSTR + brow_l*(TGW*4) + ((lane >> 3) & 1)*16;

    float acc[4][4][4];
    #pragma unroll
    for (int a = 0; a < 4; ++a)
        #pragma unroll
        for (int b = 0; b < 4; ++b)
            #pragma unroll
            for (int c = 0; c < 4; ++c) acc[a][b][c] = 0.f;

    int kt0 = 0, ktN = (K + 15) / 16;
    if (ksplit > 0) {
        int klo = blockIdx.z * ksplit;
        int khi = min(K, klo + ksplit);
        kt0 = klo >> 4;
        ktN = (khi + 15) >> 4;
    }

    #define FETCH(kt, buf) do { \
        int k_ = (kt)*16; \
        cp16(dstA + (buf)*SBUF,      Arow + k_,     mok && k_ + 8  <= K); \
        cp16(dstA + (buf)*SBUF + 16, Arow + k_ + 8, mok && k_ + 16 <= K); \
        cp16(dstB + (buf)*SBUF,      Brow + k_,     k_ + 8  <= K); \
        cp16(dstB + (buf)*SBUF + 16, Brow + k_ + 8, k_ + 16 <= K); \
        CP_COMMIT(); \
    } while (0)

    // 4-stage prologue: prefetch kt0 .. kt0+2, then wait for kt0
    {
        int nf = 0;
        FETCH(kt0, 0); ++nf;
        if (kt0 + 1 < ktN) { FETCH(kt0 + 1, 1); ++nf; }
        if (kt0 + 2 < ktN) { FETCH(kt0 + 2, 2); ++nf; }
        if (nf == 3) CP_WAITN(2);
        else if (nf == 2) CP_WAITN(1);
        else CP_WAITN(0);
    }
    __syncthreads();

    for (int kt = kt0; kt < ktN; ++kt) {
        const int s = (kt - kt0) & 3;

        uint32_t ah[4][4], al[4][4], bh[4][2], bl[4][2];
        const uint32_t sb = s*SBUF;
        #pragma unroll
        for (int mi = 0; mi < 4; ++mi) {
            ldsm_x4(ah[mi][0], ah[mi][1], ah[mi][2], ah[mi][3],
                    aoff + sb + mi*(16*TGW*4));
            ldsm_x4(al[mi][0], al[mi][1], al[mi][2], al[mi][3],
                    aoff + sb + CSTR + mi*(16*TGW*4));
        }
        #pragma unroll
        for (int p = 0; p < 2; ++p) {
            ldsm_x4(bh[2*p][0], bh[2*p][1], bh[2*p+1][0], bh[2*p+1][1],
                    boff + sb + p*(16*TGW*4));
            ldsm_x4(bl[2*p][0], bl[2*p][1], bl[2*p+1][0], bl[2*p+1][1],
                    boff + sb + CSTR + p*(16*TGW*4));
        }
        #pragma unroll
        for (int mi = 0; mi < 4; ++mi)
            #pragma unroll
            for (int ni = 0; ni < 4; ++ni) {
                asm volatile(
                    "mma.sync.aligned.m16n8k16.row.col.f32.bf16.bf16.f32 "
                    "{%0,%1,%2,%3}, {%4,%5,%6,%7}, {%8,%9}, {%0,%1,%2,%3};"
                    : "+f"(acc[mi][ni][0]), "+f"(acc[mi][ni][1]),
                      "+f"(acc[mi][ni][2]), "+f"(acc[mi][ni][3])
                    : "r"(ah[mi][0]), "r"(ah[mi][1]), "r"(ah[mi][2]), "r"(ah[mi][3]),
                      "r"(bl[ni][0]), "r"(bl[ni][1]));
                asm volatile(
                    "mma.sync.aligned.m16n8k16.row.col.f32.bf16.bf16.f32 "
                    "{%0,%1,%2,%3}, {%4,%5,%6,%7}, {%8,%9}, {%0,%1,%2,%3};"
                    : "+f"(acc[mi][ni][0]), "+f"(acc[mi][ni][1]),
                      "+f"(acc[mi][ni][2]), "+f"(acc[mi][ni][3])
                    : "r"(al[mi][0]), "r"(al[mi][1]), "r"(al[mi][2]), "r"(al[mi][3]),
                      "r"(bh[ni][0]), "r"(bh[ni][1]));
                asm volatile(
                    "mma.sync.aligned.m16n8k16.row.col.f32.bf16.bf16.f32 "
                    "{%0,%1,%2,%3}, {%4,%5,%6,%7}, {%8,%9}, {%0,%1,%2,%3};"
                    : "+f"(acc[mi][ni][0]), "+f"(acc[mi][ni][1]),
                      "+f"(acc[mi][ni][2]), "+f"(acc[mi][ni][3])
                    : "r"(ah[mi][0]), "r"(ah[mi][1]), "r"(ah[mi][2]), "r"(ah[mi][3]),
                      "r"(bh[ni][0]), "r"(bh[ni][1]));
            }

        // prefetch kt+3; ensure kt+1 complete before next iteration
        if (kt + 3 < ktN) {
            FETCH(kt + 3, (kt + 3 - kt0) & 3);
            CP_WAITN(2);
        } else if (kt + 2 < ktN) {
            CP_WAITN(1);
        } else if (kt + 1 < ktN) {
            CP_WAITN(0);
        }
        __syncthreads();
    }
    #undef FETCH

    if (epi == 7) {
        float* s_sum = (float*)SMu;
        float* s_sq  = s_sum + 512;
        float* s_mr  = s_sq + 512;
        #pragma unroll
        for (int mi = 0; mi < 4; ++mi)
            #pragma unroll
            for (int half = 0; half < 2; ++half) {
                int ml = wm + mi*16 + g + half*8;
                int m = m0 + ml;
                float rsum = 0.f, rsq = 0.f;
                #pragma unroll
                for (int ni = 0; ni < 4; ++ni) {
                    int n = wn + ni*8 + tig*2;
                    size_t off = (size_t)m * 128 + n;
                    float2 cur = *(float2*)(C + off);
                    float r0 = acc[mi][ni][half*2+0] + cur.x;
                    float r1 = acc[mi][ni][half*2+1] + cur.y;
                    *(float2*)(C + off) = make_float2(r0, r1);
                    acc[mi][ni][half*2+0] = r0; acc[mi][ni][half*2+1] = r1;
                    rsum += r0 + r1; rsq += r0*r0 + r1*r1;
                }
                rsum += __shfl_xor_sync(~0u, rsum, 1);
                rsum += __shfl_xor_sync(~0u, rsum, 2);
                rsq  += __shfl_xor_sync(~0u, rsq, 1);
                rsq  += __shfl_xor_sync(~0u, rsq, 2);
                if (tig == 0) {
                    s_sum[ml*4 + (warp & 3)] = rsum;
                    s_sq [ml*4 + (warp & 3)] = rsq;
                }
            }
        __syncthreads();
        if (tid < 128) {
            float s2 = s_sum[tid*4] + s_sum[tid*4+1] + s_sum[tid*4+2] + s_sum[tid*4+3];
            float q2 = s_sq[tid*4] + s_sq[tid*4+1] + s_sq[tid*4+2] + s_sq[tid*4+3];
            float mu = s2 * (1.0f/128.0f);
            float var = q2 * (1.0f/128.0f) - mu*mu;
            s_mr[tid*2] = mu; s_mr[tid*2+1] = rsqrtf(var + 1e-5f);
        }
        __syncthreads();
        #pragma unroll
        for (int mi = 0; mi < 4; ++mi)
            #pragma unroll
            for (int ni = 0; ni < 4; ++ni) {
                int n = wn + ni*8 + tig*2;
                float g0 = lng[n], g1 = lng[n+1];
                float b0 = lnb[n], b1 = lnb[n+1];
                #pragma unroll
                for (int half = 0; half < 2; ++half) {
                    int ml = wm + mi*16 + g + half*8;
                    int m = m0 + ml;
                    float mu = s_mr[ml*2], rg = s_mr[ml*2+1];
                    float v0 = (acc[mi][ni][half*2+0] - mu)*rg*g0 + b0;
                    float v1 = (acc[mi][ni][half*2+1] - mu)*rg*g1 + b1;
                    uint32_t hp, lp;
                    pack_split(v0, v1, hp, lp);
                    size_t off = (size_t)m * 128 + n;
                    ((uint32_t*)Oh)[off >> 1] = hp;
                    ((uint32_t*)Ol)[off >> 1] = lp;
                }
            }
        return;
    }

    // generic epilogue
    #pragma unroll
    for (int mi = 0; mi < 4; ++mi) {
        #pragma unroll
        for (int ni = 0; ni < 4; ++ni) {
            int n = n0 + wn + ni*8 + tig*2;
            float bv0 = 0.f, bv1 = 0.f;
            if (bias) { bv0 = bias[n]; bv1 = bias[n+1]; }
            #pragma unroll
            for (int half = 0; half < 2; ++half) {
                int m = m0 + wm + mi*16 + g + half*8;
                if (m >= M) continue;
                float r0 = acc[mi][ni][half*2+0] + bv0;
                float r1 = acc[mi][ni][half*2+1] + bv1;
                size_t off = (size_t)m * N + n;
                if (epi == 0) {
                    *(float2*)(C + off) = make_float2(r0, r1);
                } else if (epi == 2) {
                    r0 = gelu_exact(r0); r1 = gelu_exact(r1);
                    uint32_t hp, lp;
                    pack_split(r0, r1, hp, lp);
                    ((uint32_t*)Oh)[off >> 1] = hp;
                    ((uint32_t*)Ol)[off >> 1] = lp;
                } else if (epi == 3) {
                    float2 cur = *(float2*)(C + off);
                    *(float2*)(C + off) = make_float2(r0 + cur.x, r1 + cur.y);
                } else if (epi == 5) {
                    uint32_t hp, lp;
                    pack_split(r0, r1, hp, lp);
                    ((uint32_t*)Oh)[off >> 1] = hp;
                    ((uint32_t*)Ol)[off >> 1] = lp;
                } else if (epi == 8) {
                    atomicAdd(C + off, r0);
                    atomicAdd(C + off + 1, r1);
                } else { // 6: QKV routing
                    int buf = n >> 7, col = n & 127;
                    float* Cd = (buf == 0) ? C : (buf == 1 ? C2 : C3);
                    *(float2*)(Cd + ((size_t)m << 7) + col) = make_float2(r0, r1);
                }
            }
        }
    }
}

// ---------------- transpose enc -> X[(bl*128+d)][n], paired bf16x2 stores ----------------
__global__ void k_transpose() {   // grid (94, 96), 256 threads
    __shared__ float T[32*129];
    int n0 = blockIdx.x * 32;
    int bl = blockIdx.y;
    int b = bl / LL, l = bl % LL;
    int tid = threadIdx.x;
    int nrem = NN - n0; if (nrem > 32) nrem = 32;   // 32 or 24, always even
    for (int i = tid; i < 32*128; i += 256) {
        int r = i >> 7, c = i & 127;
        if (r < nrem)
            T[r*129 + c] = d_enc[((size_t)(b*NN + n0 + r))*6144 + l*128 + c];
    }
    __syncthreads();
    for (int i = tid; i < 128*16; i += 256) {
        int dd = i >> 4, j2 = (i & 15) * 2;
        if (j2 < nrem) {
            uint32_t hp, lp;
            pack_split(T[j2*129 + dd], T[(j2+1)*129 + dd], hp, lp);
            size_t o = ((size_t)(bl*128 + dd))*NN + n0 + j2;   // even
            ((uint32_t*)d_Xh)[o >> 1] = hp;
            ((uint32_t*)d_Xl)[o >> 1] = lp;
        }
    }
}

// ---------------- GroupNorm stat zero / finalize ----------------
__global__ void k_gzero() {
    int i = threadIdx.x;   // 384
    d_gsum[i] = 0.f; d_gsq[i] = 0.f;
}
__global__ void k_gnfin() {
    int i = threadIdx.x;   // 384
    const float inv = 1.0f / (float)(NN*32);
    float mu = d_gsum[i] * inv;
    float var = d_gsq[i] * inv - mu*mu;
    d_gmu[i] = mu;
    d_grs[i] = rsqrtf(var + 1e-5f);
}

// ---------------- tensorized per-node grouped GEMM + fused GN partial stats ----------------
#define SA 68
#define GRP2_STATS (2*96*SA + 2*128*SA)
#define GRP2_SMEM ((GRP2_STATS + 768) * 4)
__global__ void __launch_bounds__(256) k_grouped2() {
    extern __shared__ uint32_t SMu[];
    uint32_t* Ah_s = SMu;
    uint32_t* Al_s = SMu + 96*SA;
    uint32_t* Bh_s = SMu + 2*96*SA;
    uint32_t* Bl_s = SMu + 2*96*SA + 128*SA;
    float* s_sum = (float*)(SMu + GRP2_STATS);
    float* s_sq  = (float*)(SMu + GRP2_STATS + 384);
    int node = blockIdx.x, tid = threadIdx.x;
    for (int i = tid; i < 384; i += 256) { s_sum[i] = 0.f; s_sq[i] = 0.f; }
    const uint4* agh = (const uint4*)(d_aggh + (size_t)node * 12288);
    const uint4* agl = (const uint4*)(d_aggl + (size_t)node * 12288);
    const uint4* pwh = (const uint4*)(d_pwh + (size_t)node * 16384);
    const uint4* pwl = (const uint4*)(d_pwl + (size_t)node * 16384);
    for (int i = tid; i < 1536; i += 256) {
        int r = i >> 4, c = (i & 15) * 4;
        *(uint4*)(Ah_s + r*SA + c) = agh[i];
        *(uint4*)(Al_s + r*SA + c) = agl[i];
    }
    for (int i = tid; i < 2048; i += 256) {
        int r = i >> 4, c = (i & 15) * 4;
        *(uint4*)(Bh_s + r*SA + c) = pwh[i];
        *(uint4*)(Bl_s + r*SA + c) = pwl[i];
    }
    __syncthreads();

    int warp = tid >> 5, lane = tid & 31;
    int wm = (warp >> 2) * 48, wn = (warp & 3) * 32;
    int g = lane >> 2, tig = lane & 3;
    float acc[3][4][4];
    #pragma unroll
    for (int a = 0; a < 3; ++a)
        #pragma unroll
        for (int b = 0; b < 4; ++b)
            #pragma unroll
            for (int c = 0; c < 4; ++c) acc[a][b][c] = 0.f;

    #pragma unroll
    for (int kt = 0; kt < 8; ++kt) {
        uint32_t ah[3][4], al[3][4], bh[4][2], bl[4][2];
        int kb = kt*8 + tig;
        #pragma unroll
        for (int mi = 0; mi < 3; ++mi) {
            int r = wm + mi*16 + g;
            ah[mi][0] = Ah_s[ r     *SA + kb    ];
            ah[mi][1] = Ah_s[(r + 8)*SA + kb    ];
            ah[mi][2] = Ah_s[ r     *SA + kb + 4];
            ah[mi][3] = Ah_s[(r + 8)*SA + kb + 4];
            al[mi][0] = Al_s[ r     *SA + kb    ];
            al[mi][1] = Al_s[(r + 8)*SA + kb    ];
            al[mi][2] = Al_s[ r     *SA + kb + 4];
            al[mi][3] = Al_s[(r + 8)*SA + kb + 4];
        }
        #pragma unroll
        for (int ni = 0; ni < 4; ++ni) {
            int r = wn + ni*8 + g;
            bh[ni][0] = Bh_s[r*SA + kb    ];
            bh[ni][1] = Bh_s[r*SA + kb + 4];
            bl[ni][0] = Bl_s[r*SA + kb    ];
            bl[ni][1] = Bl_s[r*SA + kb + 4];
        }
        #pragma unroll
        for (int mi = 0; mi < 3; ++mi)
            #pragma unroll
            for (int ni = 0; ni < 4; ++ni) {
                asm volatile(
                    "mma.sync.aligned.m16n8k16.row.col.f32.bf16.bf16.f32 "
                    "{%0,%1,%2,%3}, {%4,%5,%6,%7}, {%8,%9}, {%0,%1,%2,%3};"
                    : "+f"(acc[mi][ni][0]), "+f"(acc[mi][ni][1]),
                      "+f"(acc[mi][ni][2]), "+f"(acc[mi][ni][3])
                    : "r"(ah[mi][0]), "r"(ah[mi][1]), "r"(ah[mi][2]), "r"(ah[mi][3]),
                      "r"(bl[ni][0]), "r"(bl[ni][1]));
                asm volatile(
                    "mma.sync.aligned.m16n8k16.row.col.f32.bf16.bf16.f32 "
                    "{%0,%1,%2,%3}, {%4,%5,%6,%7}, {%8,%9}, {%0,%1,%2,%3};"
                    : "+f"(acc[mi][ni][0]), "+f"(acc[mi][ni][1]),
                      "+f"(acc[mi][ni][2]), "+f"(acc[mi][ni][3])
                    : "r"(al[mi][0]), "r"(al[mi][1]), "r"(al[mi][2]), "r"(al[mi][3]),
                      "r"(bh[ni][0]), "r"(bh[ni][1]));
                asm volatile(
                    "mma.sync.aligned.m16n8k16.row.col.f32.bf16.bf16.f32 "
                    "{%0,%1,%2,%3}, {%4,%5,%6,%7}, {%8,%9}, {%0,%1,%2,%3};"
                    : "+f"(acc[mi][ni][0]), "+f"(acc[mi][ni][1]),
                      "+f"(acc[mi][ni][2]), "+f"(acc[mi][ni][3])
                    : "r"(ah[mi][0]), "r"(ah[mi][1]), "r"(ah[mi][2]), "r"(ah[mi][3]),
                      "r"(bh[ni][0]), "r"(bh[ni][1]));
            }
    }

    float* outp = d_gout + (size_t)node * 12288;
    #pragma unroll
    for (int mi = 0; mi < 3; ++mi)
        #pragma unroll
        for (int ni = 0; ni < 4; ++ni) {
            int n = wn + ni*8 + tig*2;
            int sidx = (n >> 5);
            #pragma unroll
            for (int half = 0; half < 2; ++half) {
                int m = wm + mi*16 + g + half*8;
                float v0 = acc[mi][ni][half*2+0];
                float v1 = acc[mi][ni][half*2+1];
                *(float2*)(outp + m*128 + n) = make_float2(v0, v1);
                atomicAdd(&s_sum[m*4 + sidx], v0 + v1);
                atomicAdd(&s_sq [m*4 + sidx], v0*v0 + v1*v1);
            }
        }
    __syncthreads();
    for (int i = tid; i < 384; i += 256) {
        atomicAdd(&d_gsum[i], s_sum[i]);
        atomicAdd(&d_gsq [i], s_sq [i]);
    }
}

// ---------------- fused GN-apply + SiLU proj + time proj + mean add ----------------
__global__ void k_final(const float* __restrict__ gg, const float* __restrict__ gb,
                        const float* __restrict__ p2w, const float* __restrict__ p2b,
                        const float* __restrict__ p1w, const float* __restrict__ p1b,
                        float* __restrict__ out) {
    __shared__ float Xs[6144];
    __shared__ float Ss[LL];
    int bn = blockIdx.x;
    int b = bn / NN, n = bn % NN;
    int tid = threadIdx.x;   // 256
    for (int i = tid; i < 6144; i += 256) {
        int l = i >> 7, c = i & 127;
        int bl = b*LL + l, g = c >> 5;
        float v = d_gout[(size_t)n*12288 + bl*128 + c];
        Xs[i] = (v - d_gmu[bl*4+g]) * d_grs[bl*4+g] * gg[c] + gb[c];
    }
    __syncthreads();
    int lane = tid & 31, w = tid >> 5;
    for (int l = w*6; l < w*6+6; ++l) {
        float s = Xs[l*128+lane]*p2w[lane] + Xs[l*128+lane+32]*p2w[lane+32]
                + Xs[l*128+lane+64]*p2w[lane+64] + Xs[l*128+lane+96]*p2w[lane+96];
        #pragma unroll
        for (int o = 16; o; o >>= 1) s += __shfl_xor_sync(~0u, s, o);
        if (lane == 0) {
            float z = s + p2b[0];
            Ss[l] = z / (1.0f + expf(-z));
        }
    }
    __syncthreads();
    if (tid < L_OUT) {
        float acc = p1b[tid];
        #pragma unroll
        for (int l = 0; l < LL; ++l) acc += Ss[l] * p1w[tid*LL + l];
        out[((size_t)(b*L_OUT + tid))*NN + n] = acc + d_mean[bn];
    }
}

// ---------------- launcher ----------------
extern "C" void kernel_launch(void* const* d_in, const int* in_sizes, int n_in,
                              void* d_out, int out_size) {
    const float* x_enc   = (const float*)d_in[0];
    const float* adj     = (const float*)d_in[1];
    const float* pe_raw  = (const float*)d_in[2];
    const float* conv_w  = (const float*)d_in[3];
    const float* pos_w   = (const float*)d_in[4];
    const float* pos_b   = (const float*)d_in[5];
    const float* wq      = (const float*)d_in[6];
    const float* wk      = (const float*)d_in[7];
    const float* wv      = (const float*)d_in[8];
    const float* wo      = (const float*)d_in[9];
    const float* ln1_g   = (const float*)d_in[10];
    const float* ln1_b   = (const float*)d_in[11];
    const float* ff_w1   = (const float*)d_in[12];
    const float* ff_b1   = (const float*)d_in[13];
    const float* ff_w2   = (const float*)d_in[14];
    const float* ff_b2   = (const float*)d_in[15];
    const float* ln2_g   = (const float*)d_in[16];
    const float* ln2_b   = (const float*)d_in[17];
    const float* wpool   = (const float*)d_in[18];
    const float* gn_g    = (const float*)d_in[19];
    const float* gn_b    = (const float*)d_in[20];
    const float* p2_w    = (const float*)d_in[21];
    const float* p2_b    = (const float*)d_in[22];
    const float* p1_w    = (const float*)d_in[23];
    const float* p1_b    = (const float*)d_in[24];
    float* out = (float*)d_out;

    float *p_enc, *p_q, *p_k, *p_v;
    bf16 *p_hh, *p_hl, *p_qh, *p_ql, *p_ffh, *p_ffl, *p_adjh, *p_adjl;
    bf16 *p_Xh, *p_Xl, *p_peTh, *p_peTl, *p_WT2h, *p_WT2l, *p_pe2h, *p_pe2l;
    bf16 *p_aggh, *p_aggl, *p_pwh, *p_pwl, *p_wph, *p_wpl;
    cudaGetSymbolAddress((void**)&p_enc, d_enc);
    cudaGetSymbolAddress((void**)&p_q,   d_qb);
    cudaGetSymbolAddress((void**)&p_k,   d_kb);
    cudaGetSymbolAddress((void**)&p_v,   d_vb);
    cudaGetSymbolAddress((void**)&p_hh,  d_hh);
    cudaGetSymbolAddress((void**)&p_hl,  d_hl);
    cudaGetSymbolAddress((void**)&p_qh,  d_qh);
    cudaGetSymbolAddress((void**)&p_ql,  d_ql);
    cudaGetSymbolAddress((void**)&p_ffh, d_ffh);
    cudaGetSymbolAddress((void**)&p_ffl, d_ffl);
    cudaGetSymbolAddress((void**)&p_adjh, d_adjh);
    cudaGetSymbolAddress((void**)&p_adjl, d_adjl);
    cudaGetSymbolAddress((void**)&p_Xh,  d_Xh);
    cudaGetSymbolAddress((void**)&p_Xl,  d_Xl);
    cudaGetSymbolAddress((void**)&p_peTh, d_peTh);
    cudaGetSymbolAddress((void**)&p_peTl, d_peTl);
    cudaGetSymbolAddress((void**)&p_WT2h, d_WT2h);
    cudaGetSymbolAddress((void**)&p_WT2l, d_WT2l);
    cudaGetSymbolAddress((void**)&p_pe2h, d_pe2h);
    cudaGetSymbolAddress((void**)&p_pe2l, d_pe2l);
    cudaGetSymbolAddress((void**)&p_aggh, d_aggh);
    cudaGetSymbolAddress((void**)&p_aggl, d_aggl);
    cudaGetSymbolAddress((void**)&p_pwh, d_pwh);
    cudaGetSymbolAddress((void**)&p_pwl, d_pwl);
    cudaGetSymbolAddress((void**)&p_wph, d_wph);
    cudaGetSymbolAddress((void**)&p_wpl, d_wpl);

    cudaFuncSetAttribute(k_attn,     cudaFuncAttributeMaxDynamicSharedMemorySize, ATTN_SMEM);
    cudaFuncSetAttribute(tgemm,      cudaFuncAttributeMaxDynamicSharedMemorySize, TG_SMEM);
    cudaFuncSetAttribute(k_grouped2, cudaFuncAttributeMaxDynamicSharedMemorySize, GRP2_SMEM);

    // prep + splits
    k_peT<<<(DD*NN+255)/256, 256>>>(pe_raw, pos_w, pos_b);
    k_WT2t<<<dim3(128, 16), 256>>>(wpool);
    k_conv<<<BNN, 128>>>(x_enc, conv_w, ln1_g, ln1_b);   // conv + mean + LN1 fused
    k_split4<<<(NN*NN/4+255)/256, 256>>>(adj, p_adjh, p_adjl, NN*NN/4);
    k_splitW<<<768, 256>>>(wq, wk, wv, wo, ff_w1, ff_w2);
    k_gzero<<<1, 384>>>();

    // temporal transformer
    tgemm<<<dim3(3, ROWS/128), 256, TG_SMEM>>>(p_hh, p_hl, p_wph+WPO_Q, p_wpl+WPO_Q,
        p_q, p_k, p_v, nullptr, nullptr, ROWS, 384, 128, nullptr, 6, 0, nullptr, nullptr, 0);
    k_attn<<<BNN, 256, ATTN_SMEM>>>();
    tgemm<<<dim3(1, ROWS/128), 256, TG_SMEM>>>(p_qh, p_ql, p_wph+WPO_O, p_wpl+WPO_O,
        p_enc, nullptr, nullptr, p_hh, p_hl, ROWS, 128, 128, nullptr, 7, 0, ln2_g, ln2_b, 0);
    tgemm<<<dim3(4, ROWS/128), 256, TG_SMEM>>>(p_hh, p_hl, p_wph+WPO_F1, p_wpl+WPO_F1,
        nullptr, nullptr, nullptr, p_ffh, p_ffl, ROWS, 512, 128, ff_b1, 2, 0, nullptr, nullptr, 0);
    tgemm<<<dim3(1, ROWS/128), 256, TG_SMEM>>>(p_ffh, p_ffl, p_wph+WPO_F2, p_wpl+WPO_F2,
        p_enc, nullptr, nullptr, nullptr, nullptr, ROWS, 128, 512, ff_b2, 3, 0, nullptr, nullptr, 0);

    // spatial GCN
    k_zero<<<(NN*DD+255)/256, 256>>>(p_q, NN*DD);        // pe2 fp32 accumulator
    k_transpose<<<dim3(94, BLL), 256>>>();
    tgemm<<<dim3(1, 24, 8), 256, TG_SMEM>>>(p_adjh, p_adjl, p_peTh, p_peTl,
        p_q, nullptr, nullptr, nullptr, nullptr, NN, 128, NN, nullptr, 8, 0, nullptr, nullptr, 384);
    k_split4<<<(NN*DD/4+255)/256, 256>>>(p_q, p_pe2h, p_pe2l, NN*DD/4);
    tgemm<<<dim3(128, 24), 256, TG_SMEM>>>(p_pe2h, p_pe2l, p_WT2h, p_WT2l,
        nullptr, nullptr, nullptr, p_pwh, p_pwl, NN, 16384, 128, nullptr, 5, 0, nullptr, nullptr, 0);
    tgemm<<<dim3(24, 96), 256, TG_SMEM>>>(p_adjh, p_adjl, p_Xh, p_Xl,
        nullptr, nullptr, nullptr, p_aggh, p_aggl, NN, 12288, NN, nullptr, 5, 1, nullptr, nullptr, 0);
    k_grouped2<<<NN, 256, GRP2_SMEM>>>();

    // groupnorm + head
    k_gnfin<<<1, 384>>>();
    k_final<<<BNN, 256>>>(gn_g, gn_b, p2_w, p2_b, p1_w, p1_b, out);
}